// round 10
// baseline (speedup 1.0000x reference)
#include <cuda_runtime.h>
#include <cuda_fp16.h>
#include <math.h>
#include <stdint.h>

// Problem constants
#define BB 2
#define NN 384
#define DD 128
#define VV 8192
#define LL 2
#define NPAIR_B 73920
#define NPAIR_T 147840
#define PT 128
#define NTILES_MMA 1155      // 147840 / 128

// ---------------- scratch ----------------
__device__ float g_x[BB * NN * DD];
__device__ float g_a[BB * NN * 256];
__device__ float g_c[BB * NN * 256];
__device__ float g_h[BB * NN * 512];
__device__ __half g_p[(size_t)BB * NN * NN * DD];   // pair vectors, fp16
__device__ float g_s[BB * NN * NN];
__device__ __half g_w2h[LL * 256 * 128];
__device__ __half g_w3h[LL * 128 * 128];

// tanh-form gelu using HW MUFU.TANH
__device__ __forceinline__ float gelu_fast(float x) {
    float x2 = x * x;
    float inner = fmaf(0.0356774081f, x2, 0.7978845608f);
    float u = x * inner;
    float t;
    asm("tanh.approx.f32 %0, %1;" : "=f"(t) : "f"(u));
    float hx = 0.5f * x;
    return fmaf(hx, t, hx);
}

__device__ __forceinline__ void ldsm4(uint32_t* r, uint32_t addr) {
    asm volatile("ldmatrix.sync.aligned.m8n8.x4.shared.b16 {%0,%1,%2,%3}, [%4];"
                 : "=r"(r[0]), "=r"(r[1]), "=r"(r[2]), "=r"(r[3]) : "r"(addr));
}
__device__ __forceinline__ void ldsm4t(uint32_t* r, uint32_t addr) {
    asm volatile("ldmatrix.sync.aligned.m8n8.x4.trans.shared.b16 {%0,%1,%2,%3}, [%4];"
                 : "=r"(r[0]), "=r"(r[1]), "=r"(r[2]), "=r"(r[3]) : "r"(addr));
}
__device__ __forceinline__ void mma_f16(float c[4], const uint32_t a[4],
                                        uint32_t b0, uint32_t b1) {
    asm volatile(
        "mma.sync.aligned.m16n8k16.row.col.f32.f16.f16.f32 "
        "{%0,%1,%2,%3}, {%4,%5,%6,%7}, {%8,%9}, {%0,%1,%2,%3};"
        : "+f"(c[0]), "+f"(c[1]), "+f"(c[2]), "+f"(c[3])
        : "r"(a[0]), "r"(a[1]), "r"(a[2]), "r"(a[3]), "r"(b0), "r"(b1));
}
__device__ __forceinline__ void cpa16(uint32_t daddr, const void* g) {
    asm volatile("cp.async.cg.shared.global [%0], [%1], 16;" :: "r"(daddr), "l"(g));
}
#define CP_COMMIT asm volatile("cp.async.commit_group;")
#define CP_WAIT0 asm volatile("cp.async.wait_group 0;")
#define CP_WAIT1 asm volatile("cp.async.wait_group 1;")

// ---------------- weight pre-convert ----------------
__global__ void convert_w(const float* __restrict__ pW2, const float* __restrict__ pW3) {
    int t = blockIdx.x * 256 + threadIdx.x;
    const int n2 = LL * 256 * 128;
    const int n3 = LL * 128 * 128;
    if (t < n2) g_w2h[t] = __float2half(pW2[t]);
    int t3 = t - n2;
    if (t3 >= 0 && t3 < n3) g_w3h[t3] = __float2half(pW3[t3]);
}

// ---------------- embedding ----------------
__global__ void embed_kernel(const int* __restrict__ ids,
                             const float* __restrict__ emb,
                             const float* __restrict__ pos) {
    int t = blockIdx.x * blockDim.x + threadIdx.x;
    if (t >= BB * NN * DD) return;
    int d = t & (DD - 1);
    int bn = t >> 7;
    int n = bn % NN;
    g_x[t] = emb[ids[bn] * DD + d] + pos[n * DD + d];
}

// ================= generic fp16-mma GEMM, 64(M)x128(N) tiles ================
#define SBW 136
#define SPF 132
#define GM_OX 0
#define GM_OW 17408
#define GM_OB 52224
#define GM_SMEM_BYTES 52736

template <int ACT>
__global__ __launch_bounds__(256, 2) void gemm_mma64(
    const float* __restrict__ A, int ldA,
    const float* __restrict__ Wa, const float* __restrict__ Wb, int nsplit, int ldW,
    const float* __restrict__ ba, const float* __restrict__ bb,
    float* __restrict__ Ca, float* __restrict__ Cb, int ldC, int K) {
    extern __shared__ char smc[];
    __half* Xh = (__half*)(smc + GM_OX);
    __half* Wh = (__half*)(smc + GM_OW);
    float* biass = (float*)(smc + GM_OB);
    float* Pf = (float*)smc;

    const int tid = threadIdx.x;
    const int lane = tid & 31;
    const int warp = tid >> 5;
    const int wm = warp >> 2;
    const int wn = warp & 3;
    const int lr = lane >> 2;
    const int lc = lane & 3;
    const int lrow = (lane & 7) + ((lane >> 3) & 1) * 8;
    const int lcol = (lane >> 4) * 8;

    const int n0 = blockIdx.x * 128;
    const int m0 = blockIdx.y * 64;

    const float* Wsrc;
    const float* bsrc;
    float* Cdst;
    if (n0 < nsplit) {
        Wsrc = Wa + n0;
        bsrc = ba ? ba + n0 : nullptr;
        Cdst = Ca + n0;
    } else {
        int nn = n0 - nsplit;
        Wsrc = Wb + nn;
        bsrc = bb ? bb + nn : nullptr;
        Cdst = Cb + nn;
    }

    const uint32_t sb = (uint32_t)__cvta_generic_to_shared(smc);
    const uint32_t x_lane = sb + GM_OX + (uint32_t)(lrow * SBW + lcol) * 2;
    const uint32_t w_lane = sb + GM_OW + (uint32_t)(lrow * SBW + lcol) * 2;

    if (tid < 128) biass[tid] = bsrc ? bsrc[tid] : 0.f;

    float acc[2][4][4] = {};
    uint32_t af[2][4];
    uint32_t bf[4];

    const int nkc = K >> 7;
    for (int kc = 0; kc < nkc; kc++) {
        const int k0 = kc << 7;
        for (int e = tid; e < 64 * 32; e += 256) {
            int r = e >> 5, c4 = e & 31;
            const float4 v = *(const float4*)&A[(size_t)(m0 + r) * ldA + k0 + c4 * 4];
            __half2* d = (__half2*)(Xh + r * SBW + c4 * 4);
            d[0] = __floats2half2_rn(v.x, v.y);
            d[1] = __floats2half2_rn(v.z, v.w);
        }
        for (int e = tid; e < 128 * 32; e += 256) {
            int k = e >> 5, n4 = e & 31;
            const float4 v = *(const float4*)&Wsrc[(size_t)(k0 + k) * ldW + n4 * 4];
            __half2* d = (__half2*)(Wh + k * SBW + n4 * 4);
            d[0] = __floats2half2_rn(v.x, v.y);
            d[1] = __floats2half2_rn(v.z, v.w);
        }
        __syncthreads();
#pragma unroll
        for (int ks = 0; ks < 8; ks++) {
            const int kb = ks * 16;
            ldsm4(af[0], x_lane + (uint32_t)((wm * 32) * SBW + kb) * 2);
            ldsm4(af[1], x_lane + (uint32_t)((wm * 32 + 16) * SBW + kb) * 2);
#pragma unroll
            for (int bt = 0; bt < 2; bt++) {
                ldsm4t(bf, w_lane + (uint32_t)(kb * SBW + wn * 32 + bt * 16) * 2);
                mma_f16(acc[0][2 * bt], af[0], bf[0], bf[1]);
                mma_f16(acc[1][2 * bt], af[1], bf[0], bf[1]);
                mma_f16(acc[0][2 * bt + 1], af[0], bf[2], bf[3]);
                mma_f16(acc[1][2 * bt + 1], af[1], bf[2], bf[3]);
            }
        }
        __syncthreads();
    }

#pragma unroll
    for (int mt = 0; mt < 2; mt++) {
        int r0 = wm * 32 + mt * 16 + lr;
#pragma unroll
        for (int nt = 0; nt < 4; nt++) {
            int cb = wn * 32 + nt * 8 + 2 * lc;
            float o0 = acc[mt][nt][0] + biass[cb];
            float o1 = acc[mt][nt][1] + biass[cb + 1];
            float o2 = acc[mt][nt][2] + biass[cb];
            float o3 = acc[mt][nt][3] + biass[cb + 1];
            if (ACT == 1) {
                o0 = gelu_fast(o0); o1 = gelu_fast(o1);
                o2 = gelu_fast(o2); o3 = gelu_fast(o3);
            }
            *(float2*)(Pf + r0 * SPF + cb) = make_float2(o0, o1);
            *(float2*)(Pf + (r0 + 8) * SPF + cb) = make_float2(o2, o3);
        }
    }
    __syncthreads();

    {
        int r = tid >> 2, q = tid & 3;
        const float* src = Pf + r * SPF + q * 32;
        float* dst = Cdst + (size_t)(m0 + r) * ldC + q * 32;
#pragma unroll
        for (int u = 0; u < 32; u += 4)
            *(float4*)(dst + u) = *(const float4*)(src + u);
    }
}

// ================= FFN2 + residual + LN fused =================
// C = g_h @ W + bias; x = LN(x + C). One 64-row tile per CTA, full N=128.
__global__ __launch_bounds__(256, 2) void ffn2_ln(
    const float* __restrict__ W, const float* __restrict__ bias,
    const float* __restrict__ lng, const float* __restrict__ lnb) {
    extern __shared__ char smc[];
    __half* Xh = (__half*)(smc + GM_OX);
    __half* Wh = (__half*)(smc + GM_OW);
    float* biass = (float*)(smc + GM_OB);
    float* Pf = (float*)smc;

    const int tid = threadIdx.x;
    const int lane = tid & 31;
    const int warp = tid >> 5;
    const int wm = warp >> 2;
    const int wn = warp & 3;
    const int lr = lane >> 2;
    const int lc = lane & 3;
    const int lrow = (lane & 7) + ((lane >> 3) & 1) * 8;
    const int lcol = (lane >> 4) * 8;
    const int m0 = blockIdx.x * 64;

    const uint32_t sb = (uint32_t)__cvta_generic_to_shared(smc);
    const uint32_t x_lane = sb + GM_OX + (uint32_t)(lrow * SBW + lcol) * 2;
    const uint32_t w_lane = sb + GM_OW + (uint32_t)(lrow * SBW + lcol) * 2;

    if (tid < 128) biass[tid] = bias[tid];

    float acc[2][4][4] = {};
    uint32_t af[2][4];
    uint32_t bf[4];

    for (int kc = 0; kc < 4; kc++) {
        const int k0 = kc << 7;
        for (int e = tid; e < 64 * 32; e += 256) {
            int r = e >> 5, c4 = e & 31;
            const float4 v = *(const float4*)&g_h[(size_t)(m0 + r) * 512 + k0 + c4 * 4];
            __half2* d = (__half2*)(Xh + r * SBW + c4 * 4);
            d[0] = __floats2half2_rn(v.x, v.y);
            d[1] = __floats2half2_rn(v.z, v.w);
        }
        for (int e = tid; e < 128 * 32; e += 256) {
            int k = e >> 5, n4 = e & 31;
            const float4 v = *(const float4*)&W[(size_t)(k0 + k) * 128 + n4 * 4];
            __half2* d = (__half2*)(Wh + k * SBW + n4 * 4);
            d[0] = __floats2half2_rn(v.x, v.y);
            d[1] = __floats2half2_rn(v.z, v.w);
        }
        __syncthreads();
#pragma unroll
        for (int ks = 0; ks < 8; ks++) {
            const int kb = ks * 16;
            ldsm4(af[0], x_lane + (uint32_t)((wm * 32) * SBW + kb) * 2);
            ldsm4(af[1], x_lane + (uint32_t)((wm * 32 + 16) * SBW + kb) * 2);
#pragma unroll
            for (int bt = 0; bt < 2; bt++) {
                ldsm4t(bf, w_lane + (uint32_t)(kb * SBW + wn * 32 + bt * 16) * 2);
                mma_f16(acc[0][2 * bt], af[0], bf[0], bf[1]);
                mma_f16(acc[1][2 * bt], af[1], bf[0], bf[1]);
                mma_f16(acc[0][2 * bt + 1], af[0], bf[2], bf[3]);
                mma_f16(acc[1][2 * bt + 1], af[1], bf[2], bf[3]);
            }
        }
        __syncthreads();
    }

    // stage C = acc + bias into Pf
#pragma unroll
    for (int mt = 0; mt < 2; mt++) {
        int r0 = wm * 32 + mt * 16 + lr;
#pragma unroll
        for (int nt = 0; nt < 4; nt++) {
            int cb = wn * 32 + nt * 8 + 2 * lc;
            *(float2*)(Pf + r0 * SPF + cb) =
                make_float2(acc[mt][nt][0] + biass[cb], acc[mt][nt][1] + biass[cb + 1]);
            *(float2*)(Pf + (r0 + 8) * SPF + cb) =
                make_float2(acc[mt][nt][2] + biass[cb], acc[mt][nt][3] + biass[cb + 1]);
        }
    }
    __syncthreads();

    // residual + LN: 4 threads per row (quad shfl), write g_x in place
    {
        int r = tid >> 2, q = tid & 3;
        int row = m0 + r;
        float4 vv[8];
        float s = 0.f, sq = 0.f;
#pragma unroll
        for (int u = 0; u < 8; u++) {
            float4 p = *(const float4*)(Pf + r * SPF + q * 32 + u * 4);
            const float4 x = *(const float4*)&g_x[row * DD + q * 32 + u * 4];
            float4 v = make_float4(p.x + x.x, p.y + x.y, p.z + x.z, p.w + x.w);
            vv[u] = v;
            s += v.x + v.y + v.z + v.w;
            sq += v.x * v.x + v.y * v.y + v.z * v.z + v.w * v.w;
        }
        s += __shfl_xor_sync(0xffffffffu, s, 1);
        s += __shfl_xor_sync(0xffffffffu, s, 2);
        sq += __shfl_xor_sync(0xffffffffu, sq, 1);
        sq += __shfl_xor_sync(0xffffffffu, sq, 2);
        float mean = s * (1.0f / DD);
        float var = sq * (1.0f / DD) - mean * mean;
        float rs = rsqrtf(var + 1e-5f);
#pragma unroll
        for (int u = 0; u < 8; u++) {
            const float4 g = *(const float4*)&lng[q * 32 + u * 4];
            const float4 b = *(const float4*)&lnb[q * 32 + u * 4];
            float4 o;
            o.x = (vv[u].x - mean) * rs * g.x + b.x;
            o.y = (vv[u].y - mean) * rs * g.y + b.y;
            o.z = (vv[u].z - mean) * rs * g.z + b.z;
            o.w = (vv[u].w - mean) * rs * g.w + b.w;
            *(float4*)&g_x[row * DD + q * 32 + u * 4] = o;
        }
    }
}

// ---------------- pair kernel: full-H1, cp.async pipelined W, fp16 mma ------
#define SA2 264   // full H1 [128][256]+8 (stride in halves; 528B rows, 33%8=1)
#define SH 136
#define OWB0 0
#define OWB1 17408
#define OH1 34816            // H1: 128*264*2 = 67584, ends 102400
#define OH2 34816            // H2 overlays H1 (dead after GEMM1)
#define OB2 102400
#define OB3 102912
#define ORA 103424
#define ORC 103936
#define OPO 104448
#define ONW 104960           // 1024 B
#define PM_SMEM_BYTES 105984

__global__ __launch_bounds__(256, 2) void pair_mma(
    const __half* __restrict__ W2h, const float* __restrict__ b2,
    const __half* __restrict__ W3h, const float* __restrict__ b3) {
    extern __shared__ char smc[];
    __half* H1s = (__half*)(smc + OH1);
    __half* H2s = (__half*)(smc + OH2);
    float* b2s = (float*)(smc + OB2);
    float* b3s = (float*)(smc + OB3);
    int* rowA = (int*)(smc + ORA);
    int* rowC = (int*)(smc + ORC);
    int* poff = (int*)(smc + OPO);
    float* normw = (float*)(smc + ONW);

    const int tid = threadIdx.x;
    const int lane = tid & 31;
    const int warp = tid >> 5;
    const int wm = warp >> 1;
    const int wn = warp & 1;
    const int lr = lane >> 2;
    const int lc = lane & 3;
    const int lrow = (lane & 7) + ((lane >> 3) & 1) * 8;
    const int lcol = (lane >> 4) * 8;

    const uint32_t sb = (uint32_t)__cvta_generic_to_shared(smc);
    const uint32_t h1_lane = sb + OH1 + (uint32_t)(lrow * SA2 + lcol) * 2;
    const uint32_t h2_lane = sb + OH2 + (uint32_t)(lrow * SH + lcol) * 2;
    const uint32_t w_lane0 = sb + OWB0 + (uint32_t)(lrow * SBW + lcol) * 2;
    const uint32_t w_lane1 = sb + OWB1 + (uint32_t)(lrow * SBW + lcol) * 2;

    auto issue_w = [&](const __half* src, uint32_t dbase) {
#pragma unroll
        for (int e = tid; e < 1024; e += 256) {
            int row = e >> 4, seg = e & 15;
            cpa16(dbase + row * (SBW * 2) + seg * 16, src + row * 128 + seg * 8);
        }
        CP_COMMIT;
    };

    // prefetch W2 chunks 0 and 1 (groups G0, G1) — land during H1 build
    issue_w(W2h, sb + OWB0);
    issue_w(W2h + 64 * 128, sb + OWB1);

    if (tid < 128) {
        b2s[tid] = b2[tid];
        b3s[tid] = b3[tid];
        int g = blockIdx.x * PT + tid;
        int b = (g >= NPAIR_B) ? 1 : 0;
        int idx = g - b * NPAIR_B;
        int i = (int)((sqrtf(8.0f * (float)idx + 1.0f) - 1.0f) * 0.5f);
        while ((i + 1) * (i + 2) / 2 <= idx) ++i;
        while (i * (i + 1) / 2 > idx) --i;
        int j = idx - i * (i + 1) / 2;
        rowA[tid] = b * NN + i;
        rowC[tid] = b * NN + j;
        poff[tid] = (b * NN + i) * NN + j;
    }
    __syncthreads();

    // build FULL H1 [128][256] once
#pragma unroll 4
    for (int e = tid; e < 128 * 64; e += 256) {
        int r = e >> 6, c4 = e & 63;
        const float4 av = *(const float4*)&g_a[rowA[r] * 256 + c4 * 4];
        const float4 cv = *(const float4*)&g_c[rowC[r] * 256 + c4 * 4];
        __half2* d = (__half2*)(H1s + r * SA2 + c4 * 4);
        d[0] = __floats2half2_rn(gelu_fast(av.x + cv.x), gelu_fast(av.y + cv.y));
        d[1] = __floats2half2_rn(gelu_fast(av.z + cv.z), gelu_fast(av.w + cv.w));
    }
    CP_WAIT1;          // W2 chunk 0 landed
    __syncthreads();

    float acc[2][8][4] = {};
    uint32_t af[2][4];
    uint32_t bf[4];

    // ---------- GEMM1: K=256, 4 chunks; only cp.async waits between bursts ----
    for (int kc = 0; kc < 4; kc++) {
        const uint32_t wl = (kc & 1) ? w_lane1 : w_lane0;
        const int kg0 = kc * 64;
#pragma unroll
        for (int ks = 0; ks < 4; ks++) {
            const int kb = ks * 16;
            ldsm4(af[0], h1_lane + (uint32_t)((wm * 32) * SA2 + kg0 + kb) * 2);
            ldsm4(af[1], h1_lane + (uint32_t)((wm * 32 + 16) * SA2 + kg0 + kb) * 2);
#pragma unroll
            for (int bt = 0; bt < 4; bt++) {
                ldsm4t(bf, wl + (uint32_t)(kb * SBW + wn * 64 + bt * 16) * 2);
                mma_f16(acc[0][2 * bt], af[0], bf[0], bf[1]);
                mma_f16(acc[1][2 * bt], af[1], bf[0], bf[1]);
                mma_f16(acc[0][2 * bt + 1], af[0], bf[2], bf[3]);
                mma_f16(acc[1][2 * bt + 1], af[1], bf[2], bf[3]);
            }
        }
        __syncthreads();   // all warps done reading this W buffer
        // refill the just-freed buffer: W2 c2, W2 c3, W3 c0; (W3 c1 after loop)
        if (kc < 2)      issue_w(W2h + (kc + 2) * 64 * 128, sb + ((kc & 1) ? OWB1 : OWB0));
        else if (kc == 2) issue_w(W3h, sb + OWB0);
        else              issue_w(W3h + 64 * 128, sb + OWB1);
        if (kc < 3) {
            CP_WAIT1;      // next chunk resident
            __syncthreads();
        }
    }
    __syncthreads();       // H1 fully read -> safe to overlay with H2

    // epilogue 1: +b2, gelu, half -> H2s (overlays H1)
#pragma unroll
    for (int mt = 0; mt < 2; mt++) {
        int r0 = wm * 32 + mt * 16 + lr;
#pragma unroll
        for (int nt = 0; nt < 8; nt++) {
            int cb = wn * 64 + nt * 8 + 2 * lc;
            float bx = b2s[cb], by = b2s[cb + 1];
            *(__half2*)(H2s + r0 * SH + cb) =
                __floats2half2_rn(gelu_fast(acc[mt][nt][0] + bx), gelu_fast(acc[mt][nt][1] + by));
            *(__half2*)(H2s + (r0 + 8) * SH + cb) =
                __floats2half2_rn(gelu_fast(acc[mt][nt][2] + bx), gelu_fast(acc[mt][nt][3] + by));
        }
    }
    CP_WAIT0;              // both W3 chunks resident
    __syncthreads();

    // ---------- GEMM2: K=128, 8 uninterrupted k-steps ----------
    float acc2[2][8][4] = {};
#pragma unroll
    for (int ks = 0; ks < 8; ks++) {
        const int kbg = ks * 16;
        const uint32_t wl = (kbg & 64) ? w_lane1 : w_lane0;
        const int kb = kbg & 63;
        ldsm4(af[0], h2_lane + (uint32_t)((wm * 32) * SH + kbg) * 2);
        ldsm4(af[1], h2_lane + (uint32_t)((wm * 32 + 16) * SH + kbg) * 2);
#pragma unroll
        for (int bt = 0; bt < 4; bt++) {
            ldsm4t(bf, wl + (uint32_t)(kb * SBW + wn * 64 + bt * 16) * 2);
            mma_f16(acc2[0][2 * bt], af[0], bf[0], bf[1]);
            mma_f16(acc2[1][2 * bt], af[1], bf[0], bf[1]);
            mma_f16(acc2[0][2 * bt + 1], af[0], bf[2], bf[3]);
            mma_f16(acc2[1][2 * bt + 1], af[1], bf[2], bf[3]);
        }
    }
    __syncthreads();       // H2s reads done -> safe to overwrite with fp16 P

    // epilogue 2: +b3, fp16 into H2s region, norms from fp32 registers
#pragma unroll
    for (int mt = 0; mt < 2; mt++) {
        int r0 = wm * 32 + mt * 16 + lr;
        float n0s = 0.f, n1s = 0.f;
#pragma unroll
        for (int nt = 0; nt < 8; nt++) {
            int cb = wn * 64 + nt * 8 + 2 * lc;
            float bx = b3s[cb], by = b3s[cb + 1];
            float o0 = acc2[mt][nt][0] + bx, o1 = acc2[mt][nt][1] + by;
            float o2 = acc2[mt][nt][2] + bx, o3 = acc2[mt][nt][3] + by;
            n0s += o0 * o0 + o1 * o1;
            n1s += o2 * o2 + o3 * o3;
            *(__half2*)(H2s + r0 * SH + cb) = __floats2half2_rn(o0, o1);
            *(__half2*)(H2s + (r0 + 8) * SH + cb) = __floats2half2_rn(o2, o3);
        }
        n0s += __shfl_xor_sync(0xffffffffu, n0s, 1);
        n0s += __shfl_xor_sync(0xffffffffu, n0s, 2);
        n1s += __shfl_xor_sync(0xffffffffu, n1s, 1);
        n1s += __shfl_xor_sync(0xffffffffu, n1s, 2);
        if (lc == 0) {
            normw[r0 * 2 + wn] = n0s;
            normw[(r0 + 8) * 2 + wn] = n1s;
        }
    }
    __syncthreads();

    // writeout: fp16 rows, 2 threads per pair-row (128 B = 8 uint4 each)
    {
        int r = tid >> 1, hf = tid & 1;
        const uint4* src = (const uint4*)(smc + OH2 + r * (SH * 2) + hf * 128);
        uint4* dst = (uint4*)(g_p + (size_t)poff[r] * DD + hf * 64);
#pragma unroll
        for (int u = 0; u < 8; u++) dst[u] = src[u];
    }
    if (tid < 128) {
        float ss = normw[tid * 2] + normw[tid * 2 + 1];
        g_s[poff[tid]] = sqrtf(fmaxf(ss, 1e-30f));
    }
}

// ---------------- head: fp16 mma, 128x128 tiles ----------------
#define OHX 0
#define OHW 34816
#define OHB 69632
#define HD_SMEM_BYTES 70144

__global__ __launch_bounds__(256) void head_mma(
    const float* __restrict__ headW, const float* __restrict__ headb,
    float* __restrict__ out) {
    extern __shared__ char smc[];
    __half* Xh = (__half*)(smc + OHX);
    __half* Wh = (__half*)(smc + OHW);
    float* biass = (float*)(smc + OHB);
    float* Pf = (float*)smc;

    const int tid = threadIdx.x;
    const int lane = tid & 31;
    const int warp = tid >> 5;
    const int wm = warp >> 1;
    const int wn = warp & 1;
    const int lr = lane >> 2;
    const int lc = lane & 3;
    const int lrow = (lane & 7) + ((lane >> 3) & 1) * 8;
    const int lcol = (lane >> 4) * 8;

    const int n0 = blockIdx.x * 128;
    const int m0 = blockIdx.y * 128;

    const uint32_t sb = (uint32_t)__cvta_generic_to_shared(smc);
    const uint32_t x_lane = sb + OHX + (uint32_t)(lrow * SBW + lcol) * 2;
    const uint32_t w_lane = sb + OHW + (uint32_t)(lrow * SBW + lcol) * 2;

    for (int e = tid; e < 128 * 32; e += 256) {
        int r = e >> 5, c4 = e & 31;
        const float4 v = *(const float4*)&g_x[(m0 + r) * DD + c4 * 4];
        __half2* d = (__half2*)(Xh + r * SBW + c4 * 4);
        d[0] = __floats2half2_rn(v.x, v.y);
        d[1] = __floats2half2_rn(v.z, v.w);
    }
    for (int e = tid; e < 128 * 32; e += 256) {
        int k = e >> 5, n4 = e & 31;
        const float4 v = *(const float4*)&headW[(size_t)k * VV + n0 + n4 * 4];
        __half2* d = (__half2*)(Wh + k * SBW + n4 * 4);
        d[0] = __floats2half2_rn(v.x, v.y);
        d[1] = __floats2half2_rn(v.z, v.w);
    }
    if (tid < 128) biass[tid] = headb[n0 + tid];
    __syncthreads();

    float acc[2][8][4] = {};
    uint32_t af[2][4];
    uint32_t bf[4];
#pragma unroll
    for (int ks = 0; ks < 8; ks++) {
        const int kb = ks * 16;
        ldsm4(af[0], x_lane + (uint32_t)((wm * 32) * SBW + kb) * 2);
        ldsm4(af[1], x_lane + (uint32_t)((wm * 32 + 16) * SBW + kb) * 2);
#pragma unroll
        for (int bt = 0; bt < 4; bt++) {
            ldsm4t(bf, w_lane + (uint32_t)(kb * SBW + wn * 64 + bt * 16) * 2);
            mma_f16(acc[0][2 * bt], af[0], bf[0], bf[1]);
            mma_f16(acc[1][2 * bt], af[1], bf[0], bf[1]);
            mma_f16(acc[0][2 * bt + 1], af[0], bf[2], bf[3]);
            mma_f16(acc[1][2 * bt + 1], af[1], bf[2], bf[3]);
        }
    }
    __syncthreads();

#pragma unroll
    for (int mt = 0; mt < 2; mt++) {
        int r0 = wm * 32 + mt * 16 + lr;
#pragma unroll
        for (int nt = 0; nt < 8; nt++) {
            int cb = wn * 64 + nt * 8 + 2 * lc;
            float bx = biass[cb], by = biass[cb + 1];
            *(float2*)(Pf + r0 * SPF + cb) =
                make_float2(acc[mt][nt][0] + bx, acc[mt][nt][1] + by);
            *(float2*)(Pf + (r0 + 8) * SPF + cb) =
                make_float2(acc[mt][nt][2] + bx, acc[mt][nt][3] + by);
        }
    }
    __syncthreads();

    {
        int r = tid >> 1, hf = tid & 1;
        const float* src = Pf + r * SPF + hf * 64;
        float* dst = out + (size_t)(m0 + r) * VV + n0 + hf * 64;
#pragma unroll
        for (int u = 0; u < 64; u += 4)
            *(float4*)(dst + u) = *(const float4*)(src + u);
    }
}

// ---------------- block reductions ----------------
__device__ __forceinline__ float blockSum512(float v, float* red) {
    int tid = threadIdx.x;
    red[tid] = v;
    __syncthreads();
    for (int s = 256; s; s >>= 1) {
        if (tid < s) red[tid] += red[tid + s];
        __syncthreads();
    }
    float r = red[0];
    __syncthreads();
    return r;
}
__device__ __forceinline__ float blockMax512(float v, float* red) {
    int tid = threadIdx.x;
    red[tid] = v;
    __syncthreads();
    for (int s = 256; s; s >>= 1) {
        if (tid < s) red[tid] = fmaxf(red[tid], red[tid + s]);
        __syncthreads();
    }
    float r = red[0];
    __syncthreads();
    return r;
}

// ---------------- phase B: softmax + weighted sum + residual + LN ----------
__global__ __launch_bounds__(512) void pair_reduce_ln(
    const float* __restrict__ lng, const float* __restrict__ lnb) {
    __shared__ float red[512];
    __shared__ float ws[NN];
    __shared__ float accbuf[8][128];
    const int bi = blockIdx.x;
    const int i = bi % NN;
    const int tid = threadIdx.x;
    const int gid = tid >> 6;
    const int c2 = tid & 63;
    const int np = i + 1;
    const float* srow = g_s + (size_t)bi * NN;

    float lm = -1e30f;
    for (int j = tid; j < np; j += 512) lm = fmaxf(lm, srow[j]);
    float m = blockMax512(lm, red);

    float dsum = 0.f;
    for (int j = tid; j < np; j += 512) {
        float w = expf(srow[j] - m);
        ws[j] = w;
        dsum += w;
    }
    float den = blockSum512(dsum, red);

    const __half2* prow = (const __half2*)(g_p + (size_t)bi * NN * DD);
    float ax = 0.f, ay = 0.f;
#pragma unroll 2
    for (int j = gid; j < np; j += 8) {
        float w = ws[j];
        float2 pf = __half22float2(prow[j * 64 + c2]);
        ax = fmaf(w, pf.x, ax);
        ay = fmaf(w, pf.y, ay);
    }
    accbuf[gid][c2 * 2] = ax;
    accbuf[gid][c2 * 2 + 1] = ay;
    __syncthreads();

    float v = 0.f;
    if (tid < 128) {
        float s = 0.f;
#pragma unroll
        for (int g = 0; g < 8; g++) s += accbuf[g][tid];
        v = g_x[bi * DD + tid] + s / den;
    }
    float mean = blockSum512(tid < 128 ? v : 0.f, red) * (1.0f / DD);
    float dv = v - mean;
    float var = blockSum512(tid < 128 ? dv * dv : 0.f, red) * (1.0f / DD);
    if (tid < 128)
        g_x[bi * DD + tid] = dv * rsqrtf(var + 1e-5f) * lng[tid] + lnb[tid];
}

// ---------------- launcher ----------------
extern "C" void kernel_launch(void* const* d_in, const int* in_sizes, int n_in,
                              void* d_out, int out_size) {
    const int* ids = (const int*)d_in[0];
    const float* embw = (const float*)d_in[1];
    const float* pos = (const float*)d_in[2];
    const float* pW1 = (const float*)d_in[3];
    const float* pb1 = (const float*)d_in[4];
    const float* pW2 = (const float*)d_in[5];
    const float* pb2 = (const float*)d_in[6];
    const float* pW3 = (const float*)d_in[7];
    const float* pb3 = (const float*)d_in[8];
    const float* ln1g = (const float*)d_in[9];
    const float* ln1b = (const float*)d_in[10];
    const float* fW1 = (const float*)d_in[11];
    const float* fb1 = (const float*)d_in[12];
    const float* fW2 = (const float*)d_in[13];
    const float* fb2 = (const float*)d_in[14];
    const float* ln2g = (const float*)d_in[15];
    const float* ln2b = (const float*)d_in[16];
    const float* headW = (const float*)d_in[17];
    const float* headb = (const float*)d_in[18];
    float* out = (float*)d_out;

    cudaFuncSetAttribute(pair_mma, cudaFuncAttributeMaxDynamicSharedMemorySize,
                         PM_SMEM_BYTES);
    cudaFuncSetAttribute(head_mma, cudaFuncAttributeMaxDynamicSharedMemorySize,
                         HD_SMEM_BYTES);
    cudaFuncSetAttribute(gemm_mma64<0>, cudaFuncAttributeMaxDynamicSharedMemorySize,
                         GM_SMEM_BYTES);
    cudaFuncSetAttribute(gemm_mma64<1>, cudaFuncAttributeMaxDynamicSharedMemorySize,
                         GM_SMEM_BYTES);
    cudaFuncSetAttribute(ffn2_ln, cudaFuncAttributeMaxDynamicSharedMemorySize,
                         GM_SMEM_BYTES);

    float *xp, *ap, *cp, *hp;
    cudaGetSymbolAddress((void**)&xp, g_x);
    cudaGetSymbolAddress((void**)&ap, g_a);
    cudaGetSymbolAddress((void**)&cp, g_c);
    cudaGetSymbolAddress((void**)&hp, g_h);
    __half *w2hp, *w3hp;
    cudaGetSymbolAddress((void**)&w2hp, g_w2h);
    cudaGetSymbolAddress((void**)&w3hp, g_w3h);

    embed_kernel<<<(BB * NN * DD + 255) / 256, 256>>>(ids, embw, pos);
    convert_w<<<(LL * 256 * 128 + LL * 128 * 128 + 255) / 256, 256>>>(pW2, pW3);

    for (int l = 0; l < LL; l++) {
        const float* W1l = pW1 + (size_t)l * 256 * 256;
        gemm_mma64<0><<<dim3(4, 12), 256, GM_SMEM_BYTES>>>(
            xp, 128, W1l, W1l + 128 * 256, 256, 256,
            pb1 + l * 256, nullptr, ap, cp, 256, 128);
        pair_mma<<<NTILES_MMA, 256, PM_SMEM_BYTES>>>(
            w2hp + (size_t)l * 256 * 128, pb2 + l * 128,
            w3hp + (size_t)l * 128 * 128, pb3 + l * 128);
        pair_reduce_ln<<<BB * NN, 512>>>(ln1g + l * 128, ln1b + l * 128);
        gemm_mma64<1><<<dim3(4, 12), 256, GM_SMEM_BYTES>>>(
            xp, 128, fW1 + (size_t)l * 128 * 512, nullptr, 1 << 30, 512,
            fb1 + l * 512, nullptr, hp, nullptr, 512, 128);
        ffn2_ln<<<12, 256, GM_SMEM_BYTES>>>(
            fW2 + (size_t)l * 512 * 128, fb2 + l * 128,
            ln2g + l * 128, ln2b + l * 128);
    }

    head_mma<<<dim3(VV / 128, 768 / 128), 256, HD_SMEM_BYTES>>>(headW, headb, out);
}

// round 13
// speedup vs baseline: 1.0037x; 1.0037x over previous
#include <cuda_runtime.h>
#include <cuda_fp16.h>
#include <math.h>
#include <stdint.h>

// Problem constants
#define BB 2
#define NN 384
#define DD 128
#define VV 8192
#define LL 2
#define NPAIR_B 73920
#define NPAIR_T 147840
#define PT 128
#define NTILES_MMA 1155      // 147840 / 128

// ---------------- scratch ----------------
__device__ float g_x[BB * NN * DD];
__device__ float g_a[BB * NN * 256];
__device__ float g_c[BB * NN * 256];
__device__ float g_h[BB * NN * 512];
__device__ float g_y[BB * NN * DD];
__device__ __half g_p[(size_t)BB * NN * NN * DD];   // pair vectors, fp16
__device__ float g_s[BB * NN * NN];
__device__ __half g_w2h[LL * 256 * 128];
__device__ __half g_w3h[LL * 128 * 128];

// tanh-form gelu using HW MUFU.TANH
__device__ __forceinline__ float gelu_fast(float x) {
    float x2 = x * x;
    float inner = fmaf(0.0356774081f, x2, 0.7978845608f);
    float u = x * inner;
    float t;
    asm("tanh.approx.f32 %0, %1;" : "=f"(t) : "f"(u));
    float hx = 0.5f * x;
    return fmaf(hx, t, hx);
}

__device__ __forceinline__ void ldsm4(uint32_t* r, uint32_t addr) {
    asm volatile("ldmatrix.sync.aligned.m8n8.x4.shared.b16 {%0,%1,%2,%3}, [%4];"
                 : "=r"(r[0]), "=r"(r[1]), "=r"(r[2]), "=r"(r[3]) : "r"(addr));
}
__device__ __forceinline__ void ldsm4t(uint32_t* r, uint32_t addr) {
    asm volatile("ldmatrix.sync.aligned.m8n8.x4.trans.shared.b16 {%0,%1,%2,%3}, [%4];"
                 : "=r"(r[0]), "=r"(r[1]), "=r"(r[2]), "=r"(r[3]) : "r"(addr));
}
__device__ __forceinline__ void mma_f16(float c[4], const uint32_t a[4],
                                        uint32_t b0, uint32_t b1) {
    asm volatile(
        "mma.sync.aligned.m16n8k16.row.col.f32.f16.f16.f32 "
        "{%0,%1,%2,%3}, {%4,%5,%6,%7}, {%8,%9}, {%0,%1,%2,%3};"
        : "+f"(c[0]), "+f"(c[1]), "+f"(c[2]), "+f"(c[3])
        : "r"(a[0]), "r"(a[1]), "r"(a[2]), "r"(a[3]), "r"(b0), "r"(b1));
}
__device__ __forceinline__ void cpa16(uint32_t daddr, const void* g) {
    asm volatile("cp.async.cg.shared.global [%0], [%1], 16;" :: "r"(daddr), "l"(g));
}
#define CP_COMMIT asm volatile("cp.async.commit_group;")
#define CP_WAIT0 asm volatile("cp.async.wait_group 0;")

// ---------------- weight pre-convert ----------------
__global__ void convert_w(const float* __restrict__ pW2, const float* __restrict__ pW3) {
    int t = blockIdx.x * 256 + threadIdx.x;
    const int n2 = LL * 256 * 128;
    const int n3 = LL * 128 * 128;
    if (t < n2) g_w2h[t] = __float2half(pW2[t]);
    int t3 = t - n2;
    if (t3 >= 0 && t3 < n3) g_w3h[t3] = __float2half(pW3[t3]);
}

// ---------------- embedding ----------------
__global__ void embed_kernel(const int* __restrict__ ids,
                             const float* __restrict__ emb,
                             const float* __restrict__ pos) {
    int t = blockIdx.x * blockDim.x + threadIdx.x;
    if (t >= BB * NN * DD) return;
    int d = t & (DD - 1);
    int bn = t >> 7;
    int n = bn % NN;
    g_x[t] = emb[ids[bn] * DD + d] + pos[n * DD + d];
}

// ================= generic fp16-mma GEMM, 64(M)x128(N) tiles ================
#define SBW 136
#define SPF 132
#define GM_OX 0
#define GM_OW 17408
#define GM_OB 52224
#define GM_SMEM_BYTES 52736

template <int ACT>
__global__ __launch_bounds__(256, 2) void gemm_mma64(
    const float* __restrict__ A, int ldA,
    const float* __restrict__ Wa, const float* __restrict__ Wb, int nsplit, int ldW,
    const float* __restrict__ ba, const float* __restrict__ bb,
    float* __restrict__ Ca, float* __restrict__ Cb, int ldC, int K) {
    extern __shared__ char smc[];
    __half* Xh = (__half*)(smc + GM_OX);
    __half* Wh = (__half*)(smc + GM_OW);
    float* biass = (float*)(smc + GM_OB);
    float* Pf = (float*)smc;

    const int tid = threadIdx.x;
    const int lane = tid & 31;
    const int warp = tid >> 5;
    const int wm = warp >> 2;
    const int wn = warp & 3;
    const int lr = lane >> 2;
    const int lc = lane & 3;
    const int lrow = (lane & 7) + ((lane >> 3) & 1) * 8;
    const int lcol = (lane >> 4) * 8;

    const int n0 = blockIdx.x * 128;
    const int m0 = blockIdx.y * 64;

    const float* Wsrc;
    const float* bsrc;
    float* Cdst;
    if (n0 < nsplit) {
        Wsrc = Wa + n0;
        bsrc = ba ? ba + n0 : nullptr;
        Cdst = Ca + n0;
    } else {
        int nn = n0 - nsplit;
        Wsrc = Wb + nn;
        bsrc = bb ? bb + nn : nullptr;
        Cdst = Cb + nn;
    }

    const uint32_t sb = (uint32_t)__cvta_generic_to_shared(smc);
    const uint32_t x_lane = sb + GM_OX + (uint32_t)(lrow * SBW + lcol) * 2;
    const uint32_t w_lane = sb + GM_OW + (uint32_t)(lrow * SBW + lcol) * 2;

    if (tid < 128) biass[tid] = bsrc ? bsrc[tid] : 0.f;

    float acc[2][4][4] = {};
    uint32_t af[2][4];
    uint32_t bf[4];

    const int nkc = K >> 7;
    for (int kc = 0; kc < nkc; kc++) {
        const int k0 = kc << 7;
        for (int e = tid; e < 64 * 32; e += 256) {
            int r = e >> 5, c4 = e & 31;
            const float4 v = *(const float4*)&A[(size_t)(m0 + r) * ldA + k0 + c4 * 4];
            __half2* d = (__half2*)(Xh + r * SBW + c4 * 4);
            d[0] = __floats2half2_rn(v.x, v.y);
            d[1] = __floats2half2_rn(v.z, v.w);
        }
        for (int e = tid; e < 128 * 32; e += 256) {
            int k = e >> 5, n4 = e & 31;
            const float4 v = *(const float4*)&Wsrc[(size_t)(k0 + k) * ldW + n4 * 4];
            __half2* d = (__half2*)(Wh + k * SBW + n4 * 4);
            d[0] = __floats2half2_rn(v.x, v.y);
            d[1] = __floats2half2_rn(v.z, v.w);
        }
        __syncthreads();
#pragma unroll
        for (int ks = 0; ks < 8; ks++) {
            const int kb = ks * 16;
            ldsm4(af[0], x_lane + (uint32_t)((wm * 32) * SBW + kb) * 2);
            ldsm4(af[1], x_lane + (uint32_t)((wm * 32 + 16) * SBW + kb) * 2);
#pragma unroll
            for (int bt = 0; bt < 2; bt++) {
                ldsm4t(bf, w_lane + (uint32_t)(kb * SBW + wn * 32 + bt * 16) * 2);
                mma_f16(acc[0][2 * bt], af[0], bf[0], bf[1]);
                mma_f16(acc[1][2 * bt], af[1], bf[0], bf[1]);
                mma_f16(acc[0][2 * bt + 1], af[0], bf[2], bf[3]);
                mma_f16(acc[1][2 * bt + 1], af[1], bf[2], bf[3]);
            }
        }
        __syncthreads();
    }

#pragma unroll
    for (int mt = 0; mt < 2; mt++) {
        int r0 = wm * 32 + mt * 16 + lr;
#pragma unroll
        for (int nt = 0; nt < 4; nt++) {
            int cb = wn * 32 + nt * 8 + 2 * lc;
            float o0 = acc[mt][nt][0] + biass[cb];
            float o1 = acc[mt][nt][1] + biass[cb + 1];
            float o2 = acc[mt][nt][2] + biass[cb];
            float o3 = acc[mt][nt][3] + biass[cb + 1];
            if (ACT == 1) {
                o0 = gelu_fast(o0); o1 = gelu_fast(o1);
                o2 = gelu_fast(o2); o3 = gelu_fast(o3);
            }
            *(float2*)(Pf + r0 * SPF + cb) = make_float2(o0, o1);
            *(float2*)(Pf + (r0 + 8) * SPF + cb) = make_float2(o2, o3);
        }
    }
    __syncthreads();

    {
        int r = tid >> 2, q = tid & 3;
        const float* src = Pf + r * SPF + q * 32;
        float* dst = Cdst + (size_t)(m0 + r) * ldC + q * 32;
#pragma unroll
        for (int u = 0; u < 32; u += 4)
            *(float4*)(dst + u) = *(const float4*)(src + u);
    }
}

// ---------------- pair kernel: dbl-buffered H1 + W, fp16 mma ---------------
#define SA 72
#define SH 136
#define OWB0 0
#define OWB1 17408
#define OH1A 34816
#define OH1B 53248
#define OH2 71680
#define OB2 106496
#define OB3 107008
#define ORA 107520
#define ORC 108032
#define OPO 108544
#define ONW 109056
#define PM_SMEM_BYTES 110080

__global__ __launch_bounds__(256, 2) void pair_mma(
    const __half* __restrict__ W2h, const float* __restrict__ b2,
    const __half* __restrict__ W3h, const float* __restrict__ b3) {
    extern __shared__ char smc[];
    __half* H2s = (__half*)(smc + OH2);
    float* b2s = (float*)(smc + OB2);
    float* b3s = (float*)(smc + OB3);
    int* rowA = (int*)(smc + ORA);
    int* rowC = (int*)(smc + ORC);
    int* poff = (int*)(smc + OPO);
    float* normw = (float*)(smc + ONW);

    const int tid = threadIdx.x;
    const int lane = tid & 31;
    const int warp = tid >> 5;
    const int wm = warp >> 1;
    const int wn = warp & 1;
    const int lr = lane >> 2;
    const int lc = lane & 3;
    const int lrow = (lane & 7) + ((lane >> 3) & 1) * 8;
    const int lcol = (lane >> 4) * 8;

    const uint32_t sb = (uint32_t)__cvta_generic_to_shared(smc);
    const uint32_t h1_lane[2] = {
        sb + OH1A + (uint32_t)(lrow * SA + lcol) * 2,
        sb + OH1B + (uint32_t)(lrow * SA + lcol) * 2};
    const uint32_t h2_lane = sb + OH2 + (uint32_t)(lrow * SH + lcol) * 2;
    const uint32_t w_lane[2] = {
        sb + OWB0 + (uint32_t)(lrow * SBW + lcol) * 2,
        sb + OWB1 + (uint32_t)(lrow * SBW + lcol) * 2};

    auto issue_w = [&](const __half* src, uint32_t dbase) {
#pragma unroll
        for (int e = tid; e < 1024; e += 256) {
            int row = e >> 4, seg = e & 15;
            cpa16(dbase + row * (SBW * 2) + seg * 16, src + row * 128 + seg * 8);
        }
        CP_COMMIT;
    };
    auto build_h1 = [&](int k0, char* dstbase) {
#pragma unroll
        for (int e = tid; e < 128 * 16; e += 256) {
            int r = e >> 4, c4 = e & 15;
            const float4 av = *(const float4*)&g_a[rowA[r] * 256 + k0 + c4 * 4];
            const float4 cv = *(const float4*)&g_c[rowC[r] * 256 + k0 + c4 * 4];
            __half2* d = (__half2*)(dstbase + (r * SA + c4 * 4) * 2);
            d[0] = __floats2half2_rn(gelu_fast(av.x + cv.x), gelu_fast(av.y + cv.y));
            d[1] = __floats2half2_rn(gelu_fast(av.z + cv.z), gelu_fast(av.w + cv.w));
        }
    };

    issue_w(W2h, sb + OWB0);

    if (tid < 128) {
        b2s[tid] = b2[tid];
        b3s[tid] = b3[tid];
        int g = blockIdx.x * PT + tid;
        int b = (g >= NPAIR_B) ? 1 : 0;
        int idx = g - b * NPAIR_B;
        int i = (int)((sqrtf(8.0f * (float)idx + 1.0f) - 1.0f) * 0.5f);
        while ((i + 1) * (i + 2) / 2 <= idx) ++i;
        while (i * (i + 1) / 2 > idx) --i;
        int j = idx - i * (i + 1) / 2;
        rowA[tid] = b * NN + i;
        rowC[tid] = b * NN + j;
        poff[tid] = (b * NN + i) * NN + j;
    }
    __syncthreads();

    build_h1(0, smc + OH1A);
    CP_WAIT0;
    __syncthreads();

    float acc[2][8][4] = {};
    uint32_t af[2][4];
    uint32_t bf[4];

    // GEMM1: K=256, 4 chunks; H1 double-buffered, build overlaps mma, 1 sync/chunk
    for (int kc = 0; kc < 4; kc++) {
        if (kc < 3) issue_w(W2h + (kc + 1) * 64 * 128, sb + (((kc + 1) & 1) ? OWB1 : OWB0));
        const uint32_t h1l = h1_lane[kc & 1];
        const uint32_t wl = w_lane[kc & 1];
#pragma unroll
        for (int ks = 0; ks < 4; ks++) {
            const int kb = ks * 16;
            ldsm4(af[0], h1l + (uint32_t)((wm * 32) * SA + kb) * 2);
            ldsm4(af[1], h1l + (uint32_t)((wm * 32 + 16) * SA + kb) * 2);
#pragma unroll
            for (int bt = 0; bt < 4; bt++) {
                ldsm4t(bf, wl + (uint32_t)(kb * SBW + wn * 64 + bt * 16) * 2);
                mma_f16(acc[0][2 * bt], af[0], bf[0], bf[1]);
                mma_f16(acc[1][2 * bt], af[1], bf[0], bf[1]);
                mma_f16(acc[0][2 * bt + 1], af[0], bf[2], bf[3]);
                mma_f16(acc[1][2 * bt + 1], af[1], bf[2], bf[3]);
            }
        }
        if (kc < 3) {
            build_h1((kc + 1) * 64, smc + (((kc + 1) & 1) ? OH1B : OH1A));
            CP_WAIT0;
        }
        __syncthreads();
    }

    // prefetch both W3 chunks (overlaps epilogue 1)
#pragma unroll
    for (int ch = 0; ch < 2; ch++)
        issue_w(W3h + ch * 64 * 128, sb + (ch ? OWB1 : OWB0));

    // epilogue 1: +b2, gelu, half -> H2s
#pragma unroll
    for (int mt = 0; mt < 2; mt++) {
        int r0 = wm * 32 + mt * 16 + lr;
#pragma unroll
        for (int nt = 0; nt < 8; nt++) {
            int cb = wn * 64 + nt * 8 + 2 * lc;
            float bx = b2s[cb], by = b2s[cb + 1];
            *(__half2*)(H2s + r0 * SH + cb) =
                __floats2half2_rn(gelu_fast(acc[mt][nt][0] + bx), gelu_fast(acc[mt][nt][1] + by));
            *(__half2*)(H2s + (r0 + 8) * SH + cb) =
                __floats2half2_rn(gelu_fast(acc[mt][nt][2] + bx), gelu_fast(acc[mt][nt][3] + by));
        }
    }
    CP_WAIT0;
    __syncthreads();

    // GEMM2: K=128, 8 uninterrupted k-steps
    float acc2[2][8][4] = {};
#pragma unroll
    for (int ks = 0; ks < 8; ks++) {
        const int kbg = ks * 16;
        const uint32_t wl = w_lane[(kbg & 64) ? 1 : 0];
        const int kb = kbg & 63;
        ldsm4(af[0], h2_lane + (uint32_t)((wm * 32) * SH + kbg) * 2);
        ldsm4(af[1], h2_lane + (uint32_t)((wm * 32 + 16) * SH + kbg) * 2);
#pragma unroll
        for (int bt = 0; bt < 4; bt++) {
            ldsm4t(bf, wl + (uint32_t)(kb * SBW + wn * 64 + bt * 16) * 2);
            mma_f16(acc2[0][2 * bt], af[0], bf[0], bf[1]);
            mma_f16(acc2[1][2 * bt], af[1], bf[0], bf[1]);
            mma_f16(acc2[0][2 * bt + 1], af[0], bf[2], bf[3]);
            mma_f16(acc2[1][2 * bt + 1], af[1], bf[2], bf[3]);
        }
    }
    __syncthreads();   // H2s reads done -> safe to overwrite with fp16 P

    // epilogue 2: +b3, fp16 into H2s region, norms from fp32 registers
#pragma unroll
    for (int mt = 0; mt < 2; mt++) {
        int r0 = wm * 32 + mt * 16 + lr;
        float n0s = 0.f, n1s = 0.f;
#pragma unroll
        for (int nt = 0; nt < 8; nt++) {
            int cb = wn * 64 + nt * 8 + 2 * lc;
            float bx = b3s[cb], by = b3s[cb + 1];
            float o0 = acc2[mt][nt][0] + bx, o1 = acc2[mt][nt][1] + by;
            float o2 = acc2[mt][nt][2] + bx, o3 = acc2[mt][nt][3] + by;
            n0s += o0 * o0 + o1 * o1;
            n1s += o2 * o2 + o3 * o3;
            *(__half2*)(H2s + r0 * SH + cb) = __floats2half2_rn(o0, o1);
            *(__half2*)(H2s + (r0 + 8) * SH + cb) = __floats2half2_rn(o2, o3);
        }
        n0s += __shfl_xor_sync(0xffffffffu, n0s, 1);
        n0s += __shfl_xor_sync(0xffffffffu, n0s, 2);
        n1s += __shfl_xor_sync(0xffffffffu, n1s, 1);
        n1s += __shfl_xor_sync(0xffffffffu, n1s, 2);
        if (lc == 0) {
            normw[r0 * 2 + wn] = n0s;
            normw[(r0 + 8) * 2 + wn] = n1s;
        }
    }
    __syncthreads();

    // writeout: fp16 rows, 2 threads per pair-row (128 B = 8 uint4 each)
    {
        int r = tid >> 1, hf = tid & 1;
        const uint4* src = (const uint4*)(smc + OH2 + r * (SH * 2) + hf * 128);
        uint4* dst = (uint4*)(g_p + (size_t)poff[r] * DD + hf * 64);
#pragma unroll
        for (int u = 0; u < 8; u++) dst[u] = src[u];
    }
    if (tid < 128) {
        float ss = normw[tid * 2] + normw[tid * 2 + 1];
        g_s[poff[tid]] = sqrtf(fmaxf(ss, 1e-30f));
    }
}

// ---------------- head: fp16 mma, 128x128 tiles ----------------
#define OHX 0
#define OHW 34816
#define OHB 69632
#define HD_SMEM_BYTES 70144

__global__ __launch_bounds__(256) void head_mma(
    const float* __restrict__ headW, const float* __restrict__ headb,
    float* __restrict__ out) {
    extern __shared__ char smc[];
    __half* Xh = (__half*)(smc + OHX);
    __half* Wh = (__half*)(smc + OHW);
    float* biass = (float*)(smc + OHB);
    float* Pf = (float*)smc;

    const int tid = threadIdx.x;
    const int lane = tid & 31;
    const int warp = tid >> 5;
    const int wm = warp >> 1;
    const int wn = warp & 1;
    const int lr = lane >> 2;
    const int lc = lane & 3;
    const int lrow = (lane & 7) + ((lane >> 3) & 1) * 8;
    const int lcol = (lane >> 4) * 8;

    const int n0 = blockIdx.x * 128;
    const int m0 = blockIdx.y * 128;

    const uint32_t sb = (uint32_t)__cvta_generic_to_shared(smc);
    const uint32_t x_lane = sb + OHX + (uint32_t)(lrow * SBW + lcol) * 2;
    const uint32_t w_lane = sb + OHW + (uint32_t)(lrow * SBW + lcol) * 2;

    for (int e = tid; e < 128 * 32; e += 256) {
        int r = e >> 5, c4 = e & 31;
        const float4 v = *(const float4*)&g_x[(m0 + r) * DD + c4 * 4];
        __half2* d = (__half2*)(Xh + r * SBW + c4 * 4);
        d[0] = __floats2half2_rn(v.x, v.y);
        d[1] = __floats2half2_rn(v.z, v.w);
    }
    for (int e = tid; e < 128 * 32; e += 256) {
        int k = e >> 5, n4 = e & 31;
        const float4 v = *(const float4*)&headW[(size_t)k * VV + n0 + n4 * 4];
        __half2* d = (__half2*)(Wh + k * SBW + n4 * 4);
        d[0] = __floats2half2_rn(v.x, v.y);
        d[1] = __floats2half2_rn(v.z, v.w);
    }
    if (tid < 128) biass[tid] = headb[n0 + tid];
    __syncthreads();

    float acc[2][8][4] = {};
    uint32_t af[2][4];
    uint32_t bf[4];
#pragma unroll
    for (int ks = 0; ks < 8; ks++) {
        const int kb = ks * 16;
        ldsm4(af[0], x_lane + (uint32_t)((wm * 32) * SBW + kb) * 2);
        ldsm4(af[1], x_lane + (uint32_t)((wm * 32 + 16) * SBW + kb) * 2);
#pragma unroll
        for (int bt = 0; bt < 4; bt++) {
            ldsm4t(bf, w_lane + (uint32_t)(kb * SBW + wn * 64 + bt * 16) * 2);
            mma_f16(acc[0][2 * bt], af[0], bf[0], bf[1]);
            mma_f16(acc[1][2 * bt], af[1], bf[0], bf[1]);
            mma_f16(acc[0][2 * bt + 1], af[0], bf[2], bf[3]);
            mma_f16(acc[1][2 * bt + 1], af[1], bf[2], bf[3]);
        }
    }
    __syncthreads();

#pragma unroll
    for (int mt = 0; mt < 2; mt++) {
        int r0 = wm * 32 + mt * 16 + lr;
#pragma unroll
        for (int nt = 0; nt < 8; nt++) {
            int cb = wn * 64 + nt * 8 + 2 * lc;
            float bx = biass[cb], by = biass[cb + 1];
            *(float2*)(Pf + r0 * SPF + cb) =
                make_float2(acc[mt][nt][0] + bx, acc[mt][nt][1] + by);
            *(float2*)(Pf + (r0 + 8) * SPF + cb) =
                make_float2(acc[mt][nt][2] + bx, acc[mt][nt][3] + by);
        }
    }
    __syncthreads();

    {
        int r = tid >> 1, hf = tid & 1;
        const float* src = Pf + r * SPF + hf * 64;
        float* dst = out + (size_t)(m0 + r) * VV + n0 + hf * 64;
#pragma unroll
        for (int u = 0; u < 64; u += 4)
            *(float4*)(dst + u) = *(const float4*)(src + u);
    }
}

// ---------------- block reductions ----------------
__device__ __forceinline__ float blockSum512(float v, float* red) {
    int tid = threadIdx.x;
    red[tid] = v;
    __syncthreads();
    for (int s = 256; s; s >>= 1) {
        if (tid < s) red[tid] += red[tid + s];
        __syncthreads();
    }
    float r = red[0];
    __syncthreads();
    return r;
}
__device__ __forceinline__ float blockSum128(float v, float* red) {
    int tid = threadIdx.x;
    red[tid] = v;
    __syncthreads();
    for (int s = 64; s; s >>= 1) {
        if (tid < s) red[tid] += red[tid + s];
        __syncthreads();
    }
    float r = red[0];
    __syncthreads();
    return r;
}

// ---------------- phase B: softmax + weighted sum + residual + LN ----------
// norms are >= 0 and small -> exp() needs no max-centering (identical math)
__global__ __launch_bounds__(512) void pair_reduce_ln(
    const float* __restrict__ lng, const float* __restrict__ lnb) {
    __shared__ float red[512];
    __shared__ float ws[NN];
    __shared__ float accbuf[8][128];
    const int bi = blockIdx.x;
    const int i = bi % NN;
    const int tid = threadIdx.x;
    const int gid = tid >> 6;
    const int c2 = tid & 63;
    const int np = i + 1;
    const float* srow = g_s + (size_t)bi * NN;

    float dsum = 0.f;
    for (int j = tid; j < np; j += 512) {
        float w = expf(srow[j]);
        ws[j] = w;
        dsum += w;
    }
    float den = blockSum512(dsum, red);   // barrier -> ws visible

    const __half2* prow = (const __half2*)(g_p + (size_t)bi * NN * DD);
    float ax = 0.f, ay = 0.f;
#pragma unroll 2
    for (int j = gid; j < np; j += 8) {
        float w = ws[j];
        float2 pf = __half22float2(prow[j * 64 + c2]);
        ax = fmaf(w, pf.x, ax);
        ay = fmaf(w, pf.y, ay);
    }
    accbuf[gid][c2 * 2] = ax;
    accbuf[gid][c2 * 2 + 1] = ay;
    __syncthreads();

    float v = 0.f;
    if (tid < 128) {
        float s = 0.f;
#pragma unroll
        for (int g = 0; g < 8; g++) s += accbuf[g][tid];
        v = g_x[bi * DD + tid] + s / den;
    }
    float mean = blockSum512(tid < 128 ? v : 0.f, red) * (1.0f / DD);
    float dv = v - mean;
    float var = blockSum512(tid < 128 ? dv * dv : 0.f, red) * (1.0f / DD);
    if (tid < 128)
        g_x[bi * DD + tid] = dv * rsqrtf(var + 1e-5f) * lng[tid] + lnb[tid];
}

// ---------------- FFN residual + LN ----------------
__global__ __launch_bounds__(128) void add_ln(
    const float* __restrict__ lng, const float* __restrict__ lnb) {
    __shared__ float red[128];
    const int bi = blockIdx.x;
    const int tid = threadIdx.x;
    float v = g_x[bi * DD + tid] + g_y[bi * DD + tid];
    float mean = blockSum128(v, red) * (1.0f / DD);
    float dv = v - mean;
    float var = blockSum128(dv * dv, red) * (1.0f / DD);
    g_x[bi * DD + tid] = dv * rsqrtf(var + 1e-5f) * lng[tid] + lnb[tid];
}

// ---------------- launcher ----------------
extern "C" void kernel_launch(void* const* d_in, const int* in_sizes, int n_in,
                              void* d_out, int out_size) {
    const int* ids = (const int*)d_in[0];
    const float* embw = (const float*)d_in[1];
    const float* pos = (const float*)d_in[2];
    const float* pW1 = (const float*)d_in[3];
    const float* pb1 = (const float*)d_in[4];
    const float* pW2 = (const float*)d_in[5];
    const float* pb2 = (const float*)d_in[6];
    const float* pW3 = (const float*)d_in[7];
    const float* pb3 = (const float*)d_in[8];
    const float* ln1g = (const float*)d_in[9];
    const float* ln1b = (const float*)d_in[10];
    const float* fW1 = (const float*)d_in[11];
    const float* fb1 = (const float*)d_in[12];
    const float* fW2 = (const float*)d_in[13];
    const float* fb2 = (const float*)d_in[14];
    const float* ln2g = (const float*)d_in[15];
    const float* ln2b = (const float*)d_in[16];
    const float* headW = (const float*)d_in[17];
    const float* headb = (const float*)d_in[18];
    float* out = (float*)d_out;

    cudaFuncSetAttribute(pair_mma, cudaFuncAttributeMaxDynamicSharedMemorySize,
                         PM_SMEM_BYTES);
    cudaFuncSetAttribute(head_mma, cudaFuncAttributeMaxDynamicSharedMemorySize,
                         HD_SMEM_BYTES);
    cudaFuncSetAttribute(gemm_mma64<0>, cudaFuncAttributeMaxDynamicSharedMemorySize,
                         GM_SMEM_BYTES);
    cudaFuncSetAttribute(gemm_mma64<1>, cudaFuncAttributeMaxDynamicSharedMemorySize,
                         GM_SMEM_BYTES);

    float *xp, *ap, *cp, *hp, *yp;
    cudaGetSymbolAddress((void**)&xp, g_x);
    cudaGetSymbolAddress((void**)&ap, g_a);
    cudaGetSymbolAddress((void**)&cp, g_c);
    cudaGetSymbolAddress((void**)&hp, g_h);
    cudaGetSymbolAddress((void**)&yp, g_y);
    __half *w2hp, *w3hp;
    cudaGetSymbolAddress((void**)&w2hp, g_w2h);
    cudaGetSymbolAddress((void**)&w3hp, g_w3h);

    embed_kernel<<<(BB * NN * DD + 255) / 256, 256>>>(ids, embw, pos);
    convert_w<<<(LL * 256 * 128 + LL * 128 * 128 + 255) / 256, 256>>>(pW2, pW3);

    for (int l = 0; l < LL; l++) {
        const float* W1l = pW1 + (size_t)l * 256 * 256;
        gemm_mma64<0><<<dim3(4, 12), 256, GM_SMEM_BYTES>>>(
            xp, 128, W1l, W1l + 128 * 256, 256, 256,
            pb1 + l * 256, nullptr, ap, cp, 256, 128);
        pair_mma<<<NTILES_MMA, 256, PM_SMEM_BYTES>>>(
            w2hp + (size_t)l * 256 * 128, pb2 + l * 128,
            w3hp + (size_t)l * 128 * 128, pb3 + l * 128);
        pair_reduce_ln<<<BB * NN, 512>>>(ln1g + l * 128, ln1b + l * 128);
        gemm_mma64<1><<<dim3(4, 12), 256, GM_SMEM_BYTES>>>(
            xp, 128, fW1 + (size_t)l * 128 * 512, nullptr, 1 << 30, 512,
            fb1 + l * 512, nullptr, hp, nullptr, 512, 128);
        gemm_mma64<0><<<dim3(1, 12), 256, GM_SMEM_BYTES>>>(
            hp, 512, fW2 + (size_t)l * 512 * 128, nullptr, 1 << 30, 128,
            fb2 + l * 128, nullptr, yp, nullptr, 128, 512);
        add_ln<<<BB * NN, 128>>>(ln2g + l * 128, ln2b + l * 128);
    }

    head_mma<<<dim3(VV / 128, 768 / 128), 256, HD_SMEM_BYTES>>>(headW, headb, out);
}

// round 14
// speedup vs baseline: 1.0313x; 1.0275x over previous
#include <cuda_runtime.h>
#include <cuda_fp16.h>
#include <math.h>
#include <stdint.h>

// Problem constants
#define BB 2
#define NN 384
#define DD 128
#define VV 8192
#define LL 2
#define NPAIR_B 73920
#define NPAIR_T 147840
#define PT 128
#define NTILES_MMA 1155      // 147840 / 128

// ---------------- scratch ----------------
__device__ float g_x[BB * NN * DD];
__device__ float g_a[BB * NN * 256];
__device__ float g_c[BB * NN * 256];
__device__ float g_h[BB * NN * 512];
__device__ float g_y[BB * NN * DD];
__device__ __half g_p[(size_t)BB * NN * NN * DD];   // pair vectors, fp16
__device__ float g_s[BB * NN * NN];
__device__ __half g_w2h[LL * 256 * 128];
__device__ __half g_w3h[LL * 128 * 128];

// scalar tanh-form gelu (HW MUFU.TANH)
__device__ __forceinline__ float gelu_fast(float x) {
    float x2 = x * x;
    float inner = fmaf(0.0356774081f, x2, 0.7978845608f);
    float u = x * inner;
    float t;
    asm("tanh.approx.f32 %0, %1;" : "=f"(t) : "f"(u));
    float hx = 0.5f * x;
    return fmaf(hx, t, hx);
}

// half2 gelu: 2 elements per MUFU via tanh.approx.f16x2; all-HFMA2 polynomial
__device__ __forceinline__ __half2 gelu2(__half2 x) {
    const __half2 c1 = __float2half2_rn(0.0356774081f);
    const __half2 c0 = __float2half2_rn(0.7978845608f);
    const __half2 hh = __float2half2_rn(0.5f);
    __half2 x2 = __hmul2(x, x);
    __half2 inner = __hfma2(c1, x2, c0);
    __half2 u = __hmul2(x, inner);
    uint32_t ui, ti;
    ui = *(uint32_t*)&u;
    asm("tanh.approx.f16x2 %0, %1;" : "=r"(ti) : "r"(ui));
    __half2 t = *(__half2*)&ti;
    __half2 hx = __hmul2(hh, x);
    return __hfma2(hx, t, hx);
}

__device__ __forceinline__ void ldsm4(uint32_t* r, uint32_t addr) {
    asm volatile("ldmatrix.sync.aligned.m8n8.x4.shared.b16 {%0,%1,%2,%3}, [%4];"
                 : "=r"(r[0]), "=r"(r[1]), "=r"(r[2]), "=r"(r[3]) : "r"(addr));
}
__device__ __forceinline__ void ldsm4t(uint32_t* r, uint32_t addr) {
    asm volatile("ldmatrix.sync.aligned.m8n8.x4.trans.shared.b16 {%0,%1,%2,%3}, [%4];"
                 : "=r"(r[0]), "=r"(r[1]), "=r"(r[2]), "=r"(r[3]) : "r"(addr));
}
__device__ __forceinline__ void mma_f16(float c[4], const uint32_t a[4],
                                        uint32_t b0, uint32_t b1) {
    asm volatile(
        "mma.sync.aligned.m16n8k16.row.col.f32.f16.f16.f32 "
        "{%0,%1,%2,%3}, {%4,%5,%6,%7}, {%8,%9}, {%0,%1,%2,%3};"
        : "+f"(c[0]), "+f"(c[1]), "+f"(c[2]), "+f"(c[3])
        : "r"(a[0]), "r"(a[1]), "r"(a[2]), "r"(a[3]), "r"(b0), "r"(b1));
}
__device__ __forceinline__ void cpa16(uint32_t daddr, const void* g) {
    asm volatile("cp.async.cg.shared.global [%0], [%1], 16;" :: "r"(daddr), "l"(g));
}
#define CP_COMMIT asm volatile("cp.async.commit_group;")
#define CP_WAIT0 asm volatile("cp.async.wait_group 0;")

// ---------------- weight pre-convert ----------------
__global__ void convert_w(const float* __restrict__ pW2, const float* __restrict__ pW3) {
    int t = blockIdx.x * 256 + threadIdx.x;
    const int n2 = LL * 256 * 128;
    const int n3 = LL * 128 * 128;
    if (t < n2) g_w2h[t] = __float2half(pW2[t]);
    int t3 = t - n2;
    if (t3 >= 0 && t3 < n3) g_w3h[t3] = __float2half(pW3[t3]);
}

// ---------------- embedding ----------------
__global__ void embed_kernel(const int* __restrict__ ids,
                             const float* __restrict__ emb,
                             const float* __restrict__ pos) {
    int t = blockIdx.x * blockDim.x + threadIdx.x;
    if (t >= BB * NN * DD) return;
    int d = t & (DD - 1);
    int bn = t >> 7;
    int n = bn % NN;
    g_x[t] = emb[ids[bn] * DD + d] + pos[n * DD + d];
}

// ================= generic fp16-mma GEMM, 64(M)x128(N) tiles ================
#define SBW 136
#define SPF 132
#define GM_OX 0
#define GM_OW 17408
#define GM_OB 52224
#define GM_SMEM_BYTES 52736

template <int ACT>
__global__ __launch_bounds__(256, 2) void gemm_mma64(
    const float* __restrict__ A, int ldA,
    const float* __restrict__ Wa, const float* __restrict__ Wb, int nsplit, int ldW,
    const float* __restrict__ ba, const float* __restrict__ bb,
    float* __restrict__ Ca, float* __restrict__ Cb, int ldC, int K) {
    extern __shared__ char smc[];
    __half* Xh = (__half*)(smc + GM_OX);
    __half* Wh = (__half*)(smc + GM_OW);
    float* biass = (float*)(smc + GM_OB);
    float* Pf = (float*)smc;

    const int tid = threadIdx.x;
    const int lane = tid & 31;
    const int warp = tid >> 5;
    const int wm = warp >> 2;
    const int wn = warp & 3;
    const int lr = lane >> 2;
    const int lc = lane & 3;
    const int lrow = (lane & 7) + ((lane >> 3) & 1) * 8;
    const int lcol = (lane >> 4) * 8;

    const int n0 = blockIdx.x * 128;
    const int m0 = blockIdx.y * 64;

    const float* Wsrc;
    const float* bsrc;
    float* Cdst;
    if (n0 < nsplit) {
        Wsrc = Wa + n0;
        bsrc = ba ? ba + n0 : nullptr;
        Cdst = Ca + n0;
    } else {
        int nn = n0 - nsplit;
        Wsrc = Wb + nn;
        bsrc = bb ? bb + nn : nullptr;
        Cdst = Cb + nn;
    }

    const uint32_t sb = (uint32_t)__cvta_generic_to_shared(smc);
    const uint32_t x_lane = sb + GM_OX + (uint32_t)(lrow * SBW + lcol) * 2;
    const uint32_t w_lane = sb + GM_OW + (uint32_t)(lrow * SBW + lcol) * 2;

    if (tid < 128) biass[tid] = bsrc ? bsrc[tid] : 0.f;

    float acc[2][4][4] = {};
    uint32_t af[2][4];
    uint32_t bf[4];

    const int nkc = K >> 7;
    for (int kc = 0; kc < nkc; kc++) {
        const int k0 = kc << 7;
        for (int e = tid; e < 64 * 32; e += 256) {
            int r = e >> 5, c4 = e & 31;
            const float4 v = *(const float4*)&A[(size_t)(m0 + r) * ldA + k0 + c4 * 4];
            __half2* d = (__half2*)(Xh + r * SBW + c4 * 4);
            d[0] = __floats2half2_rn(v.x, v.y);
            d[1] = __floats2half2_rn(v.z, v.w);
        }
        for (int e = tid; e < 128 * 32; e += 256) {
            int k = e >> 5, n4 = e & 31;
            const float4 v = *(const float4*)&Wsrc[(size_t)(k0 + k) * ldW + n4 * 4];
            __half2* d = (__half2*)(Wh + k * SBW + n4 * 4);
            d[0] = __floats2half2_rn(v.x, v.y);
            d[1] = __floats2half2_rn(v.z, v.w);
        }
        __syncthreads();
#pragma unroll
        for (int ks = 0; ks < 8; ks++) {
            const int kb = ks * 16;
            ldsm4(af[0], x_lane + (uint32_t)((wm * 32) * SBW + kb) * 2);
            ldsm4(af[1], x_lane + (uint32_t)((wm * 32 + 16) * SBW + kb) * 2);
#pragma unroll
            for (int bt = 0; bt < 2; bt++) {
                ldsm4t(bf, w_lane + (uint32_t)(kb * SBW + wn * 32 + bt * 16) * 2);
                mma_f16(acc[0][2 * bt], af[0], bf[0], bf[1]);
                mma_f16(acc[1][2 * bt], af[1], bf[0], bf[1]);
                mma_f16(acc[0][2 * bt + 1], af[0], bf[2], bf[3]);
                mma_f16(acc[1][2 * bt + 1], af[1], bf[2], bf[3]);
            }
        }
        __syncthreads();
    }

#pragma unroll
    for (int mt = 0; mt < 2; mt++) {
        int r0 = wm * 32 + mt * 16 + lr;
#pragma unroll
        for (int nt = 0; nt < 4; nt++) {
            int cb = wn * 32 + nt * 8 + 2 * lc;
            float o0 = acc[mt][nt][0] + biass[cb];
            float o1 = acc[mt][nt][1] + biass[cb + 1];
            float o2 = acc[mt][nt][2] + biass[cb];
            float o3 = acc[mt][nt][3] + biass[cb + 1];
            if (ACT == 1) {
                float2 f01 = __half22float2(gelu2(__floats2half2_rn(o0, o1)));
                float2 f23 = __half22float2(gelu2(__floats2half2_rn(o2, o3)));
                o0 = f01.x; o1 = f01.y; o2 = f23.x; o3 = f23.y;
            }
            *(float2*)(Pf + r0 * SPF + cb) = make_float2(o0, o1);
            *(float2*)(Pf + (r0 + 8) * SPF + cb) = make_float2(o2, o3);
        }
    }
    __syncthreads();

    {
        int r = tid >> 2, q = tid & 3;
        const float* src = Pf + r * SPF + q * 32;
        float* dst = Cdst + (size_t)(m0 + r) * ldC + q * 32;
#pragma unroll
        for (int u = 0; u < 32; u += 4)
            *(float4*)(dst + u) = *(const float4*)(src + u);
    }
}

// ---------------- pair kernel: chunked, cp.async dbl-buffered W, fp16 mma ---
#define SA 72
#define SH 136
#define OWB0 0
#define OWB1 17408
#define OH1 34816
#define OH2 53248
#define OB2 88064
#define OB3 88576
#define ORA 89088
#define ORC 89600
#define OPO 90112
#define ONW 90624
#define PM_SMEM_BYTES 91648

__global__ __launch_bounds__(256, 2) void pair_mma(
    const __half* __restrict__ W2h, const float* __restrict__ b2,
    const __half* __restrict__ W3h, const float* __restrict__ b3) {
    extern __shared__ char smc[];
    __half* H1s = (__half*)(smc + OH1);
    __half* H2s = (__half*)(smc + OH2);
    float* b2s = (float*)(smc + OB2);
    float* b3s = (float*)(smc + OB3);
    int* rowA = (int*)(smc + ORA);
    int* rowC = (int*)(smc + ORC);
    int* poff = (int*)(smc + OPO);
    float* normw = (float*)(smc + ONW);

    const int tid = threadIdx.x;
    const int lane = tid & 31;
    const int warp = tid >> 5;
    const int wm = warp >> 1;
    const int wn = warp & 1;
    const int lr = lane >> 2;
    const int lc = lane & 3;
    const int lrow = (lane & 7) + ((lane >> 3) & 1) * 8;
    const int lcol = (lane >> 4) * 8;

    const uint32_t sb = (uint32_t)__cvta_generic_to_shared(smc);
    const uint32_t h1_lane = sb + OH1 + (uint32_t)(lrow * SA + lcol) * 2;
    const uint32_t h2_lane = sb + OH2 + (uint32_t)(lrow * SH + lcol) * 2;
    const uint32_t w_lane0 = sb + OWB0 + (uint32_t)(lrow * SBW + lcol) * 2;
    const uint32_t w_lane1 = sb + OWB1 + (uint32_t)(lrow * SBW + lcol) * 2;

    {
        const __half* src = W2h;
        uint32_t dbase = sb + OWB0;
#pragma unroll
        for (int e = tid; e < 1024; e += 256) {
            int row = e >> 4, seg = e & 15;
            cpa16(dbase + row * (SBW * 2) + seg * 16, src + row * 128 + seg * 8);
        }
        CP_COMMIT;
    }

    if (tid < 128) {
        b2s[tid] = b2[tid];
        b3s[tid] = b3[tid];
        int g = blockIdx.x * PT + tid;
        int b = (g >= NPAIR_B) ? 1 : 0;
        int idx = g - b * NPAIR_B;
        int i = (int)((sqrtf(8.0f * (float)idx + 1.0f) - 1.0f) * 0.5f);
        while ((i + 1) * (i + 2) / 2 <= idx) ++i;
        while (i * (i + 1) / 2 > idx) --i;
        int j = idx - i * (i + 1) / 2;
        rowA[tid] = b * NN + i;
        rowC[tid] = b * NN + j;
        poff[tid] = (b * NN + i) * NN + j;
    }
    __syncthreads();

#pragma unroll
    for (int e = tid; e < 128 * 16; e += 256) {
        int r = e >> 4, c4 = e & 15;
        const float4 av = *(const float4*)&g_a[rowA[r] * 256 + c4 * 4];
        const float4 cv = *(const float4*)&g_c[rowC[r] * 256 + c4 * 4];
        __half2* d = (__half2*)(H1s + r * SA + c4 * 4);
        d[0] = gelu2(__floats2half2_rn(av.x + cv.x, av.y + cv.y));
        d[1] = gelu2(__floats2half2_rn(av.z + cv.z, av.w + cv.w));
    }
    CP_WAIT0;
    __syncthreads();

    float acc[2][8][4] = {};
    uint32_t af[2][4];
    uint32_t bf[4];

    for (int kc = 0; kc < 4; kc++) {
        if (kc < 3) {
            const __half* src = W2h + (kc + 1) * 64 * 128;
            uint32_t dbase = sb + (((kc + 1) & 1) ? OWB1 : OWB0);
#pragma unroll
            for (int e = tid; e < 1024; e += 256) {
                int row = e >> 4, seg = e & 15;
                cpa16(dbase + row * (SBW * 2) + seg * 16, src + row * 128 + seg * 8);
            }
            CP_COMMIT;
        }
        const uint32_t wl = (kc & 1) ? w_lane1 : w_lane0;
#pragma unroll
        for (int ks = 0; ks < 4; ks++) {
            const int kb = ks * 16;
            ldsm4(af[0], h1_lane + (uint32_t)((wm * 32) * SA + kb) * 2);
            ldsm4(af[1], h1_lane + (uint32_t)((wm * 32 + 16) * SA + kb) * 2);
#pragma unroll
            for (int bt = 0; bt < 4; bt++) {
                ldsm4t(bf, wl + (uint32_t)(kb * SBW + wn * 64 + bt * 16) * 2);
                mma_f16(acc[0][2 * bt], af[0], bf[0], bf[1]);
                mma_f16(acc[1][2 * bt], af[1], bf[0], bf[1]);
                mma_f16(acc[0][2 * bt + 1], af[0], bf[2], bf[3]);
                mma_f16(acc[1][2 * bt + 1], af[1], bf[2], bf[3]);
            }
        }
        __syncthreads();
        if (kc < 3) {
            const int k0 = (kc + 1) * 64;
#pragma unroll
            for (int e = tid; e < 128 * 16; e += 256) {
                int r = e >> 4, c4 = e & 15;
                const float4 av = *(const float4*)&g_a[rowA[r] * 256 + k0 + c4 * 4];
                const float4 cv = *(const float4*)&g_c[rowC[r] * 256 + k0 + c4 * 4];
                __half2* d = (__half2*)(H1s + r * SA + c4 * 4);
                d[0] = gelu2(__floats2half2_rn(av.x + cv.x, av.y + cv.y));
                d[1] = gelu2(__floats2half2_rn(av.z + cv.z, av.w + cv.w));
            }
            CP_WAIT0;
            __syncthreads();
        }
    }

#pragma unroll
    for (int ch = 0; ch < 2; ch++) {
        const __half* src = W3h + ch * 64 * 128;
        uint32_t dbase = sb + (ch ? OWB1 : OWB0);
#pragma unroll
        for (int e = tid; e < 1024; e += 256) {
            int row = e >> 4, seg = e & 15;
            cpa16(dbase + row * (SBW * 2) + seg * 16, src + row * 128 + seg * 8);
        }
        CP_COMMIT;
    }

    // epilogue 1: +b2, gelu2, half -> H2s
#pragma unroll
    for (int mt = 0; mt < 2; mt++) {
        int r0 = wm * 32 + mt * 16 + lr;
#pragma unroll
        for (int nt = 0; nt < 8; nt++) {
            int cb = wn * 64 + nt * 8 + 2 * lc;
            float bx = b2s[cb], by = b2s[cb + 1];
            *(__half2*)(H2s + r0 * SH + cb) =
                gelu2(__floats2half2_rn(acc[mt][nt][0] + bx, acc[mt][nt][1] + by));
            *(__half2*)(H2s + (r0 + 8) * SH + cb) =
                gelu2(__floats2half2_rn(acc[mt][nt][2] + bx, acc[mt][nt][3] + by));
        }
    }
    CP_WAIT0;
    __syncthreads();

    float acc2[2][8][4] = {};
#pragma unroll
    for (int ks = 0; ks < 8; ks++) {
        const int kbg = ks * 16;
        const uint32_t wl = (kbg & 64) ? w_lane1 : w_lane0;
        const int kb = kbg & 63;
        ldsm4(af[0], h2_lane + (uint32_t)((wm * 32) * SH + kbg) * 2);
        ldsm4(af[1], h2_lane + (uint32_t)((wm * 32 + 16) * SH + kbg) * 2);
#pragma unroll
        for (int bt = 0; bt < 4; bt++) {
            ldsm4t(bf, wl + (uint32_t)(kb * SBW + wn * 64 + bt * 16) * 2);
            mma_f16(acc2[0][2 * bt], af[0], bf[0], bf[1]);
            mma_f16(acc2[1][2 * bt], af[1], bf[0], bf[1]);
            mma_f16(acc2[0][2 * bt + 1], af[0], bf[2], bf[3]);
            mma_f16(acc2[1][2 * bt + 1], af[1], bf[2], bf[3]);
        }
    }
    __syncthreads();   // H2s reads done -> safe to overwrite with fp16 P

    // epilogue 2: +b3, fp16 into H2s region, norms from fp32 registers
#pragma unroll
    for (int mt = 0; mt < 2; mt++) {
        int r0 = wm * 32 + mt * 16 + lr;
        float n0s = 0.f, n1s = 0.f;
#pragma unroll
        for (int nt = 0; nt < 8; nt++) {
            int cb = wn * 64 + nt * 8 + 2 * lc;
            float bx = b3s[cb], by = b3s[cb + 1];
            float o0 = acc2[mt][nt][0] + bx, o1 = acc2[mt][nt][1] + by;
            float o2 = acc2[mt][nt][2] + bx, o3 = acc2[mt][nt][3] + by;
            n0s += o0 * o0 + o1 * o1;
            n1s += o2 * o2 + o3 * o3;
            *(__half2*)(H2s + r0 * SH + cb) = __floats2half2_rn(o0, o1);
            *(__half2*)(H2s + (r0 + 8) * SH + cb) = __floats2half2_rn(o2, o3);
        }
        n0s += __shfl_xor_sync(0xffffffffu, n0s, 1);
        n0s += __shfl_xor_sync(0xffffffffu, n0s, 2);
        n1s += __shfl_xor_sync(0xffffffffu, n1s, 1);
        n1s += __shfl_xor_sync(0xffffffffu, n1s, 2);
        if (lc == 0) {
            normw[r0 * 2 + wn] = n0s;
            normw[(r0 + 8) * 2 + wn] = n1s;
        }
    }
    __syncthreads();

    // writeout: fp16 rows, 2 threads per pair-row (128 B = 8 uint4 each)
    {
        int r = tid >> 1, hf = tid & 1;
        const uint4* src = (const uint4*)(smc + OH2 + r * (SH * 2) + hf * 128);
        uint4* dst = (uint4*)(g_p + (size_t)poff[r] * DD + hf * 64);
#pragma unroll
        for (int u = 0; u < 8; u++) dst[u] = src[u];
    }
    if (tid < 128) {
        float ss = normw[tid * 2] + normw[tid * 2 + 1];
        g_s[poff[tid]] = sqrtf(fmaxf(ss, 1e-30f));
    }
}

// ---------------- head: fp16 mma, 128x128 tiles ----------------
#define OHX 0
#define OHW 34816
#define OHB 69632
#define HD_SMEM_BYTES 70144

__global__ __launch_bounds__(256) void head_mma(
    const float* __restrict__ headW, const float* __restrict__ headb,
    float* __restrict__ out) {
    extern __shared__ char smc[];
    __half* Xh = (__half*)(smc + OHX);
    __half* Wh = (__half*)(smc + OHW);
    float* biass = (float*)(smc + OHB);
    float* Pf = (float*)smc;

    const int tid = threadIdx.x;
    const int lane = tid & 31;
    const int warp = tid >> 5;
    const int wm = warp >> 1;
    const int wn = warp & 1;
    const int lr = lane >> 2;
    const int lc = lane & 3;
    const int lrow = (lane & 7) + ((lane >> 3) & 1) * 8;
    const int lcol = (lane >> 4) * 8;

    const int n0 = blockIdx.x * 128;
    const int m0 = blockIdx.y * 128;

    const uint32_t sb = (uint32_t)__cvta_generic_to_shared(smc);
    const uint32_t x_lane = sb + OHX + (uint32_t)(lrow * SBW + lcol) * 2;
    const uint32_t w_lane = sb + OHW + (uint32_t)(lrow * SBW + lcol) * 2;

    for (int e = tid; e < 128 * 32; e += 256) {
        int r = e >> 5, c4 = e & 31;
        const float4 v = *(const float4*)&g_x[(m0 + r) * DD + c4 * 4];
        __half2* d = (__half2*)(Xh + r * SBW + c4 * 4);
        d[0] = __floats2half2_rn(v.x, v.y);
        d[1] = __floats2half2_rn(v.z, v.w);
    }
    for (int e = tid; e < 128 * 32; e += 256) {
        int k = e >> 5, n4 = e & 31;
        const float4 v = *(const float4*)&headW[(size_t)k * VV + n0 + n4 * 4];
        __half2* d = (__half2*)(Wh + k * SBW + n4 * 4);
        d[0] = __floats2half2_rn(v.x, v.y);
        d[1] = __floats2half2_rn(v.z, v.w);
    }
    if (tid < 128) biass[tid] = headb[n0 + tid];
    __syncthreads();

    float acc[2][8][4] = {};
    uint32_t af[2][4];
    uint32_t bf[4];
#pragma unroll
    for (int ks = 0; ks < 8; ks++) {
        const int kb = ks * 16;
        ldsm4(af[0], x_lane + (uint32_t)((wm * 32) * SBW + kb) * 2);
        ldsm4(af[1], x_lane + (uint32_t)((wm * 32 + 16) * SBW + kb) * 2);
#pragma unroll
        for (int bt = 0; bt < 4; bt++) {
            ldsm4t(bf, w_lane + (uint32_t)(kb * SBW + wn * 64 + bt * 16) * 2);
            mma_f16(acc[0][2 * bt], af[0], bf[0], bf[1]);
            mma_f16(acc[1][2 * bt], af[1], bf[0], bf[1]);
            mma_f16(acc[0][2 * bt + 1], af[0], bf[2], bf[3]);
            mma_f16(acc[1][2 * bt + 1], af[1], bf[2], bf[3]);
        }
    }
    __syncthreads();

#pragma unroll
    for (int mt = 0; mt < 2; mt++) {
        int r0 = wm * 32 + mt * 16 + lr;
#pragma unroll
        for (int nt = 0; nt < 8; nt++) {
            int cb = wn * 64 + nt * 8 + 2 * lc;
            float bx = biass[cb], by = biass[cb + 1];
            *(float2*)(Pf + r0 * SPF + cb) =
                make_float2(acc[mt][nt][0] + bx, acc[mt][nt][1] + by);
            *(float2*)(Pf + (r0 + 8) * SPF + cb) =
                make_float2(acc[mt][nt][2] + bx, acc[mt][nt][3] + by);
        }
    }
    __syncthreads();

    {
        int r = tid >> 1, hf = tid & 1;
        const float* src = Pf + r * SPF + hf * 64;
        float* dst = out + (size_t)(m0 + r) * VV + n0 + hf * 64;
#pragma unroll
        for (int u = 0; u < 64; u += 4)
            *(float4*)(dst + u) = *(const float4*)(src + u);
    }
}

// ---------------- block reductions ----------------
__device__ __forceinline__ float blockSum512(float v, float* red) {
    int tid = threadIdx.x;
    red[tid] = v;
    __syncthreads();
    for (int s = 256; s; s >>= 1) {
        if (tid < s) red[tid] += red[tid + s];
        __syncthreads();
    }
    float r = red[0];
    __syncthreads();
    return r;
}
__device__ __forceinline__ float blockSum128(float v, float* red) {
    int tid = threadIdx.x;
    red[tid] = v;
    __syncthreads();
    for (int s = 64; s; s >>= 1) {
        if (tid < s) red[tid] += red[tid + s];
        __syncthreads();
    }
    float r = red[0];
    __syncthreads();
    return r;
}

// ---------------- phase B: softmax + weighted sum + residual + LN ----------
// norms >= 0 and small -> exp() needs no max-centering
__global__ __launch_bounds__(512) void pair_reduce_ln(
    const float* __restrict__ lng, const float* __restrict__ lnb) {
    __shared__ float red[512];
    __shared__ float ws[NN];
    __shared__ float accbuf[8][128];
    const int bi = blockIdx.x;
    const int i = bi % NN;
    const int tid = threadIdx.x;
    const int gid = tid >> 6;
    const int c2 = tid & 63;
    const int np = i + 1;
    const float* srow = g_s + (size_t)bi * NN;

    float dsum = 0.f;
    for (int j = tid; j < np; j += 512) {
        float w = expf(srow[j]);
        ws[j] = w;
        dsum += w;
    }
    float den = blockSum512(dsum, red);

    const __half2* prow = (const __half2*)(g_p + (size_t)bi * NN * DD);
    float ax = 0.f, ay = 0.f;
#pragma unroll 2
    for (int j = gid; j < np; j += 8) {
        float w = ws[j];
        float2 pf = __half22float2(prow[j * 64 + c2]);
        ax = fmaf(w, pf.x, ax);
        ay = fmaf(w, pf.y, ay);
    }
    accbuf[gid][c2 * 2] = ax;
    accbuf[gid][c2 * 2 + 1] = ay;
    __syncthreads();

    float v = 0.f;
    if (tid < 128) {
        float s = 0.f;
#pragma unroll
        for (int g = 0; g < 8; g++) s += accbuf[g][tid];
        v = g_x[bi * DD + tid] + s / den;
    }
    float mean = blockSum512(tid < 128 ? v : 0.f, red) * (1.0f / DD);
    float dv = v - mean;
    float var = blockSum512(tid < 128 ? dv * dv : 0.f, red) * (1.0f / DD);
    if (tid < 128)
        g_x[bi * DD + tid] = dv * rsqrtf(var + 1e-5f) * lng[tid] + lnb[tid];
}

// ---------------- FFN residual + LN ----------------
__global__ __launch_bounds__(128) void add_ln(
    const float* __restrict__ lng, const float* __restrict__ lnb) {
    __shared__ float red[128];
    const int bi = blockIdx.x;
    const int tid = threadIdx.x;
    float v = g_x[bi * DD + tid] + g_y[bi * DD + tid];
    float mean = blockSum128(v, red) * (1.0f / DD);
    float dv = v - mean;
    float var = blockSum128(dv * dv, red) * (1.0f / DD);
    g_x[bi * DD + tid] = dv * rsqrtf(var + 1e-5f) * lng[tid] + lnb[tid];
}

// ---------------- launcher ----------------
extern "C" void kernel_launch(void* const* d_in, const int* in_sizes, int n_in,
                              void* d_out, int out_size) {
    const int* ids = (const int*)d_in[0];
    const float* embw = (const float*)d_in[1];
    const float* pos = (const float*)d_in[2];
    const float* pW1 = (const float*)d_in[3];
    const float* pb1 = (const float*)d_in[4];
    const float* pW2 = (const float*)d_in[5];
    const float* pb2 = (const float*)d_in[6];
    const float* pW3 = (const float*)d_in[7];
    const float* pb3 = (const float*)d_in[8];
    const float* ln1g = (const float*)d_in[9];
    const float* ln1b = (const float*)d_in[10];
    const float* fW1 = (const float*)d_in[11];
    const float* fb1 = (const float*)d_in[12];
    const float* fW2 = (const float*)d_in[13];
    const float* fb2 = (const float*)d_in[14];
    const float* ln2g = (const float*)d_in[15];
    const float* ln2b = (const float*)d_in[16];
    const float* headW = (const float*)d_in[17];
    const float* headb = (const float*)d_in[18];
    float* out = (float*)d_out;

    cudaFuncSetAttribute(pair_mma, cudaFuncAttributeMaxDynamicSharedMemorySize,
                         PM_SMEM_BYTES);
    cudaFuncSetAttribute(head_mma, cudaFuncAttributeMaxDynamicSharedMemorySize,
                         HD_SMEM_BYTES);
    cudaFuncSetAttribute(gemm_mma64<0>, cudaFuncAttributeMaxDynamicSharedMemorySize,
                         GM_SMEM_BYTES);
    cudaFuncSetAttribute(gemm_mma64<1>, cudaFuncAttributeMaxDynamicSharedMemorySize,
                         GM_SMEM_BYTES);

    float *xp, *ap, *cp, *hp, *yp;
    cudaGetSymbolAddress((void**)&xp, g_x);
    cudaGetSymbolAddress((void**)&ap, g_a);
    cudaGetSymbolAddress((void**)&cp, g_c);
    cudaGetSymbolAddress((void**)&hp, g_h);
    cudaGetSymbolAddress((void**)&yp, g_y);
    __half *w2hp, *w3hp;
    cudaGetSymbolAddress((void**)&w2hp, g_w2h);
    cudaGetSymbolAddress((void**)&w3hp, g_w3h);

    embed_kernel<<<(BB * NN * DD + 255) / 256, 256>>>(ids, embw, pos);
    convert_w<<<(LL * 256 * 128 + LL * 128 * 128 + 255) / 256, 256>>>(pW2, pW3);

    for (int l = 0; l < LL; l++) {
        const float* W1l = pW1 + (size_t)l * 256 * 256;
        gemm_mma64<0><<<dim3(4, 12), 256, GM_SMEM_BYTES>>>(
            xp, 128, W1l, W1l + 128 * 256, 256, 256,
            pb1 + l * 256, nullptr, ap, cp, 256, 128);
        pair_mma<<<NTILES_MMA, 256, PM_SMEM_BYTES>>>(
            w2hp + (size_t)l * 256 * 128, pb2 + l * 128,
            w3hp + (size_t)l * 128 * 128, pb3 + l * 128);
        pair_reduce_ln<<<BB * NN, 512>>>(ln1g + l * 128, ln1b + l * 128);
        gemm_mma64<1><<<dim3(4, 12), 256, GM_SMEM_BYTES>>>(
            xp, 128, fW1 + (size_t)l * 128 * 512, nullptr, 1 << 30, 512,
            fb1 + l * 512, nullptr, hp, nullptr, 512, 128);
        gemm_mma64<0><<<dim3(1, 12), 256, GM_SMEM_BYTES>>>(
            hp, 512, fW2 + (size_t)l * 512 * 128, nullptr, 1 << 30, 128,
            fb2 + l * 128, nullptr, yp, nullptr, 128, 512);
        add_ln<<<BB * NN, 128>>>(ln2g + l * 128, ln2b + l * 128);
    }

    head_mma<<<dim3(VV / 128, 768 / 128), 256, HD_SMEM_BYTES>>>(headW, headb, out);
}

// round 15
// speedup vs baseline: 1.1202x; 1.0861x over previous
#include <cuda_runtime.h>
#include <cuda_fp16.h>
#include <math.h>
#include <string.h>
#include <stdint.h>

// Problem constants
#define BB 2
#define NN 384
#define DD 128
#define VV 8192
#define LL 2
#define NPAIR_B 73920
#define NPAIR_T 147840
#define PT 128
#define NTILES_MMA 1155      // 147840 / 128

// ---------------- scratch ----------------
__device__ float g_x[BB * NN * DD];
__device__ __half g_ah[BB * NN * 256];              // x @ W1[:128] + b1, fp16
__device__ __half g_ch[BB * NN * 256];              // x @ W1[128:], fp16
__device__ __half g_hh[BB * NN * 512];              // FFN intermediate, fp16
__device__ float g_y[BB * NN * DD];
__device__ __half g_p[(size_t)BB * NN * NN * DD];   // pair vectors, fp16
__device__ float g_s[BB * NN * NN];
__device__ __half g_w2h[LL * 256 * 128];
__device__ __half g_w3h[LL * 128 * 128];

__device__ __forceinline__ uint32_t h2u(__half2 h) {
    uint32_t r;
    memcpy(&r, &h, 4);
    return r;
}
__device__ __forceinline__ __half2 u2h(uint32_t u) {
    __half2 r;
    memcpy(&r, &u, 4);
    return r;
}

// half2 gelu: 2 elements per MUFU via tanh.approx.f16x2
__device__ __forceinline__ __half2 gelu2(__half2 x) {
    const __half2 c1 = __float2half2_rn(0.0356774081f);
    const __half2 c0 = __float2half2_rn(0.7978845608f);
    const __half2 hh = __float2half2_rn(0.5f);
    __half2 x2 = __hmul2(x, x);
    __half2 inner = __hfma2(c1, x2, c0);
    __half2 u = __hmul2(x, inner);
    uint32_t ui = h2u(u), ti;
    asm("tanh.approx.f16x2 %0, %1;" : "=r"(ti) : "r"(ui));
    __half2 t = u2h(ti);
    __half2 hx = __hmul2(hh, x);
    return __hfma2(hx, t, hx);
}

__device__ __forceinline__ void ldsm4(uint32_t* r, uint32_t addr) {
    asm volatile("ldmatrix.sync.aligned.m8n8.x4.shared.b16 {%0,%1,%2,%3}, [%4];"
                 : "=r"(r[0]), "=r"(r[1]), "=r"(r[2]), "=r"(r[3]) : "r"(addr));
}
__device__ __forceinline__ void ldsm4t(uint32_t* r, uint32_t addr) {
    asm volatile("ldmatrix.sync.aligned.m8n8.x4.trans.shared.b16 {%0,%1,%2,%3}, [%4];"
                 : "=r"(r[0]), "=r"(r[1]), "=r"(r[2]), "=r"(r[3]) : "r"(addr));
}
__device__ __forceinline__ void mma_f16(float c[4], const uint32_t a[4],
                                        uint32_t b0, uint32_t b1) {
    asm volatile(
        "mma.sync.aligned.m16n8k16.row.col.f32.f16.f16.f32 "
        "{%0,%1,%2,%3}, {%4,%5,%6,%7}, {%8,%9}, {%0,%1,%2,%3};"
        : "+f"(c[0]), "+f"(c[1]), "+f"(c[2]), "+f"(c[3])
        : "r"(a[0]), "r"(a[1]), "r"(a[2]), "r"(a[3]), "r"(b0), "r"(b1));
}
__device__ __forceinline__ void cpa16(uint32_t daddr, const void* g) {
    asm volatile("cp.async.cg.shared.global [%0], [%1], 16;" :: "r"(daddr), "l"(g));
}
#define CP_COMMIT asm volatile("cp.async.commit_group;")
#define CP_WAIT0 asm volatile("cp.async.wait_group 0;")

// ---------------- weight pre-convert ----------------
__global__ void convert_w(const float* __restrict__ pW2, const float* __restrict__ pW3) {
    int t = blockIdx.x * 256 + threadIdx.x;
    const int n2 = LL * 256 * 128;
    const int n3 = LL * 128 * 128;
    if (t < n2) g_w2h[t] = __float2half(pW2[t]);
    int t3 = t - n2;
    if (t3 >= 0 && t3 < n3) g_w3h[t3] = __float2half(pW3[t3]);
}

// ---------------- embedding ----------------
__global__ void embed_kernel(const int* __restrict__ ids,
                             const float* __restrict__ emb,
                             const float* __restrict__ pos) {
    int t = blockIdx.x * blockDim.x + threadIdx.x;
    if (t >= BB * NN * DD) return;
    int d = t & (DD - 1);
    int bn = t >> 7;
    int n = bn % NN;
    g_x[t] = emb[ids[bn] * DD + d] + pos[n * DD + d];
}

// ================= generic fp16-mma GEMM, 64(M)x128(N) tiles ================
// TAH: A input is half; TOH: output is half
#define SBW 136
#define SPF 132
#define GM_OX 0
#define GM_OW 17408
#define GM_OB 52224
#define GM_SMEM_BYTES 52736

template <int ACT, int TAH, int TOH>
__global__ __launch_bounds__(256, 2) void gemm_mma64(
    const void* __restrict__ Av, int ldA,
    const float* __restrict__ Wa, const float* __restrict__ Wb, int nsplit, int ldW,
    const float* __restrict__ ba, const float* __restrict__ bb,
    void* __restrict__ Ca, void* __restrict__ Cb, int ldC, int K) {
    extern __shared__ char smc[];
    __half* Xh = (__half*)(smc + GM_OX);
    __half* Wh = (__half*)(smc + GM_OW);
    float* biass = (float*)(smc + GM_OB);
    float* Pf = (float*)smc;

    const int tid = threadIdx.x;
    const int lane = tid & 31;
    const int warp = tid >> 5;
    const int wm = warp >> 2;
    const int wn = warp & 3;
    const int lr = lane >> 2;
    const int lc = lane & 3;
    const int lrow = (lane & 7) + ((lane >> 3) & 1) * 8;
    const int lcol = (lane >> 4) * 8;

    const int n0 = blockIdx.x * 128;
    const int m0 = blockIdx.y * 64;

    const float* Wsrc;
    const float* bsrc;
    void* Cdst;
    if (n0 < nsplit) {
        Wsrc = Wa + n0;
        bsrc = ba ? ba + n0 : nullptr;
        Cdst = (char*)Ca + (size_t)n0 * (TOH ? 2 : 4);
    } else {
        int nn = n0 - nsplit;
        Wsrc = Wb + nn;
        bsrc = bb ? bb + nn : nullptr;
        Cdst = (char*)Cb + (size_t)nn * (TOH ? 2 : 4);
    }

    const uint32_t sb = (uint32_t)__cvta_generic_to_shared(smc);
    const uint32_t x_lane = sb + GM_OX + (uint32_t)(lrow * SBW + lcol) * 2;
    const uint32_t w_lane = sb + GM_OW + (uint32_t)(lrow * SBW + lcol) * 2;

    if (tid < 128) biass[tid] = bsrc ? bsrc[tid] : 0.f;

    float acc[2][4][4] = {};
    uint32_t af[2][4];
    uint32_t bf[4];

    const int nkc = K >> 7;
    for (int kc = 0; kc < nkc; kc++) {
        const int k0 = kc << 7;
        if (TAH) {
            const __half* A = (const __half*)Av;
            for (int e = tid; e < 64 * 16; e += 256) {
                int r = e >> 4, c8 = e & 15;
                const uint4 v = *(const uint4*)(A + (size_t)(m0 + r) * ldA + k0 + c8 * 8);
                *(uint4*)(Xh + r * SBW + c8 * 8) = v;
            }
        } else {
            const float* A = (const float*)Av;
            for (int e = tid; e < 64 * 32; e += 256) {
                int r = e >> 5, c4 = e & 31;
                const float4 v = *(const float4*)&A[(size_t)(m0 + r) * ldA + k0 + c4 * 4];
                __half2* d = (__half2*)(Xh + r * SBW + c4 * 4);
                d[0] = __floats2half2_rn(v.x, v.y);
                d[1] = __floats2half2_rn(v.z, v.w);
            }
        }
        for (int e = tid; e < 128 * 32; e += 256) {
            int k = e >> 5, n4 = e & 31;
            const float4 v = *(const float4*)&Wsrc[(size_t)(k0 + k) * ldW + n4 * 4];
            __half2* d = (__half2*)(Wh + k * SBW + n4 * 4);
            d[0] = __floats2half2_rn(v.x, v.y);
            d[1] = __floats2half2_rn(v.z, v.w);
        }
        __syncthreads();
#pragma unroll
        for (int ks = 0; ks < 8; ks++) {
            const int kb = ks * 16;
            ldsm4(af[0], x_lane + (uint32_t)((wm * 32) * SBW + kb) * 2);
            ldsm4(af[1], x_lane + (uint32_t)((wm * 32 + 16) * SBW + kb) * 2);
#pragma unroll
            for (int bt = 0; bt < 2; bt++) {
                ldsm4t(bf, w_lane + (uint32_t)(kb * SBW + wn * 32 + bt * 16) * 2);
                mma_f16(acc[0][2 * bt], af[0], bf[0], bf[1]);
                mma_f16(acc[1][2 * bt], af[1], bf[0], bf[1]);
                mma_f16(acc[0][2 * bt + 1], af[0], bf[2], bf[3]);
                mma_f16(acc[1][2 * bt + 1], af[1], bf[2], bf[3]);
            }
        }
        __syncthreads();
    }

#pragma unroll
    for (int mt = 0; mt < 2; mt++) {
        int r0 = wm * 32 + mt * 16 + lr;
#pragma unroll
        for (int nt = 0; nt < 4; nt++) {
            int cb = wn * 32 + nt * 8 + 2 * lc;
            float o0 = acc[mt][nt][0] + biass[cb];
            float o1 = acc[mt][nt][1] + biass[cb + 1];
            float o2 = acc[mt][nt][2] + biass[cb];
            float o3 = acc[mt][nt][3] + biass[cb + 1];
            if (ACT == 1) {
                float2 f01 = __half22float2(gelu2(__floats2half2_rn(o0, o1)));
                float2 f23 = __half22float2(gelu2(__floats2half2_rn(o2, o3)));
                o0 = f01.x; o1 = f01.y; o2 = f23.x; o3 = f23.y;
            }
            *(float2*)(Pf + r0 * SPF + cb) = make_float2(o0, o1);
            *(float2*)(Pf + (r0 + 8) * SPF + cb) = make_float2(o2, o3);
        }
    }
    __syncthreads();

    {
        int r = tid >> 2, q = tid & 3;
        const float* src = Pf + r * SPF + q * 32;
        if (TOH) {
            __half* dst = (__half*)Cdst + (size_t)(m0 + r) * ldC + q * 32;
#pragma unroll
            for (int u = 0; u < 32; u += 8) {
                float4 v0 = *(const float4*)(src + u);
                float4 v1 = *(const float4*)(src + u + 4);
                uint4 o;
                o.x = h2u(__floats2half2_rn(v0.x, v0.y));
                o.y = h2u(__floats2half2_rn(v0.z, v0.w));
                o.z = h2u(__floats2half2_rn(v1.x, v1.y));
                o.w = h2u(__floats2half2_rn(v1.z, v1.w));
                *(uint4*)(dst + u) = o;
            }
        } else {
            float* dst = (float*)Cdst + (size_t)(m0 + r) * ldC + q * 32;
#pragma unroll
            for (int u = 0; u < 32; u += 4)
                *(float4*)(dst + u) = *(const float4*)(src + u);
        }
    }
}

// ---------------- pair kernel: chunked, cp.async dbl-buffered W, fp16 mma ---
#define SA 72
#define SH 136
#define OWB0 0
#define OWB1 17408
#define OH1 34816
#define OH2 53248
#define OB2 88064
#define OB3 88576
#define ORA 89088
#define ORC 89600
#define OPO 90112
#define ONW 90624
#define PM_SMEM_BYTES 91648

__global__ __launch_bounds__(256, 2) void pair_mma(
    const __half* __restrict__ W2h, const float* __restrict__ b2,
    const __half* __restrict__ W3h, const float* __restrict__ b3) {
    extern __shared__ char smc[];
    __half* H1s = (__half*)(smc + OH1);
    __half* H2s = (__half*)(smc + OH2);
    float* b2s = (float*)(smc + OB2);
    float* b3s = (float*)(smc + OB3);
    int* rowA = (int*)(smc + ORA);
    int* rowC = (int*)(smc + ORC);
    int* poff = (int*)(smc + OPO);
    float* normw = (float*)(smc + ONW);

    const int tid = threadIdx.x;
    const int lane = tid & 31;
    const int warp = tid >> 5;
    const int wm = warp >> 1;
    const int wn = warp & 1;
    const int lr = lane >> 2;
    const int lc = lane & 3;
    const int lrow = (lane & 7) + ((lane >> 3) & 1) * 8;
    const int lcol = (lane >> 4) * 8;

    const uint32_t sb = (uint32_t)__cvta_generic_to_shared(smc);
    const uint32_t h1_lane = sb + OH1 + (uint32_t)(lrow * SA + lcol) * 2;
    const uint32_t h2_lane = sb + OH2 + (uint32_t)(lrow * SH + lcol) * 2;
    const uint32_t w_lane0 = sb + OWB0 + (uint32_t)(lrow * SBW + lcol) * 2;
    const uint32_t w_lane1 = sb + OWB1 + (uint32_t)(lrow * SBW + lcol) * 2;

    {
        const __half* src = W2h;
        uint32_t dbase = sb + OWB0;
#pragma unroll
        for (int e = tid; e < 1024; e += 256) {
            int row = e >> 4, seg = e & 15;
            cpa16(dbase + row * (SBW * 2) + seg * 16, src + row * 128 + seg * 8);
        }
        CP_COMMIT;
    }

    if (tid < 128) {
        b2s[tid] = b2[tid];
        b3s[tid] = b3[tid];
        int g = blockIdx.x * PT + tid;
        int b = (g >= NPAIR_B) ? 1 : 0;
        int idx = g - b * NPAIR_B;
        int i = (int)((sqrtf(8.0f * (float)idx + 1.0f) - 1.0f) * 0.5f);
        while ((i + 1) * (i + 2) / 2 <= idx) ++i;
        while (i * (i + 1) / 2 > idx) --i;
        int j = idx - i * (i + 1) / 2;
        rowA[tid] = b * NN + i;
        rowC[tid] = b * NN + j;
        poff[tid] = (b * NN + i) * NN + j;
    }
    __syncthreads();

    // H1 build chunk 0: fp16 inputs, 2 LDG.128 per 8 cols
#pragma unroll
    for (int e = tid; e < 128 * 8; e += 256) {
        int r = e >> 3, c8 = e & 7;
        const uint4 av = *(const uint4*)(g_ah + rowA[r] * 256 + c8 * 8);
        const uint4 cv = *(const uint4*)(g_ch + rowC[r] * 256 + c8 * 8);
        uint4 o;
        o.x = h2u(gelu2(__hadd2(u2h(av.x), u2h(cv.x))));
        o.y = h2u(gelu2(__hadd2(u2h(av.y), u2h(cv.y))));
        o.z = h2u(gelu2(__hadd2(u2h(av.z), u2h(cv.z))));
        o.w = h2u(gelu2(__hadd2(u2h(av.w), u2h(cv.w))));
        *(uint4*)(H1s + r * SA + c8 * 8) = o;
    }
    CP_WAIT0;
    __syncthreads();

    float acc[2][8][4] = {};
    uint32_t af[2][4];
    uint32_t bf[4];

    for (int kc = 0; kc < 4; kc++) {
        if (kc < 3) {
            const __half* src = W2h + (kc + 1) * 64 * 128;
            uint32_t dbase = sb + (((kc + 1) & 1) ? OWB1 : OWB0);
#pragma unroll
            for (int e = tid; e < 1024; e += 256) {
                int row = e >> 4, seg = e & 15;
                cpa16(dbase + row * (SBW * 2) + seg * 16, src + row * 128 + seg * 8);
            }
            CP_COMMIT;
        }
        const uint32_t wl = (kc & 1) ? w_lane1 : w_lane0;
#pragma unroll
        for (int ks = 0; ks < 4; ks++) {
            const int kb = ks * 16;
            ldsm4(af[0], h1_lane + (uint32_t)((wm * 32) * SA + kb) * 2);
            ldsm4(af[1], h1_lane + (uint32_t)((wm * 32 + 16) * SA + kb) * 2);
#pragma unroll
            for (int bt = 0; bt < 4; bt++) {
                ldsm4t(bf, wl + (uint32_t)(kb * SBW + wn * 64 + bt * 16) * 2);
                mma_f16(acc[0][2 * bt], af[0], bf[0], bf[1]);
                mma_f16(acc[1][2 * bt], af[1], bf[0], bf[1]);
                mma_f16(acc[0][2 * bt + 1], af[0], bf[2], bf[3]);
                mma_f16(acc[1][2 * bt + 1], af[1], bf[2], bf[3]);
            }
        }
        __syncthreads();
        if (kc < 3) {
            const int k0 = (kc + 1) * 64;
#pragma unroll
            for (int e = tid; e < 128 * 8; e += 256) {
                int r = e >> 3, c8 = e & 7;
                const uint4 av = *(const uint4*)(g_ah + rowA[r] * 256 + k0 + c8 * 8);
                const uint4 cv = *(const uint4*)(g_ch + rowC[r] * 256 + k0 + c8 * 8);
                uint4 o;
                o.x = h2u(gelu2(__hadd2(u2h(av.x), u2h(cv.x))));
                o.y = h2u(gelu2(__hadd2(u2h(av.y), u2h(cv.y))));
                o.z = h2u(gelu2(__hadd2(u2h(av.z), u2h(cv.z))));
                o.w = h2u(gelu2(__hadd2(u2h(av.w), u2h(cv.w))));
                *(uint4*)(H1s + r * SA + c8 * 8) = o;
            }
            CP_WAIT0;
            __syncthreads();
        }
    }

#pragma unroll
    for (int ch = 0; ch < 2; ch++) {
        const __half* src = W3h + ch * 64 * 128;
        uint32_t dbase = sb + (ch ? OWB1 : OWB0);
#pragma unroll
        for (int e = tid; e < 1024; e += 256) {
            int row = e >> 4, seg = e & 15;
            cpa16(dbase + row * (SBW * 2) + seg * 16, src + row * 128 + seg * 8);
        }
        CP_COMMIT;
    }

    // epilogue 1: +b2, gelu2, half -> H2s
#pragma unroll
    for (int mt = 0; mt < 2; mt++) {
        int r0 = wm * 32 + mt * 16 + lr;
#pragma unroll
        for (int nt = 0; nt < 8; nt++) {
            int cb = wn * 64 + nt * 8 + 2 * lc;
            float bx = b2s[cb], by = b2s[cb + 1];
            *(__half2*)(H2s + r0 * SH + cb) =
                gelu2(__floats2half2_rn(acc[mt][nt][0] + bx, acc[mt][nt][1] + by));
            *(__half2*)(H2s + (r0 + 8) * SH + cb) =
                gelu2(__floats2half2_rn(acc[mt][nt][2] + bx, acc[mt][nt][3] + by));
        }
    }
    CP_WAIT0;
    __syncthreads();

    float acc2[2][8][4] = {};
#pragma unroll
    for (int ks = 0; ks < 8; ks++) {
        const int kbg = ks * 16;
        const uint32_t wl = (kbg & 64) ? w_lane1 : w_lane0;
        const int kb = kbg & 63;
        ldsm4(af[0], h2_lane + (uint32_t)((wm * 32) * SH + kbg) * 2);
        ldsm4(af[1], h2_lane + (uint32_t)((wm * 32 + 16) * SH + kbg) * 2);
#pragma unroll
        for (int bt = 0; bt < 4; bt++) {
            ldsm4t(bf, wl + (uint32_t)(kb * SBW + wn * 64 + bt * 16) * 2);
            mma_f16(acc2[0][2 * bt], af[0], bf[0], bf[1]);
            mma_f16(acc2[1][2 * bt], af[1], bf[0], bf[1]);
            mma_f16(acc2[0][2 * bt + 1], af[0], bf[2], bf[3]);
            mma_f16(acc2[1][2 * bt + 1], af[1], bf[2], bf[3]);
        }
    }
    __syncthreads();   // H2s reads done -> safe to overwrite with fp16 P

    // epilogue 2: +b3, fp16 into H2s region, norms from fp32 registers
#pragma unroll
    for (int mt = 0; mt < 2; mt++) {
        int r0 = wm * 32 + mt * 16 + lr;
        float n0s = 0.f, n1s = 0.f;
#pragma unroll
        for (int nt = 0; nt < 8; nt++) {
            int cb = wn * 64 + nt * 8 + 2 * lc;
            float bx = b3s[cb], by = b3s[cb + 1];
            float o0 = acc2[mt][nt][0] + bx, o1 = acc2[mt][nt][1] + by;
            float o2 = acc2[mt][nt][2] + bx, o3 = acc2[mt][nt][3] + by;
            n0s += o0 * o0 + o1 * o1;
            n1s += o2 * o2 + o3 * o3;
            *(__half2*)(H2s + r0 * SH + cb) = __floats2half2_rn(o0, o1);
            *(__half2*)(H2s + (r0 + 8) * SH + cb) = __floats2half2_rn(o2, o3);
        }
        n0s += __shfl_xor_sync(0xffffffffu, n0s, 1);
        n0s += __shfl_xor_sync(0xffffffffu, n0s, 2);
        n1s += __shfl_xor_sync(0xffffffffu, n1s, 1);
        n1s += __shfl_xor_sync(0xffffffffu, n1s, 2);
        if (lc == 0) {
            normw[r0 * 2 + wn] = n0s;
            normw[(r0 + 8) * 2 + wn] = n1s;
        }
    }
    __syncthreads();

    // writeout: fp16 rows, 2 threads per pair-row (128 B = 8 uint4 each)
    {
        int r = tid >> 1, hf = tid & 1;
        const uint4* src = (const uint4*)(smc + OH2 + r * (SH * 2) + hf * 128);
        uint4* dst = (uint4*)(g_p + (size_t)poff[r] * DD + hf * 64);
#pragma unroll
        for (int u = 0; u < 8; u++) dst[u] = src[u];
    }
    if (tid < 128) {
        float ss = normw[tid * 2] + normw[tid * 2 + 1];
        g_s[poff[tid]] = sqrtf(fmaxf(ss, 1e-30f));
    }
}

// ---------------- head: fp16 mma, 128x128 tiles ----------------
#define OHX 0
#define OHW 34816
#define OHB 69632
#define HD_SMEM_BYTES 70144

__global__ __launch_bounds__(256) void head_mma(
    const float* __restrict__ headW, const float* __restrict__ headb,
    float* __restrict__ out) {
    extern __shared__ char smc[];
    __half* Xh = (__half*)(smc + OHX);
    __half* Wh = (__half*)(smc + OHW);
    float* biass = (float*)(smc + OHB);
    float* Pf = (float*)smc;

    const int tid = threadIdx.x;
    const int lane = tid & 31;
    const int warp = tid >> 5;
    const int wm = warp >> 1;
    const int wn = warp & 1;
    const int lr = lane >> 2;
    const int lc = lane & 3;
    const int lrow = (lane & 7) + ((lane >> 3) & 1) * 8;
    const int lcol = (lane >> 4) * 8;

    const int n0 = blockIdx.x * 128;
    const int m0 = blockIdx.y * 128;

    const uint32_t sb = (uint32_t)__cvta_generic_to_shared(smc);
    const uint32_t x_lane = sb + OHX + (uint32_t)(lrow * SBW + lcol) * 2;
    const uint32_t w_lane = sb + OHW + (uint32_t)(lrow * SBW + lcol) * 2;

    for (int e = tid; e < 128 * 32; e += 256) {
        int r = e >> 5, c4 = e & 31;
        const float4 v = *(const float4*)&g_x[(m0 + r) * DD + c4 * 4];
        __half2* d = (__half2*)(Xh + r * SBW + c4 * 4);
        d[0] = __floats2half2_rn(v.x, v.y);
        d[1] = __floats2half2_rn(v.z, v.w);
    }
    for (int e = tid; e < 128 * 32; e += 256) {
        int k = e >> 5, n4 = e & 31;
        const float4 v = *(const float4*)&headW[(size_t)k * VV + n0 + n4 * 4];
        __half2* d = (__half2*)(Wh + k * SBW + n4 * 4);
        d[0] = __floats2half2_rn(v.x, v.y);
        d[1] = __floats2half2_rn(v.z, v.w);
    }
    if (tid < 128) biass[tid] = headb[n0 + tid];
    __syncthreads();

    float acc[2][8][4] = {};
    uint32_t af[2][4];
    uint32_t bf[4];
#pragma unroll
    for (int ks = 0; ks < 8; ks++) {
        const int kb = ks * 16;
        ldsm4(af[0], x_lane + (uint32_t)((wm * 32) * SBW + kb) * 2);
        ldsm4(af[1], x_lane + (uint32_t)((wm * 32 + 16) * SBW + kb) * 2);
#pragma unroll
        for (int bt = 0; bt < 4; bt++) {
            ldsm4t(bf, w_lane + (uint32_t)(kb * SBW + wn * 64 + bt * 16) * 2);
            mma_f16(acc[0][2 * bt], af[0], bf[0], bf[1]);
            mma_f16(acc[1][2 * bt], af[1], bf[0], bf[1]);
            mma_f16(acc[0][2 * bt + 1], af[0], bf[2], bf[3]);
            mma_f16(acc[1][2 * bt + 1], af[1], bf[2], bf[3]);
        }
    }
    __syncthreads();

#pragma unroll
    for (int mt = 0; mt < 2; mt++) {
        int r0 = wm * 32 + mt * 16 + lr;
#pragma unroll
        for (int nt = 0; nt < 8; nt++) {
            int cb = wn * 64 + nt * 8 + 2 * lc;
            float bx = biass[cb], by = biass[cb + 1];
            *(float2*)(Pf + r0 * SPF + cb) =
                make_float2(acc[mt][nt][0] + bx, acc[mt][nt][1] + by);
            *(float2*)(Pf + (r0 + 8) * SPF + cb) =
                make_float2(acc[mt][nt][2] + bx, acc[mt][nt][3] + by);
        }
    }
    __syncthreads();

    {
        int r = tid >> 1, hf = tid & 1;
        const float* src = Pf + r * SPF + hf * 64;
        float* dst = out + (size_t)(m0 + r) * VV + n0 + hf * 64;
#pragma unroll
        for (int u = 0; u < 64; u += 4)
            *(float4*)(dst + u) = *(const float4*)(src + u);
    }
}

// ---------------- block reductions ----------------
__device__ __forceinline__ float blockSum512(float v, float* red) {
    int tid = threadIdx.x;
    red[tid] = v;
    __syncthreads();
    for (int s = 256; s; s >>= 1) {
        if (tid < s) red[tid] += red[tid + s];
        __syncthreads();
    }
    float r = red[0];
    __syncthreads();
    return r;
}
__device__ __forceinline__ float blockSum128(float v, float* red) {
    int tid = threadIdx.x;
    red[tid] = v;
    __syncthreads();
    for (int s = 64; s; s >>= 1) {
        if (tid < s) red[tid] += red[tid + s];
        __syncthreads();
    }
    float r = red[0];
    __syncthreads();
    return r;
}

// ---------------- phase B: softmax + weighted sum + residual + LN ----------
__global__ __launch_bounds__(512) void pair_reduce_ln(
    const float* __restrict__ lng, const float* __restrict__ lnb) {
    __shared__ float red[512];
    __shared__ float ws[NN];
    __shared__ float accbuf[8][128];
    const int bi = blockIdx.x;
    const int i = bi % NN;
    const int tid = threadIdx.x;
    const int gid = tid >> 6;
    const int c2 = tid & 63;
    const int np = i + 1;
    const float* srow = g_s + (size_t)bi * NN;

    float dsum = 0.f;
    for (int j = tid; j < np; j += 512) {
        float w = expf(srow[j]);
        ws[j] = w;
        dsum += w;
    }
    float den = blockSum512(dsum, red);

    const __half2* prow = (const __half2*)(g_p + (size_t)bi * NN * DD);
    float ax = 0.f, ay = 0.f;
#pragma unroll 2
    for (int j = gid; j < np; j += 8) {
        float w = ws[j];
        float2 pf = __half22float2(prow[j * 64 + c2]);
        ax = fmaf(w, pf.x, ax);
        ay = fmaf(w, pf.y, ay);
    }
    accbuf[gid][c2 * 2] = ax;
    accbuf[gid][c2 * 2 + 1] = ay;
    __syncthreads();

    float v = 0.f;
    if (tid < 128) {
        float s = 0.f;
#pragma unroll
        for (int g = 0; g < 8; g++) s += accbuf[g][tid];
        v = g_x[bi * DD + tid] + s / den;
    }
    float mean = blockSum512(tid < 128 ? v : 0.f, red) * (1.0f / DD);
    float dv = v - mean;
    float var = blockSum512(tid < 128 ? dv * dv : 0.f, red) * (1.0f / DD);
    if (tid < 128)
        g_x[bi * DD + tid] = dv * rsqrtf(var + 1e-5f) * lng[tid] + lnb[tid];
}

// ---------------- FFN residual + LN ----------------
__global__ __launch_bounds__(128) void add_ln(
    const float* __restrict__ lng, const float* __restrict__ lnb) {
    __shared__ float red[128];
    const int bi = blockIdx.x;
    const int tid = threadIdx.x;
    float v = g_x[bi * DD + tid] + g_y[bi * DD + tid];
    float mean = blockSum128(v, red) * (1.0f / DD);
    float dv = v - mean;
    float var = blockSum128(dv * dv, red) * (1.0f / DD);
    g_x[bi * DD + tid] = dv * rsqrtf(var + 1e-5f) * lng[tid] + lnb[tid];
}

// ---------------- launcher ----------------
extern "C" void kernel_launch(void* const* d_in, const int* in_sizes, int n_in,
                              void* d_out, int out_size) {
    const int* ids = (const int*)d_in[0];
    const float* embw = (const float*)d_in[1];
    const float* pos = (const float*)d_in[2];
    const float* pW1 = (const float*)d_in[3];
    const float* pb1 = (const float*)d_in[4];
    const float* pW2 = (const float*)d_in[5];
    const float* pb2 = (const float*)d_in[6];
    const float* pW3 = (const float*)d_in[7];
    const float* pb3 = (const float*)d_in[8];
    const float* ln1g = (const float*)d_in[9];
    const float* ln1b = (const float*)d_in[10];
    const float* fW1 = (const float*)d_in[11];
    const float* fb1 = (const float*)d_in[12];
    const float* fW2 = (const float*)d_in[13];
    const float* fb2 = (const float*)d_in[14];
    const float* ln2g = (const float*)d_in[15];
    const float* ln2b = (const float*)d_in[16];
    const float* headW = (const float*)d_in[17];
    const float* headb = (const float*)d_in[18];
    float* out = (float*)d_out;

    cudaFuncSetAttribute(pair_mma, cudaFuncAttributeMaxDynamicSharedMemorySize,
                         PM_SMEM_BYTES);
    cudaFuncSetAttribute(head_mma, cudaFuncAttributeMaxDynamicSharedMemorySize,
                         HD_SMEM_BYTES);
    cudaFuncSetAttribute(gemm_mma64<0, 0, 1>, cudaFuncAttributeMaxDynamicSharedMemorySize,
                         GM_SMEM_BYTES);
    cudaFuncSetAttribute(gemm_mma64<1, 0, 1>, cudaFuncAttributeMaxDynamicSharedMemorySize,
                         GM_SMEM_BYTES);
    cudaFuncSetAttribute(gemm_mma64<0, 1, 0>, cudaFuncAttributeMaxDynamicSharedMemorySize,
                         GM_SMEM_BYTES);

    float *xp, *yp;
    cudaGetSymbolAddress((void**)&xp, g_x);
    cudaGetSymbolAddress((void**)&yp, g_y);
    __half *ahp, *chp, *hhp, *w2hp, *w3hp;
    cudaGetSymbolAddress((void**)&ahp, g_ah);
    cudaGetSymbolAddress((void**)&chp, g_ch);
    cudaGetSymbolAddress((void**)&hhp, g_hh);
    cudaGetSymbolAddress((void**)&w2hp, g_w2h);
    cudaGetSymbolAddress((void**)&w3hp, g_w3h);

    embed_kernel<<<(BB * NN * DD + 255) / 256, 256>>>(ids, embw, pos);
    convert_w<<<(LL * 256 * 128 + LL * 128 * 128 + 255) / 256, 256>>>(pW2, pW3);

    for (int l = 0; l < LL; l++) {
        const float* W1l = pW1 + (size_t)l * 256 * 256;
        // fused a/c gemm -> fp16 outputs
        gemm_mma64<0, 0, 1><<<dim3(4, 12), 256, GM_SMEM_BYTES>>>(
            xp, 128, W1l, W1l + 128 * 256, 256, 256,
            pb1 + l * 256, nullptr, ahp, chp, 256, 128);
        pair_mma<<<NTILES_MMA, 256, PM_SMEM_BYTES>>>(
            w2hp + (size_t)l * 256 * 128, pb2 + l * 128,
            w3hp + (size_t)l * 128 * 128, pb3 + l * 128);
        pair_reduce_ln<<<BB * NN, 512>>>(ln1g + l * 128, ln1b + l * 128);
        // FFN1 -> fp16 g_hh
        gemm_mma64<1, 0, 1><<<dim3(4, 12), 256, GM_SMEM_BYTES>>>(
            xp, 128, fW1 + (size_t)l * 128 * 512, nullptr, 1 << 30, 512,
            fb1 + l * 512, nullptr, hhp, nullptr, 512, 128);
        // FFN2: half A input -> fp32 g_y
        gemm_mma64<0, 1, 0><<<dim3(1, 12), 256, GM_SMEM_BYTES>>>(
            hhp, 512, fW2 + (size_t)l * 512 * 128, nullptr, 1 << 30, 128,
            fb2 + l * 128, nullptr, yp, nullptr, 128, 512);
        add_ln<<<BB * NN, 128>>>(ln2g + l * 128, ln2b + l * 128);
    }

    head_mma<<<dim3(VV / 128, 768 / 128), 256, HD_SMEM_BYTES>>>(headW, headb, out);
}

// round 16
// speedup vs baseline: 1.1546x; 1.0307x over previous
#include <cuda_runtime.h>
#include <cuda_fp16.h>
#include <math.h>
#include <string.h>
#include <stdint.h>

// Problem constants
#define BB 2
#define NN 384
#define DD 128
#define VV 8192
#define LL 2
#define NPAIR_B 73920
#define NPAIR_T 147840
#define PT 128
#define NTILES_MMA 1155      // 147840 / 128

// ---------------- scratch ----------------
__device__ float g_x[BB * NN * DD];
__device__ __half g_ah[BB * NN * 256];
__device__ __half g_ch[BB * NN * 256];
__device__ __half g_hh[BB * NN * 512];
__device__ float g_y[BB * NN * DD];
__device__ __half g_p[(size_t)BB * NN * NN * DD];
__device__ float g_s[BB * NN * NN];
__device__ __half g_w2h[LL * 256 * 128];
__device__ __half g_w3h[LL * 128 * 128];
__device__ __half g_whd[DD * VV];                  // headW fp16

__device__ __forceinline__ uint32_t h2u(__half2 h) {
    uint32_t r;
    memcpy(&r, &h, 4);
    return r;
}
__device__ __forceinline__ __half2 u2h(uint32_t u) {
    __half2 r;
    memcpy(&r, &u, 4);
    return r;
}

// half2 gelu: 2 elements per MUFU via tanh.approx.f16x2
__device__ __forceinline__ __half2 gelu2(__half2 x) {
    const __half2 c1 = __float2half2_rn(0.0356774081f);
    const __half2 c0 = __float2half2_rn(0.7978845608f);
    const __half2 hh = __float2half2_rn(0.5f);
    __half2 x2 = __hmul2(x, x);
    __half2 inner = __hfma2(c1, x2, c0);
    __half2 u = __hmul2(x, inner);
    uint32_t ui = h2u(u), ti;
    asm("tanh.approx.f16x2 %0, %1;" : "=r"(ti) : "r"(ui));
    __half2 t = u2h(ti);
    __half2 hx = __hmul2(hh, x);
    return __hfma2(hx, t, hx);
}

__device__ __forceinline__ void ldsm4(uint32_t* r, uint32_t addr) {
    asm volatile("ldmatrix.sync.aligned.m8n8.x4.shared.b16 {%0,%1,%2,%3}, [%4];"
                 : "=r"(r[0]), "=r"(r[1]), "=r"(r[2]), "=r"(r[3]) : "r"(addr));
}
__device__ __forceinline__ void ldsm4t(uint32_t* r, uint32_t addr) {
    asm volatile("ldmatrix.sync.aligned.m8n8.x4.trans.shared.b16 {%0,%1,%2,%3}, [%4];"
                 : "=r"(r[0]), "=r"(r[1]), "=r"(r[2]), "=r"(r[3]) : "r"(addr));
}
__device__ __forceinline__ void mma_f16(float c[4], const uint32_t a[4],
                                        uint32_t b0, uint32_t b1) {
    asm volatile(
        "mma.sync.aligned.m16n8k16.row.col.f32.f16.f16.f32 "
        "{%0,%1,%2,%3}, {%4,%5,%6,%7}, {%8,%9}, {%0,%1,%2,%3};"
        : "+f"(c[0]), "+f"(c[1]), "+f"(c[2]), "+f"(c[3])
        : "r"(a[0]), "r"(a[1]), "r"(a[2]), "r"(a[3]), "r"(b0), "r"(b1));
}
__device__ __forceinline__ void cpa16(uint32_t daddr, const void* g) {
    asm volatile("cp.async.cg.shared.global [%0], [%1], 16;" :: "r"(daddr), "l"(g));
}
#define CP_COMMIT asm volatile("cp.async.commit_group;")
#define CP_WAIT0 asm volatile("cp.async.wait_group 0;")

// ---------------- weight pre-convert ----------------
__global__ void convert_w(const float* __restrict__ pW2, const float* __restrict__ pW3,
                          const float* __restrict__ headW) {
    int t = blockIdx.x * 256 + threadIdx.x;
    const int n2 = LL * 256 * 128;
    const int n3 = LL * 128 * 128;
    const int nh = DD * VV;
    if (t < n2) {
        g_w2h[t] = __float2half(pW2[t]);
    } else if (t < n2 + n3) {
        int t3 = t - n2;
        g_w3h[t3] = __float2half(pW3[t3]);
    } else if (t < n2 + n3 + nh) {
        int th = t - n2 - n3;
        g_whd[th] = __float2half(headW[th]);
    }
}

// ---------------- embedding ----------------
__global__ void embed_kernel(const int* __restrict__ ids,
                             const float* __restrict__ emb,
                             const float* __restrict__ pos) {
    int t = blockIdx.x * blockDim.x + threadIdx.x;
    if (t >= BB * NN * DD) return;
    int d = t & (DD - 1);
    int bn = t >> 7;
    int n = bn % NN;
    g_x[t] = emb[ids[bn] * DD + d] + pos[n * DD + d];
}

// ================= generic fp16-mma GEMM, 64(M)x128(N) tiles ================
#define SBW 136
#define SPF 132
#define GM_OX 0
#define GM_OW 17408
#define GM_OB 52224
#define GM_SMEM_BYTES 52736

template <int ACT, int TAH, int TOH>
__global__ __launch_bounds__(256, 2) void gemm_mma64(
    const void* __restrict__ Av, int ldA,
    const float* __restrict__ Wa, const float* __restrict__ Wb, int nsplit, int ldW,
    const float* __restrict__ ba, const float* __restrict__ bb,
    void* __restrict__ Ca, void* __restrict__ Cb, int ldC, int K) {
    extern __shared__ char smc[];
    __half* Xh = (__half*)(smc + GM_OX);
    __half* Wh = (__half*)(smc + GM_OW);
    float* biass = (float*)(smc + GM_OB);
    float* Pf = (float*)smc;

    const int tid = threadIdx.x;
    const int lane = tid & 31;
    const int warp = tid >> 5;
    const int wm = warp >> 2;
    const int wn = warp & 3;
    const int lr = lane >> 2;
    const int lc = lane & 3;
    const int lrow = (lane & 7) + ((lane >> 3) & 1) * 8;
    const int lcol = (lane >> 4) * 8;

    const int n0 = blockIdx.x * 128;
    const int m0 = blockIdx.y * 64;

    const float* Wsrc;
    const float* bsrc;
    void* Cdst;
    if (n0 < nsplit) {
        Wsrc = Wa + n0;
        bsrc = ba ? ba + n0 : nullptr;
        Cdst = (char*)Ca + (size_t)n0 * (TOH ? 2 : 4);
    } else {
        int nn = n0 - nsplit;
        Wsrc = Wb + nn;
        bsrc = bb ? bb + nn : nullptr;
        Cdst = (char*)Cb + (size_t)nn * (TOH ? 2 : 4);
    }

    const uint32_t sb = (uint32_t)__cvta_generic_to_shared(smc);
    const uint32_t x_lane = sb + GM_OX + (uint32_t)(lrow * SBW + lcol) * 2;
    const uint32_t w_lane = sb + GM_OW + (uint32_t)(lrow * SBW + lcol) * 2;

    if (tid < 128) biass[tid] = bsrc ? bsrc[tid] : 0.f;

    float acc[2][4][4] = {};
    uint32_t af[2][4];
    uint32_t bf[4];

    const int nkc = K >> 7;
    for (int kc = 0; kc < nkc; kc++) {
        const int k0 = kc << 7;
        if (TAH) {
            const __half* A = (const __half*)Av;
            for (int e = tid; e < 64 * 16; e += 256) {
                int r = e >> 4, c8 = e & 15;
                const uint4 v = *(const uint4*)(A + (size_t)(m0 + r) * ldA + k0 + c8 * 8);
                *(uint4*)(Xh + r * SBW + c8 * 8) = v;
            }
        } else {
            const float* A = (const float*)Av;
            for (int e = tid; e < 64 * 32; e += 256) {
                int r = e >> 5, c4 = e & 31;
                const float4 v = *(const float4*)&A[(size_t)(m0 + r) * ldA + k0 + c4 * 4];
                __half2* d = (__half2*)(Xh + r * SBW + c4 * 4);
                d[0] = __floats2half2_rn(v.x, v.y);
                d[1] = __floats2half2_rn(v.z, v.w);
            }
        }
        for (int e = tid; e < 128 * 32; e += 256) {
            int k = e >> 5, n4 = e & 31;
            const float4 v = *(const float4*)&Wsrc[(size_t)(k0 + k) * ldW + n4 * 4];
            __half2* d = (__half2*)(Wh + k * SBW + n4 * 4);
            d[0] = __floats2half2_rn(v.x, v.y);
            d[1] = __floats2half2_rn(v.z, v.w);
        }
        __syncthreads();
#pragma unroll
        for (int ks = 0; ks < 8; ks++) {
            const int kb = ks * 16;
            ldsm4(af[0], x_lane + (uint32_t)((wm * 32) * SBW + kb) * 2);
            ldsm4(af[1], x_lane + (uint32_t)((wm * 32 + 16) * SBW + kb) * 2);
#pragma unroll
            for (int bt = 0; bt < 2; bt++) {
                ldsm4t(bf, w_lane + (uint32_t)(kb * SBW + wn * 32 + bt * 16) * 2);
                mma_f16(acc[0][2 * bt], af[0], bf[0], bf[1]);
                mma_f16(acc[1][2 * bt], af[1], bf[0], bf[1]);
                mma_f16(acc[0][2 * bt + 1], af[0], bf[2], bf[3]);
                mma_f16(acc[1][2 * bt + 1], af[1], bf[2], bf[3]);
            }
        }
        __syncthreads();
    }

#pragma unroll
    for (int mt = 0; mt < 2; mt++) {
        int r0 = wm * 32 + mt * 16 + lr;
#pragma unroll
        for (int nt = 0; nt < 4; nt++) {
            int cb = wn * 32 + nt * 8 + 2 * lc;
            float o0 = acc[mt][nt][0] + biass[cb];
            float o1 = acc[mt][nt][1] + biass[cb + 1];
            float o2 = acc[mt][nt][2] + biass[cb];
            float o3 = acc[mt][nt][3] + biass[cb + 1];
            if (ACT == 1) {
                float2 f01 = __half22float2(gelu2(__floats2half2_rn(o0, o1)));
                float2 f23 = __half22float2(gelu2(__floats2half2_rn(o2, o3)));
                o0 = f01.x; o1 = f01.y; o2 = f23.x; o3 = f23.y;
            }
            *(float2*)(Pf + r0 * SPF + cb) = make_float2(o0, o1);
            *(float2*)(Pf + (r0 + 8) * SPF + cb) = make_float2(o2, o3);
        }
    }
    __syncthreads();

    {
        int r = tid >> 2, q = tid & 3;
        const float* src = Pf + r * SPF + q * 32;
        if (TOH) {
            __half* dst = (__half*)Cdst + (size_t)(m0 + r) * ldC + q * 32;
#pragma unroll
            for (int u = 0; u < 32; u += 8) {
                float4 v0 = *(const float4*)(src + u);
                float4 v1 = *(const float4*)(src + u + 4);
                uint4 o;
                o.x = h2u(__floats2half2_rn(v0.x, v0.y));
                o.y = h2u(__floats2half2_rn(v0.z, v0.w));
                o.z = h2u(__floats2half2_rn(v1.x, v1.y));
                o.w = h2u(__floats2half2_rn(v1.z, v1.w));
                *(uint4*)(dst + u) = o;
            }
        } else {
            float* dst = (float*)Cdst + (size_t)(m0 + r) * ldC + q * 32;
#pragma unroll
            for (int u = 0; u < 32; u += 4)
                *(float4*)(dst + u) = *(const float4*)(src + u);
        }
    }
}

// ---------------- pair kernel: chunked, cp.async dbl-buffered W, fp16 mma ---
#define SA 72
#define SH 136
#define OWB0 0
#define OWB1 17408
#define OH1 34816
#define OH2 53248
#define OB2 88064
#define OB3 88576
#define ORA 89088
#define ORC 89600
#define OPO 90112
#define ONW 90624
#define PM_SMEM_BYTES 91648

__global__ __launch_bounds__(256, 2) void pair_mma(
    const __half* __restrict__ W2h, const float* __restrict__ b2,
    const __half* __restrict__ W3h, const float* __restrict__ b3) {
    extern __shared__ char smc[];
    __half* H1s = (__half*)(smc + OH1);
    __half* H2s = (__half*)(smc + OH2);
    float* b2s = (float*)(smc + OB2);
    float* b3s = (float*)(smc + OB3);
    int* rowA = (int*)(smc + ORA);
    int* rowC = (int*)(smc + ORC);
    int* poff = (int*)(smc + OPO);
    float* normw = (float*)(smc + ONW);

    const int tid = threadIdx.x;
    const int lane = tid & 31;
    const int warp = tid >> 5;
    const int wm = warp >> 1;
    const int wn = warp & 1;
    const int lr = lane >> 2;
    const int lc = lane & 3;
    const int lrow = (lane & 7) + ((lane >> 3) & 1) * 8;
    const int lcol = (lane >> 4) * 8;

    const uint32_t sb = (uint32_t)__cvta_generic_to_shared(smc);
    const uint32_t h1_lane = sb + OH1 + (uint32_t)(lrow * SA + lcol) * 2;
    const uint32_t h2_lane = sb + OH2 + (uint32_t)(lrow * SH + lcol) * 2;
    const uint32_t w_lane0 = sb + OWB0 + (uint32_t)(lrow * SBW + lcol) * 2;
    const uint32_t w_lane1 = sb + OWB1 + (uint32_t)(lrow * SBW + lcol) * 2;

    {
        const __half* src = W2h;
        uint32_t dbase = sb + OWB0;
#pragma unroll
        for (int e = tid; e < 1024; e += 256) {
            int row = e >> 4, seg = e & 15;
            cpa16(dbase + row * (SBW * 2) + seg * 16, src + row * 128 + seg * 8);
        }
        CP_COMMIT;
    }

    if (tid < 128) {
        b2s[tid] = b2[tid];
        b3s[tid] = b3[tid];
        int g = blockIdx.x * PT + tid;
        int b = (g >= NPAIR_B) ? 1 : 0;
        int idx = g - b * NPAIR_B;
        int i = (int)((sqrtf(8.0f * (float)idx + 1.0f) - 1.0f) * 0.5f);
        while ((i + 1) * (i + 2) / 2 <= idx) ++i;
        while (i * (i + 1) / 2 > idx) --i;
        int j = idx - i * (i + 1) / 2;
        rowA[tid] = b * NN + i;
        rowC[tid] = b * NN + j;
        poff[tid] = (b * NN + i) * NN + j;
    }
    __syncthreads();

#pragma unroll
    for (int e = tid; e < 128 * 8; e += 256) {
        int r = e >> 3, c8 = e & 7;
        const uint4 av = *(const uint4*)(g_ah + rowA[r] * 256 + c8 * 8);
        const uint4 cv = *(const uint4*)(g_ch + rowC[r] * 256 + c8 * 8);
        uint4 o;
        o.x = h2u(gelu2(__hadd2(u2h(av.x), u2h(cv.x))));
        o.y = h2u(gelu2(__hadd2(u2h(av.y), u2h(cv.y))));
        o.z = h2u(gelu2(__hadd2(u2h(av.z), u2h(cv.z))));
        o.w = h2u(gelu2(__hadd2(u2h(av.w), u2h(cv.w))));
        *(uint4*)(H1s + r * SA + c8 * 8) = o;
    }
    CP_WAIT0;
    __syncthreads();

    float acc[2][8][4] = {};
    uint32_t af[2][4];
    uint32_t bf[4];

    for (int kc = 0; kc < 4; kc++) {
        if (kc < 3) {
            const __half* src = W2h + (kc + 1) * 64 * 128;
            uint32_t dbase = sb + (((kc + 1) & 1) ? OWB1 : OWB0);
#pragma unroll
            for (int e = tid; e < 1024; e += 256) {
                int row = e >> 4, seg = e & 15;
                cpa16(dbase + row * (SBW * 2) + seg * 16, src + row * 128 + seg * 8);
            }
            CP_COMMIT;
        }
        const uint32_t wl = (kc & 1) ? w_lane1 : w_lane0;
#pragma unroll
        for (int ks = 0; ks < 4; ks++) {
            const int kb = ks * 16;
            ldsm4(af[0], h1_lane + (uint32_t)((wm * 32) * SA + kb) * 2);
            ldsm4(af[1], h1_lane + (uint32_t)((wm * 32 + 16) * SA + kb) * 2);
#pragma unroll
            for (int bt = 0; bt < 4; bt++) {
                ldsm4t(bf, wl + (uint32_t)(kb * SBW + wn * 64 + bt * 16) * 2);
                mma_f16(acc[0][2 * bt], af[0], bf[0], bf[1]);
                mma_f16(acc[1][2 * bt], af[1], bf[0], bf[1]);
                mma_f16(acc[0][2 * bt + 1], af[0], bf[2], bf[3]);
                mma_f16(acc[1][2 * bt + 1], af[1], bf[2], bf[3]);
            }
        }
        __syncthreads();
        if (kc < 3) {
            const int k0 = (kc + 1) * 64;
#pragma unroll
            for (int e = tid; e < 128 * 8; e += 256) {
                int r = e >> 3, c8 = e & 7;
                const uint4 av = *(const uint4*)(g_ah + rowA[r] * 256 + k0 + c8 * 8);
                const uint4 cv = *(const uint4*)(g_ch + rowC[r] * 256 + k0 + c8 * 8);
                uint4 o;
                o.x = h2u(gelu2(__hadd2(u2h(av.x), u2h(cv.x))));
                o.y = h2u(gelu2(__hadd2(u2h(av.y), u2h(cv.y))));
                o.z = h2u(gelu2(__hadd2(u2h(av.z), u2h(cv.z))));
                o.w = h2u(gelu2(__hadd2(u2h(av.w), u2h(cv.w))));
                *(uint4*)(H1s + r * SA + c8 * 8) = o;
            }
            CP_WAIT0;
            __syncthreads();
        }
    }

#pragma unroll
    for (int ch = 0; ch < 2; ch++) {
        const __half* src = W3h + ch * 64 * 128;
        uint32_t dbase = sb + (ch ? OWB1 : OWB0);
#pragma unroll
        for (int e = tid; e < 1024; e += 256) {
            int row = e >> 4, seg = e & 15;
            cpa16(dbase + row * (SBW * 2) + seg * 16, src + row * 128 + seg * 8);
        }
        CP_COMMIT;
    }

#pragma unroll
    for (int mt = 0; mt < 2; mt++) {
        int r0 = wm * 32 + mt * 16 + lr;
#pragma unroll
        for (int nt = 0; nt < 8; nt++) {
            int cb = wn * 64 + nt * 8 + 2 * lc;
            float bx = b2s[cb], by = b2s[cb + 1];
            *(__half2*)(H2s + r0 * SH + cb) =
                gelu2(__floats2half2_rn(acc[mt][nt][0] + bx, acc[mt][nt][1] + by));
            *(__half2*)(H2s + (r0 + 8) * SH + cb) =
                gelu2(__floats2half2_rn(acc[mt][nt][2] + bx, acc[mt][nt][3] + by));
        }
    }
    CP_WAIT0;
    __syncthreads();

    float acc2[2][8][4] = {};
#pragma unroll
    for (int ks = 0; ks < 8; ks++) {
        const int kbg = ks * 16;
        const uint32_t wl = (kbg & 64) ? w_lane1 : w_lane0;
        const int kb = kbg & 63;
        ldsm4(af[0], h2_lane + (uint32_t)((wm * 32) * SH + kbg) * 2);
        ldsm4(af[1], h2_lane + (uint32_t)((wm * 32 + 16) * SH + kbg) * 2);
#pragma unroll
        for (int bt = 0; bt < 4; bt++) {
            ldsm4t(bf, wl + (uint32_t)(kb * SBW + wn * 64 + bt * 16) * 2);
            mma_f16(acc2[0][2 * bt], af[0], bf[0], bf[1]);
            mma_f16(acc2[1][2 * bt], af[1], bf[0], bf[1]);
            mma_f16(acc2[0][2 * bt + 1], af[0], bf[2], bf[3]);
            mma_f16(acc2[1][2 * bt + 1], af[1], bf[2], bf[3]);
        }
    }
    __syncthreads();

#pragma unroll
    for (int mt = 0; mt < 2; mt++) {
        int r0 = wm * 32 + mt * 16 + lr;
        float n0s = 0.f, n1s = 0.f;
#pragma unroll
        for (int nt = 0; nt < 8; nt++) {
            int cb = wn * 64 + nt * 8 + 2 * lc;
            float bx = b3s[cb], by = b3s[cb + 1];
            float o0 = acc2[mt][nt][0] + bx, o1 = acc2[mt][nt][1] + by;
            float o2 = acc2[mt][nt][2] + bx, o3 = acc2[mt][nt][3] + by;
            n0s += o0 * o0 + o1 * o1;
            n1s += o2 * o2 + o3 * o3;
            *(__half2*)(H2s + r0 * SH + cb) = __floats2half2_rn(o0, o1);
            *(__half2*)(H2s + (r0 + 8) * SH + cb) = __floats2half2_rn(o2, o3);
        }
        n0s += __shfl_xor_sync(0xffffffffu, n0s, 1);
        n0s += __shfl_xor_sync(0xffffffffu, n0s, 2);
        n1s += __shfl_xor_sync(0xffffffffu, n1s, 1);
        n1s += __shfl_xor_sync(0xffffffffu, n1s, 2);
        if (lc == 0) {
            normw[r0 * 2 + wn] = n0s;
            normw[(r0 + 8) * 2 + wn] = n1s;
        }
    }
    __syncthreads();

    {
        int r = tid >> 1, hf = tid & 1;
        const uint4* src = (const uint4*)(smc + OH2 + r * (SH * 2) + hf * 128);
        uint4* dst = (uint4*)(g_p + (size_t)poff[r] * DD + hf * 64);
#pragma unroll
        for (int u = 0; u < 8; u++) dst[u] = src[u];
    }
    if (tid < 128) {
        float ss = normw[tid * 2] + normw[tid * 2 + 1];
        g_s[poff[tid]] = sqrtf(fmaxf(ss, 1e-30f));
    }
}

// ---------------- head: fp16 mma, 128x128 tiles, fp16 W loads ----------------
#define OHX 0
#define OHW 34816
#define OHB 69632
#define HD_SMEM_BYTES 70144

__global__ __launch_bounds__(256) void head_mma(
    const __half* __restrict__ headWh, const float* __restrict__ headb,
    float* __restrict__ out) {
    extern __shared__ char smc[];
    __half* Xh = (__half*)(smc + OHX);
    __half* Wh = (__half*)(smc + OHW);
    float* biass = (float*)(smc + OHB);
    float* Pf = (float*)smc;

    const int tid = threadIdx.x;
    const int lane = tid & 31;
    const int warp = tid >> 5;
    const int wm = warp >> 1;
    const int wn = warp & 1;
    const int lr = lane >> 2;
    const int lc = lane & 3;
    const int lrow = (lane & 7) + ((lane >> 3) & 1) * 8;
    const int lcol = (lane >> 4) * 8;

    const int n0 = blockIdx.x * 128;
    const int m0 = blockIdx.y * 128;

    const uint32_t sb = (uint32_t)__cvta_generic_to_shared(smc);
    const uint32_t x_lane = sb + OHX + (uint32_t)(lrow * SBW + lcol) * 2;
    const uint32_t w_lane = sb + OHW + (uint32_t)(lrow * SBW + lcol) * 2;

    for (int e = tid; e < 128 * 32; e += 256) {
        int r = e >> 5, c4 = e & 31;
        const float4 v = *(const float4*)&g_x[(m0 + r) * DD + c4 * 4];
        __half2* d = (__half2*)(Xh + r * SBW + c4 * 4);
        d[0] = __floats2half2_rn(v.x, v.y);
        d[1] = __floats2half2_rn(v.z, v.w);
    }
    for (int e = tid; e < 128 * 16; e += 256) {
        int k = e >> 4, n8 = e & 15;
        const uint4 v = *(const uint4*)(headWh + (size_t)k * VV + n0 + n8 * 8);
        *(uint4*)(Wh + k * SBW + n8 * 8) = v;
    }
    if (tid < 128) biass[tid] = headb[n0 + tid];
    __syncthreads();

    float acc[2][8][4] = {};
    uint32_t af[2][4];
    uint32_t bf[4];
#pragma unroll
    for (int ks = 0; ks < 8; ks++) {
        const int kb = ks * 16;
        ldsm4(af[0], x_lane + (uint32_t)((wm * 32) * SBW + kb) * 2);
        ldsm4(af[1], x_lane + (uint32_t)((wm * 32 + 16) * SBW + kb) * 2);
#pragma unroll
        for (int bt = 0; bt < 4; bt++) {
            ldsm4t(bf, w_lane + (uint32_t)(kb * SBW + wn * 64 + bt * 16) * 2);
            mma_f16(acc[0][2 * bt], af[0], bf[0], bf[1]);
            mma_f16(acc[1][2 * bt], af[1], bf[0], bf[1]);
            mma_f16(acc[0][2 * bt + 1], af[0], bf[2], bf[3]);
            mma_f16(acc[1][2 * bt + 1], af[1], bf[2], bf[3]);
        }
    }
    __syncthreads();

#pragma unroll
    for (int mt = 0; mt < 2; mt++) {
        int r0 = wm * 32 + mt * 16 + lr;
#pragma unroll
        for (int nt = 0; nt < 8; nt++) {
            int cb = wn * 64 + nt * 8 + 2 * lc;
            float bx = biass[cb], by = biass[cb + 1];
            *(float2*)(Pf + r0 * SPF + cb) =
                make_float2(acc[mt][nt][0] + bx, acc[mt][nt][1] + by);
            *(float2*)(Pf + (r0 + 8) * SPF + cb) =
                make_float2(acc[mt][nt][2] + bx, acc[mt][nt][3] + by);
        }
    }
    __syncthreads();

    {
        int r = tid >> 1, hf = tid & 1;
        const float* src = Pf + r * SPF + hf * 64;
        float* dst = out + (size_t)(m0 + r) * VV + n0 + hf * 64;
#pragma unroll
        for (int u = 0; u < 64; u += 4)
            *(float4*)(dst + u) = *(const float4*)(src + u);
    }
}

// ---------------- block reductions ----------------
__device__ __forceinline__ float blockSum512(float v, float* red) {
    int tid = threadIdx.x;
    red[tid] = v;
    __syncthreads();
    for (int s = 256; s; s >>= 1) {
        if (tid < s) red[tid] += red[tid + s];
        __syncthreads();
    }
    float r = red[0];
    __syncthreads();
    return r;
}
__device__ __forceinline__ float blockSum128(float v, float* red) {
    int tid = threadIdx.x;
    red[tid] = v;
    __syncthreads();
    for (int s = 64; s; s >>= 1) {
        if (tid < s) red[tid] += red[tid + s];
        __syncthreads();
    }
    float r = red[0];
    __syncthreads();
    return r;
}

// ---------------- phase B: softmax + weighted sum + residual + LN ----------
// 16 j-groups x 32 lanes x 4 cols; LDG.64 of g_p per iteration
__global__ __launch_bounds__(512) void pair_reduce_ln(
    const float* __restrict__ lng, const float* __restrict__ lnb) {
    __shared__ float red[512];
    __shared__ float ws[NN];
    __shared__ float accbuf[16][128];
    const int bi = blockIdx.x;
    const int i = bi % NN;
    const int tid = threadIdx.x;
    const int gid = tid >> 5;        // 0..15
    const int c4 = tid & 31;         // 4 cols each
    const int np = i + 1;
    const float* srow = g_s + (size_t)bi * NN;

    float dsum = 0.f;
    for (int j = tid; j < np; j += 512) {
        float w = expf(srow[j]);
        ws[j] = w;
        dsum += w;
    }
    float den = blockSum512(dsum, red);   // barrier -> ws visible

    const uint2* prow = (const uint2*)(g_p + (size_t)bi * NN * DD);
    float a0 = 0.f, a1 = 0.f, a2 = 0.f, a3 = 0.f;
#pragma unroll 2
    for (int j = gid; j < np; j += 16) {
        float w = ws[j];
        uint2 v = prow[j * 32 + c4];
        float2 p0 = __half22float2(u2h(v.x));
        float2 p1 = __half22float2(u2h(v.y));
        a0 = fmaf(w, p0.x, a0);
        a1 = fmaf(w, p0.y, a1);
        a2 = fmaf(w, p1.x, a2);
        a3 = fmaf(w, p1.y, a3);
    }
    accbuf[gid][c4 * 4] = a0;
    accbuf[gid][c4 * 4 + 1] = a1;
    accbuf[gid][c4 * 4 + 2] = a2;
    accbuf[gid][c4 * 4 + 3] = a3;
    __syncthreads();

    float v = 0.f;
    if (tid < 128) {
        float s = 0.f;
#pragma unroll
        for (int g = 0; g < 16; g++) s += accbuf[g][tid];
        v = g_x[bi * DD + tid] + s / den;
    }
    float mean = blockSum512(tid < 128 ? v : 0.f, red) * (1.0f / DD);
    float dv = v - mean;
    float var = blockSum512(tid < 128 ? dv * dv : 0.f, red) * (1.0f / DD);
    if (tid < 128)
        g_x[bi * DD + tid] = dv * rsqrtf(var + 1e-5f) * lng[tid] + lnb[tid];
}

// ---------------- FFN residual + LN ----------------
__global__ __launch_bounds__(128) void add_ln(
    const float* __restrict__ lng, const float* __restrict__ lnb) {
    __shared__ float red[128];
    const int bi = blockIdx.x;
    const int tid = threadIdx.x;
    float v = g_x[bi * DD + tid] + g_y[bi * DD + tid];
    float mean = blockSum128(v, red) * (1.0f / DD);
    float dv = v - mean;
    float var = blockSum128(dv * dv, red) * (1.0f / DD);
    g_x[bi * DD + tid] = dv * rsqrtf(var + 1e-5f) * lng[tid] + lnb[tid];
}

// ---------------- launcher ----------------
extern "C" void kernel_launch(void* const* d_in, const int* in_sizes, int n_in,
                              void* d_out, int out_size) {
    const int* ids = (const int*)d_in[0];
    const float* embw = (const float*)d_in[1];
    const float* pos = (const float*)d_in[2];
    const float* pW1 = (const float*)d_in[3];
    const float* pb1 = (const float*)d_in[4];
    const float* pW2 = (const float*)d_in[5];
    const float* pb2 = (const float*)d_in[6];
    const float* pW3 = (const float*)d_in[7];
    const float* pb3 = (const float*)d_in[8];
    const float* ln1g = (const float*)d_in[9];
    const float* ln1b = (const float*)d_in[10];
    const float* fW1 = (const float*)d_in[11];
    const float* fb1 = (const float*)d_in[12];
    const float* fW2 = (const float*)d_in[13];
    const float* fb2 = (const float*)d_in[14];
    const float* ln2g = (const float*)d_in[15];
    const float* ln2b = (const float*)d_in[16];
    const float* headW = (const float*)d_in[17];
    const float* headb = (const float*)d_in[18];
    float* out = (float*)d_out;

    cudaFuncSetAttribute(pair_mma, cudaFuncAttributeMaxDynamicSharedMemorySize,
                         PM_SMEM_BYTES);
    cudaFuncSetAttribute(head_mma, cudaFuncAttributeMaxDynamicSharedMemorySize,
                         HD_SMEM_BYTES);
    cudaFuncSetAttribute(gemm_mma64<0, 0, 1>, cudaFuncAttributeMaxDynamicSharedMemorySize,
                         GM_SMEM_BYTES);
    cudaFuncSetAttribute(gemm_mma64<1, 0, 1>, cudaFuncAttributeMaxDynamicSharedMemorySize,
                         GM_SMEM_BYTES);
    cudaFuncSetAttribute(gemm_mma64<0, 1, 0>, cudaFuncAttributeMaxDynamicSharedMemorySize,
                         GM_SMEM_BYTES);

    float *xp, *yp;
    cudaGetSymbolAddress((void**)&xp, g_x);
    cudaGetSymbolAddress((void**)&yp, g_y);
    __half *ahp, *chp, *hhp, *w2hp, *w3hp, *whdp;
    cudaGetSymbolAddress((void**)&ahp, g_ah);
    cudaGetSymbolAddress((void**)&chp, g_ch);
    cudaGetSymbolAddress((void**)&hhp, g_hh);
    cudaGetSymbolAddress((void**)&w2hp, g_w2h);
    cudaGetSymbolAddress((void**)&w3hp, g_w3h);
    cudaGetSymbolAddress((void**)&whdp, g_whd);

    embed_kernel<<<(BB * NN * DD + 255) / 256, 256>>>(ids, embw, pos);
    convert_w<<<(LL * 256 * 128 + LL * 128 * 128 + DD * VV + 255) / 256, 256>>>(
        pW2, pW3, headW);

    for (int l = 0; l < LL; l++) {
        const float* W1l = pW1 + (size_t)l * 256 * 256;
        gemm_mma64<0, 0, 1><<<dim3(4, 12), 256, GM_SMEM_BYTES>>>(
            xp, 128, W1l, W1l + 128 * 256, 256, 256,
            pb1 + l * 256, nullptr, ahp, chp, 256, 128);
        pair_mma<<<NTILES_MMA, 256, PM_SMEM_BYTES>>>(
            w2hp + (size_t)l * 256 * 128, pb2 + l * 128,
            w3hp + (size_t)l * 128 * 128, pb3 + l * 128);
        pair_reduce_ln<<<BB * NN, 512>>>(ln1g + l * 128, ln1b + l * 128);
        gemm_mma64<1, 0, 1><<<dim3(4, 12), 256, GM_SMEM_BYTES>>>(
            xp, 128, fW1 + (size_t)l * 128 * 512, nullptr, 1 << 30, 512,
            fb1 + l * 512, nullptr, hhp, nullptr, 512, 128);
        gemm_mma64<0, 1, 0><<<dim3(1, 12), 256, GM_SMEM_BYTES>>>(
            hhp, 512, fW2 + (size_t)l * 512 * 128, nullptr, 1 << 30, 128,
            fb2 + l * 128, nullptr, yp, nullptr, 128, 512);
        add_ln<<<BB * NN, 128>>>(ln2g + l * 128, ln2b + l * 128);
    }

    head_mma<<<dim3(VV / 128, 768 / 128), 256, HD_SMEM_BYTES>>>(whdp, headb, out);
}

// round 17
// speedup vs baseline: 1.1708x; 1.0141x over previous
#include <cuda_runtime.h>
#include <cuda_fp16.h>
#include <math.h>
#include <string.h>
#include <stdint.h>

// Problem constants
#define BB 2
#define NN 384
#define DD 128
#define VV 8192
#define LL 2
#define NPAIR_B 73920
#define NPAIR_T 147840
#define PT 128
#define NTILES_MMA 1155      // 147840 / 128

// ---------------- scratch ----------------
__device__ float g_x[BB * NN * DD];
__device__ __half g_ah[BB * NN * 256];
__device__ __half g_ch[BB * NN * 256];
__device__ __half g_hh[BB * NN * 512];
__device__ __half g_p[(size_t)BB * NN * NN * DD];
__device__ float g_s[BB * NN * NN];
__device__ __half g_w2h[LL * 256 * 128];
__device__ __half g_w3h[LL * 128 * 128];
__device__ __half g_whd[DD * VV];                  // headW fp16

__device__ __forceinline__ uint32_t h2u(__half2 h) {
    uint32_t r;
    memcpy(&r, &h, 4);
    return r;
}
__device__ __forceinline__ __half2 u2h(uint32_t u) {
    __half2 r;
    memcpy(&r, &u, 4);
    return r;
}

// half2 gelu: 2 elements per MUFU via tanh.approx.f16x2
__device__ __forceinline__ __half2 gelu2(__half2 x) {
    const __half2 c1 = __float2half2_rn(0.0356774081f);
    const __half2 c0 = __float2half2_rn(0.7978845608f);
    const __half2 hh = __float2half2_rn(0.5f);
    __half2 x2 = __hmul2(x, x);
    __half2 inner = __hfma2(c1, x2, c0);
    __half2 u = __hmul2(x, inner);
    uint32_t ui = h2u(u), ti;
    asm("tanh.approx.f16x2 %0, %1;" : "=r"(ti) : "r"(ui));
    __half2 t = u2h(ti);
    __half2 hx = __hmul2(hh, x);
    return __hfma2(hx, t, hx);
}

__device__ __forceinline__ void ldsm4(uint32_t* r, uint32_t addr) {
    asm volatile("ldmatrix.sync.aligned.m8n8.x4.shared.b16 {%0,%1,%2,%3}, [%4];"
                 : "=r"(r[0]), "=r"(r[1]), "=r"(r[2]), "=r"(r[3]) : "r"(addr));
}
__device__ __forceinline__ void ldsm4t(uint32_t* r, uint32_t addr) {
    asm volatile("ldmatrix.sync.aligned.m8n8.x4.trans.shared.b16 {%0,%1,%2,%3}, [%4];"
                 : "=r"(r[0]), "=r"(r[1]), "=r"(r[2]), "=r"(r[3]) : "r"(addr));
}
__device__ __forceinline__ void mma_f16(float c[4], const uint32_t a[4],
                                        uint32_t b0, uint32_t b1) {
    asm volatile(
        "mma.sync.aligned.m16n8k16.row.col.f32.f16.f16.f32 "
        "{%0,%1,%2,%3}, {%4,%5,%6,%7}, {%8,%9}, {%0,%1,%2,%3};"
        : "+f"(c[0]), "+f"(c[1]), "+f"(c[2]), "+f"(c[3])
        : "r"(a[0]), "r"(a[1]), "r"(a[2]), "r"(a[3]), "r"(b0), "r"(b1));
}
__device__ __forceinline__ void cpa16(uint32_t daddr, const void* g) {
    asm volatile("cp.async.cg.shared.global [%0], [%1], 16;" :: "r"(daddr), "l"(g));
}
#define CP_COMMIT asm volatile("cp.async.commit_group;")
#define CP_WAIT0 asm volatile("cp.async.wait_group 0;")

// ---------------- weight pre-convert ----------------
__global__ void convert_w(const float* __restrict__ pW2, const float* __restrict__ pW3,
                          const float* __restrict__ headW) {
    int t = blockIdx.x * 256 + threadIdx.x;
    const int n2 = LL * 256 * 128;
    const int n3 = LL * 128 * 128;
    const int nh = DD * VV;
    if (t < n2) {
        g_w2h[t] = __float2half(pW2[t]);
    } else if (t < n2 + n3) {
        int t3 = t - n2;
        g_w3h[t3] = __float2half(pW3[t3]);
    } else if (t < n2 + n3 + nh) {
        int th = t - n2 - n3;
        g_whd[th] = __float2half(headW[th]);
    }
}

// ---------------- embedding ----------------
__global__ void embed_kernel(const int* __restrict__ ids,
                             const float* __restrict__ emb,
                             const float* __restrict__ pos) {
    int t = blockIdx.x * blockDim.x + threadIdx.x;
    if (t >= BB * NN * DD) return;
    int d = t & (DD - 1);
    int bn = t >> 7;
    int n = bn % NN;
    g_x[t] = emb[ids[bn] * DD + d] + pos[n * DD + d];
}

// ================= generic fp16-mma GEMM, 64(M)x128(N) tiles ================
#define SBW 136
#define SPF 132
#define GM_OX 0
#define GM_OW 17408
#define GM_OB 52224
#define GM_SMEM_BYTES 52736

template <int ACT, int TAH, int TOH>
__global__ __launch_bounds__(256, 2) void gemm_mma64(
    const void* __restrict__ Av, int ldA,
    const float* __restrict__ Wa, const float* __restrict__ Wb, int nsplit, int ldW,
    const float* __restrict__ ba, const float* __restrict__ bb,
    void* __restrict__ Ca, void* __restrict__ Cb, int ldC, int K) {
    extern __shared__ char smc[];
    __half* Xh = (__half*)(smc + GM_OX);
    __half* Wh = (__half*)(smc + GM_OW);
    float* biass = (float*)(smc + GM_OB);
    float* Pf = (float*)smc;

    const int tid = threadIdx.x;
    const int lane = tid & 31;
    const int warp = tid >> 5;
    const int wm = warp >> 2;
    const int wn = warp & 3;
    const int lr = lane >> 2;
    const int lc = lane & 3;
    const int lrow = (lane & 7) + ((lane >> 3) & 1) * 8;
    const int lcol = (lane >> 4) * 8;

    const int n0 = blockIdx.x * 128;
    const int m0 = blockIdx.y * 64;

    const float* Wsrc;
    const float* bsrc;
    void* Cdst;
    if (n0 < nsplit) {
        Wsrc = Wa + n0;
        bsrc = ba ? ba + n0 : nullptr;
        Cdst = (char*)Ca + (size_t)n0 * (TOH ? 2 : 4);
    } else {
        int nn = n0 - nsplit;
        Wsrc = Wb + nn;
        bsrc = bb ? bb + nn : nullptr;
        Cdst = (char*)Cb + (size_t)nn * (TOH ? 2 : 4);
    }

    const uint32_t sb = (uint32_t)__cvta_generic_to_shared(smc);
    const uint32_t x_lane = sb + GM_OX + (uint32_t)(lrow * SBW + lcol) * 2;
    const uint32_t w_lane = sb + GM_OW + (uint32_t)(lrow * SBW + lcol) * 2;

    if (tid < 128) biass[tid] = bsrc ? bsrc[tid] : 0.f;

    float acc[2][4][4] = {};
    uint32_t af[2][4];
    uint32_t bf[4];

    const int nkc = K >> 7;
    for (int kc = 0; kc < nkc; kc++) {
        const int k0 = kc << 7;
        if (TAH) {
            const __half* A = (const __half*)Av;
            for (int e = tid; e < 64 * 16; e += 256) {
                int r = e >> 4, c8 = e & 15;
                const uint4 v = *(const uint4*)(A + (size_t)(m0 + r) * ldA + k0 + c8 * 8);
                *(uint4*)(Xh + r * SBW + c8 * 8) = v;
            }
        } else {
            const float* A = (const float*)Av;
            for (int e = tid; e < 64 * 32; e += 256) {
                int r = e >> 5, c4 = e & 31;
                const float4 v = *(const float4*)&A[(size_t)(m0 + r) * ldA + k0 + c4 * 4];
                __half2* d = (__half2*)(Xh + r * SBW + c4 * 4);
                d[0] = __floats2half2_rn(v.x, v.y);
                d[1] = __floats2half2_rn(v.z, v.w);
            }
        }
        for (int e = tid; e < 128 * 32; e += 256) {
            int k = e >> 5, n4 = e & 31;
            const float4 v = *(const float4*)&Wsrc[(size_t)(k0 + k) * ldW + n4 * 4];
            __half2* d = (__half2*)(Wh + k * SBW + n4 * 4);
            d[0] = __floats2half2_rn(v.x, v.y);
            d[1] = __floats2half2_rn(v.z, v.w);
        }
        __syncthreads();
#pragma unroll
        for (int ks = 0; ks < 8; ks++) {
            const int kb = ks * 16;
            ldsm4(af[0], x_lane + (uint32_t)((wm * 32) * SBW + kb) * 2);
            ldsm4(af[1], x_lane + (uint32_t)((wm * 32 + 16) * SBW + kb) * 2);
#pragma unroll
            for (int bt = 0; bt < 2; bt++) {
                ldsm4t(bf, w_lane + (uint32_t)(kb * SBW + wn * 32 + bt * 16) * 2);
                mma_f16(acc[0][2 * bt], af[0], bf[0], bf[1]);
                mma_f16(acc[1][2 * bt], af[1], bf[0], bf[1]);
                mma_f16(acc[0][2 * bt + 1], af[0], bf[2], bf[3]);
                mma_f16(acc[1][2 * bt + 1], af[1], bf[2], bf[3]);
            }
        }
        __syncthreads();
    }

#pragma unroll
    for (int mt = 0; mt < 2; mt++) {
        int r0 = wm * 32 + mt * 16 + lr;
#pragma unroll
        for (int nt = 0; nt < 4; nt++) {
            int cb = wn * 32 + nt * 8 + 2 * lc;
            float o0 = acc[mt][nt][0] + biass[cb];
            float o1 = acc[mt][nt][1] + biass[cb + 1];
            float o2 = acc[mt][nt][2] + biass[cb];
            float o3 = acc[mt][nt][3] + biass[cb + 1];
            if (ACT == 1) {
                float2 f01 = __half22float2(gelu2(__floats2half2_rn(o0, o1)));
                float2 f23 = __half22float2(gelu2(__floats2half2_rn(o2, o3)));
                o0 = f01.x; o1 = f01.y; o2 = f23.x; o3 = f23.y;
            }
            *(float2*)(Pf + r0 * SPF + cb) = make_float2(o0, o1);
            *(float2*)(Pf + (r0 + 8) * SPF + cb) = make_float2(o2, o3);
        }
    }
    __syncthreads();

    {
        int r = tid >> 2, q = tid & 3;
        const float* src = Pf + r * SPF + q * 32;
        if (TOH) {
            __half* dst = (__half*)Cdst + (size_t)(m0 + r) * ldC + q * 32;
#pragma unroll
            for (int u = 0; u < 32; u += 8) {
                float4 v0 = *(const float4*)(src + u);
                float4 v1 = *(const float4*)(src + u + 4);
                uint4 o;
                o.x = h2u(__floats2half2_rn(v0.x, v0.y));
                o.y = h2u(__floats2half2_rn(v0.z, v0.w));
                o.z = h2u(__floats2half2_rn(v1.x, v1.y));
                o.w = h2u(__floats2half2_rn(v1.z, v1.w));
                *(uint4*)(dst + u) = o;
            }
        } else {
            float* dst = (float*)Cdst + (size_t)(m0 + r) * ldC + q * 32;
#pragma unroll
            for (int u = 0; u < 32; u += 4)
                *(float4*)(dst + u) = *(const float4*)(src + u);
        }
    }
}

// ================= FFN2 + residual + LN fused (half A input) ================
__global__ __launch_bounds__(256, 2) void ffn2_ln(
    const float* __restrict__ W, const float* __restrict__ bias,
    const float* __restrict__ lng, const float* __restrict__ lnb) {
    extern __shared__ char smc[];
    __half* Xh = (__half*)(smc + GM_OX);
    __half* Wh = (__half*)(smc + GM_OW);
    float* biass = (float*)(smc + GM_OB);
    float* Pf = (float*)smc;

    const int tid = threadIdx.x;
    const int lane = tid & 31;
    const int warp = tid >> 5;
    const int wm = warp >> 2;
    const int wn = warp & 3;
    const int lr = lane >> 2;
    const int lc = lane & 3;
    const int lrow = (lane & 7) + ((lane >> 3) & 1) * 8;
    const int lcol = (lane >> 4) * 8;
    const int m0 = blockIdx.x * 64;

    const uint32_t sb = (uint32_t)__cvta_generic_to_shared(smc);
    const uint32_t x_lane = sb + GM_OX + (uint32_t)(lrow * SBW + lcol) * 2;
    const uint32_t w_lane = sb + GM_OW + (uint32_t)(lrow * SBW + lcol) * 2;

    if (tid < 128) biass[tid] = bias[tid];

    float acc[2][4][4] = {};
    uint32_t af[2][4];
    uint32_t bf[4];

    for (int kc = 0; kc < 4; kc++) {
        const int k0 = kc << 7;
        for (int e = tid; e < 64 * 16; e += 256) {
            int r = e >> 4, c8 = e & 15;
            const uint4 v = *(const uint4*)(g_hh + (size_t)(m0 + r) * 512 + k0 + c8 * 8);
            *(uint4*)(Xh + r * SBW + c8 * 8) = v;
        }
        for (int e = tid; e < 128 * 32; e += 256) {
            int k = e >> 5, n4 = e & 31;
            const float4 v = *(const float4*)&W[(size_t)(k0 + k) * 128 + n4 * 4];
            __half2* d = (__half2*)(Wh + k * SBW + n4 * 4);
            d[0] = __floats2half2_rn(v.x, v.y);
            d[1] = __floats2half2_rn(v.z, v.w);
        }
        __syncthreads();
#pragma unroll
        for (int ks = 0; ks < 8; ks++) {
            const int kb = ks * 16;
            ldsm4(af[0], x_lane + (uint32_t)((wm * 32) * SBW + kb) * 2);
            ldsm4(af[1], x_lane + (uint32_t)((wm * 32 + 16) * SBW + kb) * 2);
#pragma unroll
            for (int bt = 0; bt < 2; bt++) {
                ldsm4t(bf, w_lane + (uint32_t)(kb * SBW + wn * 32 + bt * 16) * 2);
                mma_f16(acc[0][2 * bt], af[0], bf[0], bf[1]);
                mma_f16(acc[1][2 * bt], af[1], bf[0], bf[1]);
                mma_f16(acc[0][2 * bt + 1], af[0], bf[2], bf[3]);
                mma_f16(acc[1][2 * bt + 1], af[1], bf[2], bf[3]);
            }
        }
        __syncthreads();
    }

    // stage C = acc + bias into Pf
#pragma unroll
    for (int mt = 0; mt < 2; mt++) {
        int r0 = wm * 32 + mt * 16 + lr;
#pragma unroll
        for (int nt = 0; nt < 4; nt++) {
            int cb = wn * 32 + nt * 8 + 2 * lc;
            *(float2*)(Pf + r0 * SPF + cb) =
                make_float2(acc[mt][nt][0] + biass[cb], acc[mt][nt][1] + biass[cb + 1]);
            *(float2*)(Pf + (r0 + 8) * SPF + cb) =
                make_float2(acc[mt][nt][2] + biass[cb], acc[mt][nt][3] + biass[cb + 1]);
        }
    }
    __syncthreads();

    // residual + LN: 4 threads per row (quad shfl), write g_x in place
    {
        int r = tid >> 2, q = tid & 3;
        int row = m0 + r;
        float4 vv[8];
        float s = 0.f, sq = 0.f;
#pragma unroll
        for (int u = 0; u < 8; u++) {
            float4 p = *(const float4*)(Pf + r * SPF + q * 32 + u * 4);
            const float4 x = *(const float4*)&g_x[row * DD + q * 32 + u * 4];
            float4 v = make_float4(p.x + x.x, p.y + x.y, p.z + x.z, p.w + x.w);
            vv[u] = v;
            s += v.x + v.y + v.z + v.w;
            sq += v.x * v.x + v.y * v.y + v.z * v.z + v.w * v.w;
        }
        s += __shfl_xor_sync(0xffffffffu, s, 1);
        s += __shfl_xor_sync(0xffffffffu, s, 2);
        sq += __shfl_xor_sync(0xffffffffu, sq, 1);
        sq += __shfl_xor_sync(0xffffffffu, sq, 2);
        float mean = s * (1.0f / DD);
        float var = sq * (1.0f / DD) - mean * mean;
        float rs = rsqrtf(var + 1e-5f);
#pragma unroll
        for (int u = 0; u < 8; u++) {
            const float4 g = *(const float4*)&lng[q * 32 + u * 4];
            const float4 b = *(const float4*)&lnb[q * 32 + u * 4];
            float4 o;
            o.x = (vv[u].x - mean) * rs * g.x + b.x;
            o.y = (vv[u].y - mean) * rs * g.y + b.y;
            o.z = (vv[u].z - mean) * rs * g.z + b.z;
            o.w = (vv[u].w - mean) * rs * g.w + b.w;
            *(float4*)&g_x[row * DD + q * 32 + u * 4] = o;
        }
    }
}

// ---------------- pair kernel: chunked, cp.async dbl-buffered W, fp16 mma ---
#define SA 72
#define SH 136
#define OWB0 0
#define OWB1 17408
#define OH1 34816
#define OH2 53248
#define OB2 88064
#define OB3 88576
#define ORA 89088
#define ORC 89600
#define OPO 90112
#define ONW 90624
#define PM_SMEM_BYTES 91648

__global__ __launch_bounds__(256, 2) void pair_mma(
    const __half* __restrict__ W2h, const float* __restrict__ b2,
    const __half* __restrict__ W3h, const float* __restrict__ b3) {
    extern __shared__ char smc[];
    __half* H1s = (__half*)(smc + OH1);
    __half* H2s = (__half*)(smc + OH2);
    float* b2s = (float*)(smc + OB2);
    float* b3s = (float*)(smc + OB3);
    int* rowA = (int*)(smc + ORA);
    int* rowC = (int*)(smc + ORC);
    int* poff = (int*)(smc + OPO);
    float* normw = (float*)(smc + ONW);

    const int tid = threadIdx.x;
    const int lane = tid & 31;
    const int warp = tid >> 5;
    const int wm = warp >> 1;
    const int wn = warp & 1;
    const int lr = lane >> 2;
    const int lc = lane & 3;
    const int lrow = (lane & 7) + ((lane >> 3) & 1) * 8;
    const int lcol = (lane >> 4) * 8;

    const uint32_t sb = (uint32_t)__cvta_generic_to_shared(smc);
    const uint32_t h1_lane = sb + OH1 + (uint32_t)(lrow * SA + lcol) * 2;
    const uint32_t h2_lane = sb + OH2 + (uint32_t)(lrow * SH + lcol) * 2;
    const uint32_t w_lane0 = sb + OWB0 + (uint32_t)(lrow * SBW + lcol) * 2;
    const uint32_t w_lane1 = sb + OWB1 + (uint32_t)(lrow * SBW + lcol) * 2;

    {
        const __half* src = W2h;
        uint32_t dbase = sb + OWB0;
#pragma unroll
        for (int e = tid; e < 1024; e += 256) {
            int row = e >> 4, seg = e & 15;
            cpa16(dbase + row * (SBW * 2) + seg * 16, src + row * 128 + seg * 8);
        }
        CP_COMMIT;
    }

    if (tid < 128) {
        b2s[tid] = b2[tid];
        b3s[tid] = b3[tid];
        int g = blockIdx.x * PT + tid;
        int b = (g >= NPAIR_B) ? 1 : 0;
        int idx = g - b * NPAIR_B;
        int i = (int)((sqrtf(8.0f * (float)idx + 1.0f) - 1.0f) * 0.5f);
        while ((i + 1) * (i + 2) / 2 <= idx) ++i;
        while (i * (i + 1) / 2 > idx) --i;
        int j = idx - i * (i + 1) / 2;
        rowA[tid] = b * NN + i;
        rowC[tid] = b * NN + j;
        poff[tid] = (b * NN + i) * NN + j;
    }
    __syncthreads();

#pragma unroll
    for (int e = tid; e < 128 * 8; e += 256) {
        int r = e >> 3, c8 = e & 7;
        const uint4 av = *(const uint4*)(g_ah + rowA[r] * 256 + c8 * 8);
        const uint4 cv = *(const uint4*)(g_ch + rowC[r] * 256 + c8 * 8);
        uint4 o;
        o.x = h2u(gelu2(__hadd2(u2h(av.x), u2h(cv.x))));
        o.y = h2u(gelu2(__hadd2(u2h(av.y), u2h(cv.y))));
        o.z = h2u(gelu2(__hadd2(u2h(av.z), u2h(cv.z))));
        o.w = h2u(gelu2(__hadd2(u2h(av.w), u2h(cv.w))));
        *(uint4*)(H1s + r * SA + c8 * 8) = o;
    }
    CP_WAIT0;
    __syncthreads();

    float acc[2][8][4] = {};
    uint32_t af[2][4];
    uint32_t bf[4];

    for (int kc = 0; kc < 4; kc++) {
        if (kc < 3) {
            const __half* src = W2h + (kc + 1) * 64 * 128;
            uint32_t dbase = sb + (((kc + 1) & 1) ? OWB1 : OWB0);
#pragma unroll
            for (int e = tid; e < 1024; e += 256) {
                int row = e >> 4, seg = e & 15;
                cpa16(dbase + row * (SBW * 2) + seg * 16, src + row * 128 + seg * 8);
            }
            CP_COMMIT;
        }
        const uint32_t wl = (kc & 1) ? w_lane1 : w_lane0;
#pragma unroll
        for (int ks = 0; ks < 4; ks++) {
            const int kb = ks * 16;
            ldsm4(af[0], h1_lane + (uint32_t)((wm * 32) * SA + kb) * 2);
            ldsm4(af[1], h1_lane + (uint32_t)((wm * 32 + 16) * SA + kb) * 2);
#pragma unroll
            for (int bt = 0; bt < 4; bt++) {
                ldsm4t(bf, wl + (uint32_t)(kb * SBW + wn * 64 + bt * 16) * 2);
                mma_f16(acc[0][2 * bt], af[0], bf[0], bf[1]);
                mma_f16(acc[1][2 * bt], af[1], bf[0], bf[1]);
                mma_f16(acc[0][2 * bt + 1], af[0], bf[2], bf[3]);
                mma_f16(acc[1][2 * bt + 1], af[1], bf[2], bf[3]);
            }
        }
        __syncthreads();
        if (kc < 3) {
            const int k0 = (kc + 1) * 64;
#pragma unroll
            for (int e = tid; e < 128 * 8; e += 256) {
                int r = e >> 3, c8 = e & 7;
                const uint4 av = *(const uint4*)(g_ah + rowA[r] * 256 + k0 + c8 * 8);
                const uint4 cv = *(const uint4*)(g_ch + rowC[r] * 256 + k0 + c8 * 8);
                uint4 o;
                o.x = h2u(gelu2(__hadd2(u2h(av.x), u2h(cv.x))));
                o.y = h2u(gelu2(__hadd2(u2h(av.y), u2h(cv.y))));
                o.z = h2u(gelu2(__hadd2(u2h(av.z), u2h(cv.z))));
                o.w = h2u(gelu2(__hadd2(u2h(av.w), u2h(cv.w))));
                *(uint4*)(H1s + r * SA + c8 * 8) = o;
            }
            CP_WAIT0;
            __syncthreads();
        }
    }

#pragma unroll
    for (int ch = 0; ch < 2; ch++) {
        const __half* src = W3h + ch * 64 * 128;
        uint32_t dbase = sb + (ch ? OWB1 : OWB0);
#pragma unroll
        for (int e = tid; e < 1024; e += 256) {
            int row = e >> 4, seg = e & 15;
            cpa16(dbase + row * (SBW * 2) + seg * 16, src + row * 128 + seg * 8);
        }
        CP_COMMIT;
    }

#pragma unroll
    for (int mt = 0; mt < 2; mt++) {
        int r0 = wm * 32 + mt * 16 + lr;
#pragma unroll
        for (int nt = 0; nt < 8; nt++) {
            int cb = wn * 64 + nt * 8 + 2 * lc;
            float bx = b2s[cb], by = b2s[cb + 1];
            *(__half2*)(H2s + r0 * SH + cb) =
                gelu2(__floats2half2_rn(acc[mt][nt][0] + bx, acc[mt][nt][1] + by));
            *(__half2*)(H2s + (r0 + 8) * SH + cb) =
                gelu2(__floats2half2_rn(acc[mt][nt][2] + bx, acc[mt][nt][3] + by));
        }
    }
    CP_WAIT0;
    __syncthreads();

    float acc2[2][8][4] = {};
#pragma unroll
    for (int ks = 0; ks < 8; ks++) {
        const int kbg = ks * 16;
        const uint32_t wl = (kbg & 64) ? w_lane1 : w_lane0;
        const int kb = kbg & 63;
        ldsm4(af[0], h2_lane + (uint32_t)((wm * 32) * SH + kbg) * 2);
        ldsm4(af[1], h2_lane + (uint32_t)((wm * 32 + 16) * SH + kbg) * 2);
#pragma unroll
        for (int bt = 0; bt < 4; bt++) {
            ldsm4t(bf, wl + (uint32_t)(kb * SBW + wn * 64 + bt * 16) * 2);
            mma_f16(acc2[0][2 * bt], af[0], bf[0], bf[1]);
            mma_f16(acc2[1][2 * bt], af[1], bf[0], bf[1]);
            mma_f16(acc2[0][2 * bt + 1], af[0], bf[2], bf[3]);
            mma_f16(acc2[1][2 * bt + 1], af[1], bf[2], bf[3]);
        }
    }
    __syncthreads();

#pragma unroll
    for (int mt = 0; mt < 2; mt++) {
        int r0 = wm * 32 + mt * 16 + lr;
        float n0s = 0.f, n1s = 0.f;
#pragma unroll
        for (int nt = 0; nt < 8; nt++) {
            int cb = wn * 64 + nt * 8 + 2 * lc;
            float bx = b3s[cb], by = b3s[cb + 1];
            float o0 = acc2[mt][nt][0] + bx, o1 = acc2[mt][nt][1] + by;
            float o2 = acc2[mt][nt][2] + bx, o3 = acc2[mt][nt][3] + by;
            n0s += o0 * o0 + o1 * o1;
            n1s += o2 * o2 + o3 * o3;
            *(__half2*)(H2s + r0 * SH + cb) = __floats2half2_rn(o0, o1);
            *(__half2*)(H2s + (r0 + 8) * SH + cb) = __floats2half2_rn(o2, o3);
        }
        n0s += __shfl_xor_sync(0xffffffffu, n0s, 1);
        n0s += __shfl_xor_sync(0xffffffffu, n0s, 2);
        n1s += __shfl_xor_sync(0xffffffffu, n1s, 1);
        n1s += __shfl_xor_sync(0xffffffffu, n1s, 2);
        if (lc == 0) {
            normw[r0 * 2 + wn] = n0s;
            normw[(r0 + 8) * 2 + wn] = n1s;
        }
    }
    __syncthreads();

    {
        int r = tid >> 1, hf = tid & 1;
        const uint4* src = (const uint4*)(smc + OH2 + r * (SH * 2) + hf * 128);
        uint4* dst = (uint4*)(g_p + (size_t)poff[r] * DD + hf * 64);
#pragma unroll
        for (int u = 0; u < 8; u++) dst[u] = src[u];
    }
    if (tid < 128) {
        float ss = normw[tid * 2] + normw[tid * 2 + 1];
        g_s[poff[tid]] = sqrtf(fmaxf(ss, 1e-30f));
    }
}

// ---------------- head: fp16 mma, 128x128 tiles, fp16 W loads ----------------
#define OHX 0
#define OHW 34816
#define OHB 69632
#define HD_SMEM_BYTES 70144

__global__ __launch_bounds__(256) void head_mma(
    const __half* __restrict__ headWh, const float* __restrict__ headb,
    float* __restrict__ out) {
    extern __shared__ char smc[];
    __half* Xh = (__half*)(smc + OHX);
    __half* Wh = (__half*)(smc + OHW);
    float* biass = (float*)(smc + OHB);
    float* Pf = (float*)smc;

    const int tid = threadIdx.x;
    const int lane = tid & 31;
    const int warp = tid >> 5;
    const int wm = warp >> 1;
    const int wn = warp & 1;
    const int lr = lane >> 2;
    const int lc = lane & 3;
    const int lrow = (lane & 7) + ((lane >> 3) & 1) * 8;
    const int lcol = (lane >> 4) * 8;

    const int n0 = blockIdx.x * 128;
    const int m0 = blockIdx.y * 128;

    const uint32_t sb = (uint32_t)__cvta_generic_to_shared(smc);
    const uint32_t x_lane = sb + OHX + (uint32_t)(lrow * SBW + lcol) * 2;
    const uint32_t w_lane = sb + OHW + (uint32_t)(lrow * SBW + lcol) * 2;

    for (int e = tid; e < 128 * 32; e += 256) {
        int r = e >> 5, c4 = e & 31;
        const float4 v = *(const float4*)&g_x[(m0 + r) * DD + c4 * 4];
        __half2* d = (__half2*)(Xh + r * SBW + c4 * 4);
        d[0] = __floats2half2_rn(v.x, v.y);
        d[1] = __floats2half2_rn(v.z, v.w);
    }
    for (int e = tid; e < 128 * 16; e += 256) {
        int k = e >> 4, n8 = e & 15;
        const uint4 v = *(const uint4*)(headWh + (size_t)k * VV + n0 + n8 * 8);
        *(uint4*)(Wh + k * SBW + n8 * 8) = v;
    }
    if (tid < 128) biass[tid] = headb[n0 + tid];
    __syncthreads();

    float acc[2][8][4] = {};
    uint32_t af[2][4];
    uint32_t bf[4];
#pragma unroll
    for (int ks = 0; ks < 8; ks++) {
        const int kb = ks * 16;
        ldsm4(af[0], x_lane + (uint32_t)((wm * 32) * SBW + kb) * 2);
        ldsm4(af[1], x_lane + (uint32_t)((wm * 32 + 16) * SBW + kb) * 2);
#pragma unroll
        for (int bt = 0; bt < 4; bt++) {
            ldsm4t(bf, w_lane + (uint32_t)(kb * SBW + wn * 64 + bt * 16) * 2);
            mma_f16(acc[0][2 * bt], af[0], bf[0], bf[1]);
            mma_f16(acc[1][2 * bt], af[1], bf[0], bf[1]);
            mma_f16(acc[0][2 * bt + 1], af[0], bf[2], bf[3]);
            mma_f16(acc[1][2 * bt + 1], af[1], bf[2], bf[3]);
        }
    }
    __syncthreads();

#pragma unroll
    for (int mt = 0; mt < 2; mt++) {
        int r0 = wm * 32 + mt * 16 + lr;
#pragma unroll
        for (int nt = 0; nt < 8; nt++) {
            int cb = wn * 64 + nt * 8 + 2 * lc;
            float bx = biass[cb], by = biass[cb + 1];
            *(float2*)(Pf + r0 * SPF + cb) =
                make_float2(acc[mt][nt][0] + bx, acc[mt][nt][1] + by);
            *(float2*)(Pf + (r0 + 8) * SPF + cb) =
                make_float2(acc[mt][nt][2] + bx, acc[mt][nt][3] + by);
        }
    }
    __syncthreads();

    {
        int r = tid >> 1, hf = tid & 1;
        const float* src = Pf + r * SPF + hf * 64;
        float* dst = out + (size_t)(m0 + r) * VV + n0 + hf * 64;
#pragma unroll
        for (int u = 0; u < 64; u += 4)
            *(float4*)(dst + u) = *(const float4*)(src + u);
    }
}

// ---------------- block reductions ----------------
__device__ __forceinline__ float blockSum512(float v, float* red) {
    int tid = threadIdx.x;
    red[tid] = v;
    __syncthreads();
    for (int s = 256; s; s >>= 1) {
        if (tid < s) red[tid] += red[tid + s];
        __syncthreads();
    }
    float r = red[0];
    __syncthreads();
    return r;
}

// ---------------- phase B: softmax + weighted sum + residual + LN ----------
// 16 j-groups x 32 lanes x 4 cols; 4-deep pipelined LDG.64 of g_p
__global__ __launch_bounds__(512) void pair_reduce_ln(
    const float* __restrict__ lng, const float* __restrict__ lnb) {
    __shared__ float red[512];
    __shared__ float ws[NN];
    __shared__ float accbuf[16][128];
    const int bi = blockIdx.x;
    const int i = bi % NN;
    const int tid = threadIdx.x;
    const int gid = tid >> 5;
    const int c4 = tid & 31;
    const int np = i + 1;
    const float* srow = g_s + (size_t)bi * NN;

    float dsum = 0.f;
    for (int j = tid; j < np; j += 512) {
        float w = expf(srow[j]);
        ws[j] = w;
        dsum += w;
    }
    float den = blockSum512(dsum, red);

    const uint2* prow = (const uint2*)(g_p + (size_t)bi * NN * DD);
    float a0 = 0.f, a1 = 0.f, a2 = 0.f, a3 = 0.f;
    int j = gid;
    for (; j + 48 < np; j += 64) {
        uint2 v0 = prow[j * 32 + c4];
        uint2 v1 = prow[(j + 16) * 32 + c4];
        uint2 v2 = prow[(j + 32) * 32 + c4];
        uint2 v3 = prow[(j + 48) * 32 + c4];
        float w0 = ws[j], w1 = ws[j + 16], w2 = ws[j + 32], w3 = ws[j + 48];
        float2 p;
        p = __half22float2(u2h(v0.x)); a0 = fmaf(w0, p.x, a0); a1 = fmaf(w0, p.y, a1);
        p = __half22float2(u2h(v0.y)); a2 = fmaf(w0, p.x, a2); a3 = fmaf(w0, p.y, a3);
        p = __half22float2(u2h(v1.x)); a0 = fmaf(w1, p.x, a0); a1 = fmaf(w1, p.y, a1);
        p = __half22float2(u2h(v1.y)); a2 = fmaf(w1, p.x, a2); a3 = fmaf(w1, p.y, a3);
        p = __half22float2(u2h(v2.x)); a0 = fmaf(w2, p.x, a0); a1 = fmaf(w2, p.y, a1);
        p = __half22float2(u2h(v2.y)); a2 = fmaf(w2, p.x, a2); a3 = fmaf(w2, p.y, a3);
        p = __half22float2(u2h(v3.x)); a0 = fmaf(w3, p.x, a0); a1 = fmaf(w3, p.y, a1);
        p = __half22float2(u2h(v3.y)); a2 = fmaf(w3, p.x, a2); a3 = fmaf(w3, p.y, a3);
    }
    for (; j < np; j += 16) {
        float w = ws[j];
        uint2 v = prow[j * 32 + c4];
        float2 p0 = __half22float2(u2h(v.x));
        float2 p1 = __half22float2(u2h(v.y));
        a0 = fmaf(w, p0.x, a0);
        a1 = fmaf(w, p0.y, a1);
        a2 = fmaf(w, p1.x, a2);
        a3 = fmaf(w, p1.y, a3);
    }
    accbuf[gid][c4 * 4] = a0;
    accbuf[gid][c4 * 4 + 1] = a1;
    accbuf[gid][c4 * 4 + 2] = a2;
    accbuf[gid][c4 * 4 + 3] = a3;
    __syncthreads();

    float v = 0.f;
    if (tid < 128) {
        float s = 0.f;
#pragma unroll
        for (int g = 0; g < 16; g++) s += accbuf[g][tid];
        v = g_x[bi * DD + tid] + s / den;
    }
    float mean = blockSum512(tid < 128 ? v : 0.f, red) * (1.0f / DD);
    float dv = v - mean;
    float var = blockSum512(tid < 128 ? dv * dv : 0.f, red) * (1.0f / DD);
    if (tid < 128)
        g_x[bi * DD + tid] = dv * rsqrtf(var + 1e-5f) * lng[tid] + lnb[tid];
}

// ---------------- launcher ----------------
extern "C" void kernel_launch(void* const* d_in, const int* in_sizes, int n_in,
                              void* d_out, int out_size) {
    const int* ids = (const int*)d_in[0];
    const float* embw = (const float*)d_in[1];
    const float* pos = (const float*)d_in[2];
    const float* pW1 = (const float*)d_in[3];
    const float* pb1 = (const float*)d_in[4];
    const float* pW2 = (const float*)d_in[5];
    const float* pb2 = (const float*)d_in[6];
    const float* pW3 = (const float*)d_in[7];
    const float* pb3 = (const float*)d_in[8];
    const float* ln1g = (const float*)d_in[9];
    const float* ln1b = (const float*)d_in[10];
    const float* fW1 = (const float*)d_in[11];
    const float* fb1 = (const float*)d_in[12];
    const float* fW2 = (const float*)d_in[13];
    const float* fb2 = (const float*)d_in[14];
    const float* ln2g = (const float*)d_in[15];
    const float* ln2b = (const float*)d_in[16];
    const float* headW = (const float*)d_in[17];
    const float* headb = (const float*)d_in[18];
    float* out = (float*)d_out;

    cudaFuncSetAttribute(pair_mma, cudaFuncAttributeMaxDynamicSharedMemorySize,
                         PM_SMEM_BYTES);
    cudaFuncSetAttribute(head_mma, cudaFuncAttributeMaxDynamicSharedMemorySize,
                         HD_SMEM_BYTES);
    cudaFuncSetAttribute(gemm_mma64<0, 0, 1>, cudaFuncAttributeMaxDynamicSharedMemorySize,
                         GM_SMEM_BYTES);
    cudaFuncSetAttribute(gemm_mma64<1, 0, 1>, cudaFuncAttributeMaxDynamicSharedMemorySize,
                         GM_SMEM_BYTES);
    cudaFuncSetAttribute(ffn2_ln, cudaFuncAttributeMaxDynamicSharedMemorySize,
                         GM_SMEM_BYTES);

    float* xp;
    cudaGetSymbolAddress((void**)&xp, g_x);
    __half *ahp, *chp, *hhp, *w2hp, *w3hp, *whdp;
    cudaGetSymbolAddress((void**)&ahp, g_ah);
    cudaGetSymbolAddress((void**)&chp, g_ch);
    cudaGetSymbolAddress((void**)&hhp, g_hh);
    cudaGetSymbolAddress((void**)&w2hp, g_w2h);
    cudaGetSymbolAddress((void**)&w3hp, g_w3h);
    cudaGetSymbolAddress((void**)&whdp, g_whd);

    embed_kernel<<<(BB * NN * DD + 255) / 256, 256>>>(ids, embw, pos);
    convert_w<<<(LL * 256 * 128 + LL * 128 * 128 + DD * VV + 255) / 256, 256>>>(
        pW2, pW3, headW);

    for (int l = 0; l < LL; l++) {
        const float* W1l = pW1 + (size_t)l * 256 * 256;
        gemm_mma64<0, 0, 1><<<dim3(4, 12), 256, GM_SMEM_BYTES>>>(
            xp, 128, W1l, W1l + 128 * 256, 256, 256,
            pb1 + l * 256, nullptr, ahp, chp, 256, 128);
        pair_mma<<<NTILES_MMA, 256, PM_SMEM_BYTES>>>(
            w2hp + (size_t)l * 256 * 128, pb2 + l * 128,
            w3hp + (size_t)l * 128 * 128, pb3 + l * 128);
        pair_reduce_ln<<<BB * NN, 512>>>(ln1g + l * 128, ln1b + l * 128);
        gemm_mma64<1, 0, 1><<<dim3(4, 12), 256, GM_SMEM_BYTES>>>(
            xp, 128, fW1 + (size_t)l * 128 * 512, nullptr, 1 << 30, 512,
            fb1 + l * 512, nullptr, hhp, nullptr, 512, 128);
        ffn2_ln<<<12, 256, GM_SMEM_BYTES>>>(
            fW2 + (size_t)l * 512 * 128, fb2 + l * 128,
            ln2g + l * 128, ln2b + l * 128);
    }

    head_mma<<<dim3(VV / 128, 768 / 128), 256, HD_SMEM_BYTES>>>(whdp, headb, out);
}